// round 2
// baseline (speedup 1.0000x reference)
#include <cuda_runtime.h>

// Problem constants
#define THREADS 512
#define KJ      24
#define TBT     8            // t-values per CTA
#define CC      3072
#define TLEN    4096
#define M1      192          // KJ * TBT fused rows
#define XS_ROW  129          // padded row for x tile (conflict-free per-k)
#define TOK_ROW 130
#define QKV_ROW 386          // even -> 8B-aligned float2/u64 access
#define PO_ROW  129
#define XS_SZ   (M1 * XS_ROW)      // 24768 floats
#define TOK_SZ  (M1 * TOK_ROW)     // 24960 floats
#define PROBS_SZ (2 * 24 * 25)     // 1200 floats
#define SMEM_BYTES ((XS_SZ + TOK_SZ + PROBS_SZ) * 4)   // 203712 B

// ---- packed f32x2 helpers (FFMA2: 2x fp32 FMA throughput on sm_103a) ----
static __device__ __forceinline__ unsigned long long pk2(float a) {
    unsigned long long r;
    asm("mov.b64 %0, {%1, %1};" : "=l"(r) : "f"(a));
    return r;
}
static __device__ __forceinline__ void fma2(unsigned long long& d,
                                            unsigned long long a,
                                            unsigned long long b) {
    asm("fma.rn.f32x2 %0, %1, %2, %0;" : "+l"(d) : "l"(a), "l"(b));
}
static __device__ __forceinline__ void up2(unsigned long long v, float& a, float& b) {
    asm("mov.b64 {%0, %1}, %2;" : "=f"(a), "=f"(b) : "l"(v));
}

__global__ __launch_bounds__(THREADS, 1)
void wan_joint_attn_kernel(
    const float* __restrict__ x,
    const float* __restrict__ W_tok,  const float* __restrict__ b_tok,
    const float* __restrict__ g_norm,
    const float* __restrict__ W_qkv,  const float* __restrict__ b_qkv,
    const float* __restrict__ W_proj, const float* __restrict__ b_proj,
    const float* __restrict__ W_from, const float* __restrict__ b_from,
    float* __restrict__ out)
{
    extern __shared__ float smem[];
    float* xs    = smem;                      // [192][129] -> later reused as qkv / pout scratch
    float* tok   = smem + XS_SZ;              // [192][130] -> tok, then aout, then fout
    float* probs = smem + XS_SZ + TOK_SZ;     // [2][24][25]

    const int tid  = threadIdx.x;
    const int warp = tid >> 5;
    const int lane = tid & 31;
    const int b    = blockIdx.y;
    const int t0   = blockIdx.x * TBT;
    const long long xbase = ((long long)b * CC) * TLEN + t0;

    // ---------------- Phase 1: load x tile (coalesced 32B sectors) ----------------
    for (int i = tid; i < CC * TBT; i += THREADS) {
        int tt = i & 7;
        int cg = i >> 3;            // channel 0..3071
        int k  = cg >> 7;
        int c  = cg & 127;
        xs[(k * 8 + tt) * XS_ROW + c] = x[xbase + (long long)cg * TLEN + tt];
    }
    __syncthreads();

    // ---------------- Phase 2: GEMM1  tok = X @ W_tok + b_tok  (M=192,N=128,K=128) ----
    {
        const int r0 = warp * 12;
        const int d0 = lane * 4;
        unsigned long long acc[12][2];
        #pragma unroll
        for (int i = 0; i < 12; i++) { acc[i][0] = 0ull; acc[i][1] = 0ull; }
        const unsigned long long* Wp =
            reinterpret_cast<const unsigned long long*>(W_tok + d0);
        #pragma unroll 4
        for (int c = 0; c < 128; c++) {
            unsigned long long b01 = Wp[c * 64];
            unsigned long long b23 = Wp[c * 64 + 1];
            #pragma unroll
            for (int i = 0; i < 12; i++) {
                unsigned long long a2 = pk2(xs[(r0 + i) * XS_ROW + c]);
                fma2(acc[i][0], a2, b01);
                fma2(acc[i][1], a2, b23);
            }
        }
        float bb0 = b_tok[d0], bb1 = b_tok[d0 + 1], bb2 = b_tok[d0 + 2], bb3 = b_tok[d0 + 3];
        #pragma unroll
        for (int i = 0; i < 12; i++) {
            float v0, v1, v2, v3;
            up2(acc[i][0], v0, v1);
            up2(acc[i][1], v2, v3);
            float* tp = tok + (r0 + i) * TOK_ROW + d0;
            tp[0] = v0 + bb0; tp[1] = v1 + bb1; tp[2] = v2 + bb2; tp[3] = v3 + bb3;
        }
    }
    __syncthreads();

    // ---------------- Phase 3: RMSNorm rows of tok ----------------
    {
        #pragma unroll 2
        for (int i = 0; i < 12; i++) {
            int r = warp * 12 + i;
            float* tp = tok + r * TOK_ROW;
            float s = 0.f;
            #pragma unroll
            for (int j = 0; j < 4; j++) {
                float v = tp[lane + 32 * j];
                s += v * v;
            }
            #pragma unroll
            for (int o = 16; o > 0; o >>= 1) s += __shfl_xor_sync(0xffffffffu, s, o);
            float inv = rsqrtf(s * (1.0f / 128.0f) + 1e-5f);
            #pragma unroll
            for (int j = 0; j < 4; j++) {
                int d = lane + 32 * j;
                tp[d] = tp[d] * inv * g_norm[d];
            }
        }
    }
    __syncthreads();

    const float SCALE = 0.08838834764831845f;  // 128^-0.5
    float* qkv = xs;                            // [48][386] scratch per t-pair

    // ---------------- Phase 4: per t-pair: qkv GEMM, attention, AV ----------------
    for (int tp = 0; tp < 4; tp++) {
        // GEMM2: qkv = tok_pair @ W_qkv + b_qkv  (M=48, N=384, K=128)
        {
            const int r0 = warp * 3;     // rows r2 = k*2 + tt2
            const int n0 = lane * 12;
            unsigned long long acc[3][6];
            #pragma unroll
            for (int i = 0; i < 3; i++)
                #pragma unroll
                for (int j = 0; j < 6; j++) acc[i][j] = 0ull;
            const unsigned long long* Wp =
                reinterpret_cast<const unsigned long long*>(W_qkv + n0);
            #pragma unroll 2
            for (int c = 0; c < 128; c++) {
                unsigned long long bv[6];
                #pragma unroll
                for (int j = 0; j < 6; j++) bv[j] = Wp[c * 192 + j];
                #pragma unroll
                for (int i = 0; i < 3; i++) {
                    int r2  = r0 + i;
                    int k   = r2 >> 1;
                    int tt2 = r2 & 1;
                    unsigned long long a2 =
                        pk2(tok[(k * 8 + tp * 2 + tt2) * TOK_ROW + c]);
                    #pragma unroll
                    for (int j = 0; j < 6; j++) fma2(acc[i][j], a2, bv[j]);
                }
            }
            #pragma unroll
            for (int i = 0; i < 3; i++) {
                float* qp = qkv + (r0 + i) * QKV_ROW + n0;
                #pragma unroll
                for (int j = 0; j < 6; j++) {
                    float v0, v1;
                    up2(acc[i][j], v0, v1);
                    qp[2 * j]     = v0 + b_qkv[n0 + 2 * j];
                    qp[2 * j + 1] = v1 + b_qkv[n0 + 2 * j + 1];
                }
            }
        }
        __syncthreads();

        // Scores: S[tt2][i][j] = SCALE * <q_i, k_j>
        for (int o = tid; o < 1152; o += THREADS) {
            int tt2 = o / 576;
            int rem = o - tt2 * 576;
            int i   = rem / 24;
            int j   = rem - i * 24;
            const float2* qp = reinterpret_cast<const float2*>(qkv + (i * 2 + tt2) * QKV_ROW);
            const float2* kp = reinterpret_cast<const float2*>(qkv + (j * 2 + tt2) * QKV_ROW + 128);
            float s = 0.f;
            #pragma unroll 8
            for (int c = 0; c < 64; c++) {
                float2 qv = qp[c];
                float2 kv = kp[c];
                s += qv.x * kv.x + qv.y * kv.y;
            }
            probs[(tt2 * 24 + i) * 25 + j] = s * SCALE;
        }
        __syncthreads();

        // Softmax over j (24) per (tt2, i) row
        if (tid < 48) {
            int tt2 = tid & 1, i = tid >> 1;
            float* pr = probs + (tt2 * 24 + i) * 25;
            float m = pr[0];
            #pragma unroll
            for (int j = 1; j < 24; j++) m = fmaxf(m, pr[j]);
            float s = 0.f;
            #pragma unroll
            for (int j = 0; j < 24; j++) { float e = __expf(pr[j] - m); pr[j] = e; s += e; }
            float inv = 1.0f / s;
            #pragma unroll
            for (int j = 0; j < 24; j++) pr[j] *= inv;
        }
        __syncthreads();

        // AV: aout = attn @ v  -> overwrite this pair's (dead) tok rows
        {
            int tt2 = warp >> 3;             // warps 0-7: tt2=0, 8-15: tt2=1
            int i0  = (warp & 7) * 3;        // 3 joints per warp
            const int d0 = lane * 4;
            unsigned long long acc[3][2];
            #pragma unroll
            for (int ii = 0; ii < 3; ii++) { acc[ii][0] = 0ull; acc[ii][1] = 0ull; }
            #pragma unroll 4
            for (int j = 0; j < 24; j++) {
                const unsigned long long* vp = reinterpret_cast<const unsigned long long*>(
                    qkv + (j * 2 + tt2) * QKV_ROW + 256 + d0);
                unsigned long long v01 = vp[0], v23 = vp[1];
                #pragma unroll
                for (int ii = 0; ii < 3; ii++) {
                    unsigned long long p2 = pk2(probs[(tt2 * 24 + i0 + ii) * 25 + j]);
                    fma2(acc[ii][0], p2, v01);
                    fma2(acc[ii][1], p2, v23);
                }
            }
            #pragma unroll
            for (int ii = 0; ii < 3; ii++) {
                float v0, v1, v2, v3;
                up2(acc[ii][0], v0, v1);
                up2(acc[ii][1], v2, v3);
                float* ap = tok + ((i0 + ii) * 8 + tp * 2 + tt2) * TOK_ROW + d0;
                ap[0] = v0; ap[1] = v1; ap[2] = v2; ap[3] = v3;
            }
        }
        __syncthreads();
    }

    // ---------------- Phase 5: proj  pout = aout @ W_proj + b_proj (M=192) --------
    float* pout = xs;   // reuse (qkv dead)
    {
        const int r0 = warp * 12;
        const int d0 = lane * 4;
        unsigned long long acc[12][2];
        #pragma unroll
        for (int i = 0; i < 12; i++) { acc[i][0] = 0ull; acc[i][1] = 0ull; }
        const unsigned long long* Wp =
            reinterpret_cast<const unsigned long long*>(W_proj + d0);
        #pragma unroll 4
        for (int c = 0; c < 128; c++) {
            unsigned long long b01 = Wp[c * 64];
            unsigned long long b23 = Wp[c * 64 + 1];
            #pragma unroll
            for (int i = 0; i < 12; i++) {
                unsigned long long a2 = pk2(tok[(r0 + i) * TOK_ROW + c]);
                fma2(acc[i][0], a2, b01);
                fma2(acc[i][1], a2, b23);
            }
        }
        float bb0 = b_proj[d0], bb1 = b_proj[d0 + 1], bb2 = b_proj[d0 + 2], bb3 = b_proj[d0 + 3];
        #pragma unroll
        for (int i = 0; i < 12; i++) {
            float v0, v1, v2, v3;
            up2(acc[i][0], v0, v1);
            up2(acc[i][1], v2, v3);
            float* pp = pout + (r0 + i) * PO_ROW + d0;
            pp[0] = v0 + bb0; pp[1] = v1 + bb1; pp[2] = v2 + bb2; pp[3] = v3 + bb3;
        }
    }
    __syncthreads();

    // ---------------- Phase 6: from  fout = pout @ W_from + b_from (M=192) --------
    {
        const int r0 = warp * 12;
        const int d0 = lane * 4;
        unsigned long long acc[12][2];
        #pragma unroll
        for (int i = 0; i < 12; i++) { acc[i][0] = 0ull; acc[i][1] = 0ull; }
        const unsigned long long* Wp =
            reinterpret_cast<const unsigned long long*>(W_from + d0);
        #pragma unroll 4
        for (int c = 0; c < 128; c++) {
            unsigned long long b01 = Wp[c * 64];
            unsigned long long b23 = Wp[c * 64 + 1];
            #pragma unroll
            for (int i = 0; i < 12; i++) {
                unsigned long long a2 = pk2(pout[(r0 + i) * PO_ROW + c]);
                fma2(acc[i][0], a2, b01);
                fma2(acc[i][1], a2, b23);
            }
        }
        float bb0 = b_from[d0], bb1 = b_from[d0 + 1], bb2 = b_from[d0 + 2], bb3 = b_from[d0 + 3];
        #pragma unroll
        for (int i = 0; i < 12; i++) {
            float v0, v1, v2, v3;
            up2(acc[i][0], v0, v1);
            up2(acc[i][1], v2, v3);
            float* fp = tok + (r0 + i) * TOK_ROW + d0;   // fout overwrites aout
            fp[0] = v0 + bb0; fp[1] = v1 + bb1; fp[2] = v2 + bb2; fp[3] = v3 + bb3;
        }
    }
    __syncthreads();

    // ---------------- Phase 7: residual + coalesced store ----------------
    for (int i = tid; i < CC * TBT; i += THREADS) {
        int tt = i & 7;
        int cg = i >> 3;
        int k  = cg >> 7;
        int c  = cg & 127;
        long long gi = xbase + (long long)cg * TLEN + tt;
        out[gi] = x[gi] + tok[(k * 8 + tt) * TOK_ROW + c];
    }
}

extern "C" void kernel_launch(void* const* d_in, const int* in_sizes, int n_in,
                              void* d_out, int out_size)
{
    (void)in_sizes; (void)n_in; (void)out_size;
    const float* x      = (const float*)d_in[0];
    const float* W_tok  = (const float*)d_in[1];
    const float* b_tok  = (const float*)d_in[2];
    const float* g_norm = (const float*)d_in[3];
    const float* W_qkv  = (const float*)d_in[4];
    const float* b_qkv  = (const float*)d_in[5];
    const float* W_proj = (const float*)d_in[6];
    const float* b_proj = (const float*)d_in[7];
    const float* W_from = (const float*)d_in[8];
    const float* b_from = (const float*)d_in[9];
    float* out = (float*)d_out;

    cudaFuncSetAttribute(wan_joint_attn_kernel,
                         cudaFuncAttributeMaxDynamicSharedMemorySize, SMEM_BYTES);

    dim3 grid(TLEN / TBT, 4);
    wan_joint_attn_kernel<<<grid, THREADS, SMEM_BYTES>>>(
        x, W_tok, b_tok, g_norm, W_qkv, b_qkv, W_proj, b_proj, W_from, b_from, out);
}

// round 4
// speedup vs baseline: 1.1032x; 1.1032x over previous
#include <cuda_runtime.h>

#define THREADS 512
#define KJ      24
#define TBT     4
#define CC      3072
#define TLEN    4096
#define MROWS   96                  // KJ * TBT
#define AD_STRIDE 260               // dup row stride (floats), multiple of 4
#define QKV_STRIDE 386              // non-dup qkv stride (8B-bank stride 193: odd -> conflict-free)
#define FOUT_STRIDE 132
#define PR_STRIDE 52                // dup probs stride, multiple of 4
#define XS_SZ   (MROWS * AD_STRIDE)     // 24960 floats
#define TOK_SZ  (MROWS * AD_STRIDE)     // 24960 floats
#define PROBS_SZ (2 * 24 * PR_STRIDE)   // 2496 floats
#define SMEM_BYTES ((XS_SZ + TOK_SZ + PROBS_SZ) * 4)   // 209664 B

typedef unsigned long long u64;

static __device__ __forceinline__ void fma2(u64& d, u64 a, u64 b) {
    asm("fma.rn.f32x2 %0, %1, %2, %0;" : "+l"(d) : "l"(a), "l"(b));
}
static __device__ __forceinline__ void up2(u64 v, float& a, float& b) {
    asm("mov.b64 {%0, %1}, %2;" : "=f"(a), "=f"(b) : "l"(v));
}

// Out[M=96][128] = A_dup @ W + bias.  A dup-layout stride AD_STRIDE.
// DUPOUT: write duplicated layout (stride AD_STRIDE); else plain (stride FOUT_STRIDE).
template<bool DUPOUT>
static __device__ __forceinline__ void gemm96_128(
    const float* __restrict__ W, const float* __restrict__ bias,
    const float* A, float* Out, int warp, int lane)
{
    const int r0 = warp * 6;
    const int d0 = lane * 4;
    u64 acc[6][2];
    #pragma unroll
    for (int r = 0; r < 6; r++) { acc[r][0] = 0ull; acc[r][1] = 0ull; }

    const ulonglong2* __restrict__ Wv =
        reinterpret_cast<const ulonglong2*>(W);      // [c][32] of 16B
    const float* Ab = A + r0 * AD_STRIDE;

    #pragma unroll 4
    for (int cp = 0; cp < 64; cp++) {
        ulonglong2 w0 = Wv[(2 * cp) * 32 + lane];        // W[2cp][d0..d0+3]
        ulonglong2 w1 = Wv[(2 * cp + 1) * 32 + lane];    // W[2cp+1][d0..d0+3]
        #pragma unroll
        for (int r = 0; r < 6; r++) {
            ulonglong2 a = *reinterpret_cast<const ulonglong2*>(
                Ab + r * AD_STRIDE + 4 * cp);            // (ac,ac,ac1,ac1)
            fma2(acc[r][0], a.x, w0.x);
            fma2(acc[r][1], a.x, w0.y);
            fma2(acc[r][0], a.y, w1.x);
            fma2(acc[r][1], a.y, w1.y);
        }
    }
    float4 bb = *reinterpret_cast<const float4*>(bias + d0);
    #pragma unroll
    for (int r = 0; r < 6; r++) {
        float v0, v1, v2, v3;
        up2(acc[r][0], v0, v1);
        up2(acc[r][1], v2, v3);
        v0 += bb.x; v1 += bb.y; v2 += bb.z; v3 += bb.w;
        if (DUPOUT) {
            float* op = Out + (r0 + r) * AD_STRIDE + 2 * d0;
            *reinterpret_cast<float4*>(op)     = make_float4(v0, v0, v1, v1);
            *reinterpret_cast<float4*>(op + 4) = make_float4(v2, v2, v3, v3);
        } else {
            float* op = Out + (r0 + r) * FOUT_STRIDE + d0;
            *reinterpret_cast<float4*>(op) = make_float4(v0, v1, v2, v3);
        }
    }
}

__global__ __launch_bounds__(THREADS, 1)
void wan_joint_attn_kernel(
    const float* __restrict__ x,
    const float* __restrict__ W_tok,  const float* __restrict__ b_tok,
    const float* __restrict__ g_norm,
    const float* __restrict__ W_qkv,  const float* __restrict__ b_qkv,
    const float* __restrict__ W_proj, const float* __restrict__ b_proj,
    const float* __restrict__ W_from, const float* __restrict__ b_from,
    float* __restrict__ out)
{
    extern __shared__ float smem[];
    float* xs    = smem;                    // xsdup -> qkv scratch -> poutdup
    float* tok   = smem + XS_SZ;            // tokdup -> aoutdup -> fout(non-dup)
    float* probs = smem + XS_SZ + TOK_SZ;   // [2][24][PR_STRIDE] dup over j

    const int tid  = threadIdx.x;
    const int warp = tid >> 5;
    const int lane = tid & 31;
    const int b    = blockIdx.y;
    const int t0   = blockIdx.x * TBT;
    const long long xbase = ((long long)b * CC) * TLEN + t0;

    // ---- Phase 1: load x tile -> xsdup (row = k*4+tt, dup cols) ----
    for (int cg = tid; cg < CC; cg += THREADS) {
        int k = cg >> 7;
        int c = cg & 127;
        float4 xv = *reinterpret_cast<const float4*>(x + xbase + (long long)cg * TLEN);
        float* base = xs + (k * 4) * AD_STRIDE + 2 * c;
        *reinterpret_cast<float2*>(base)                 = make_float2(xv.x, xv.x);
        *reinterpret_cast<float2*>(base + AD_STRIDE)     = make_float2(xv.y, xv.y);
        *reinterpret_cast<float2*>(base + 2 * AD_STRIDE) = make_float2(xv.z, xv.z);
        *reinterpret_cast<float2*>(base + 3 * AD_STRIDE) = make_float2(xv.w, xv.w);
    }
    __syncthreads();

    // ---- Phase 2: GEMM1 tok = xs @ W_tok + b (dup out) ----
    gemm96_128<true>(W_tok, b_tok, xs, tok, warp, lane);
    __syncwarp();   // each warp owns its 6 full rows

    // ---- Phase 3: RMSNorm rows (warp-local) ----
    {
        float g0 = g_norm[lane], g1 = g_norm[lane + 32],
              g2 = g_norm[lane + 64], g3 = g_norm[lane + 96];
        #pragma unroll
        for (int rl = 0; rl < 6; rl++) {
            float* tp = tok + (warp * 6 + rl) * AD_STRIDE;
            float v0 = tp[2 * lane], v1 = tp[2 * (lane + 32)],
                  v2 = tp[2 * (lane + 64)], v3 = tp[2 * (lane + 96)];
            float s = v0 * v0 + v1 * v1 + v2 * v2 + v3 * v3;
            #pragma unroll
            for (int o = 16; o > 0; o >>= 1) s += __shfl_xor_sync(0xffffffffu, s, o);
            float inv = rsqrtf(s * (1.0f / 128.0f) + 1e-5f);
            v0 *= inv * g0; v1 *= inv * g1; v2 *= inv * g2; v3 *= inv * g3;
            *reinterpret_cast<float2*>(tp + 2 * lane)        = make_float2(v0, v0);
            *reinterpret_cast<float2*>(tp + 2 * (lane + 32)) = make_float2(v1, v1);
            *reinterpret_cast<float2*>(tp + 2 * (lane + 64)) = make_float2(v2, v2);
            *reinterpret_cast<float2*>(tp + 2 * (lane + 96)) = make_float2(v3, v3);
        }
    }
    __syncthreads();

    const float SCALE = 0.08838834764831845f;   // 128^-0.5
    float* qkv = xs;                            // [48][QKV_STRIDE] per t-pair

    // ---- Phase 4: per t-pair (tg): qkv GEMM, scores, softmax, AV ----
    for (int tg = 0; tg < 2; tg++) {
        // GEMM2: qkv[48][384] = tok_rows @ W_qkv + b ; rows rr = k*2+tt2
        {
            const int rr0 = warp * 3;
            const int d0 = lane * 4;
            u64 acc[3][3][2];
            #pragma unroll
            for (int r = 0; r < 3; r++)
                #pragma unroll
                for (int nb = 0; nb < 3; nb++) { acc[r][nb][0] = 0ull; acc[r][nb][1] = 0ull; }

            const float* Arow[3];
            #pragma unroll
            for (int r = 0; r < 3; r++) {
                int rr = rr0 + r;
                Arow[r] = tok + ((rr >> 1) * 4 + tg * 2 + (rr & 1)) * AD_STRIDE;
            }
            const ulonglong2* __restrict__ Wv =
                reinterpret_cast<const ulonglong2*>(W_qkv);   // [c][96] of 16B
            #pragma unroll 2
            for (int cp = 0; cp < 64; cp++) {
                ulonglong2 a[3];
                #pragma unroll
                for (int r = 0; r < 3; r++)
                    a[r] = *reinterpret_cast<const ulonglong2*>(Arow[r] + 4 * cp);
                #pragma unroll
                for (int nb = 0; nb < 3; nb++) {
                    ulonglong2 w0 = Wv[(2 * cp) * 96 + nb * 32 + lane];
                    ulonglong2 w1 = Wv[(2 * cp + 1) * 96 + nb * 32 + lane];
                    #pragma unroll
                    for (int r = 0; r < 3; r++) {
                        fma2(acc[r][nb][0], a[r].x, w0.x);
                        fma2(acc[r][nb][1], a[r].x, w0.y);
                        fma2(acc[r][nb][0], a[r].y, w1.x);
                        fma2(acc[r][nb][1], a[r].y, w1.y);
                    }
                }
            }
            #pragma unroll
            for (int nb = 0; nb < 3; nb++) {
                float4 bb = *reinterpret_cast<const float4*>(b_qkv + nb * 128 + d0);
                #pragma unroll
                for (int r = 0; r < 3; r++) {
                    float v0, v1, v2, v3;
                    up2(acc[r][nb][0], v0, v1);
                    up2(acc[r][nb][1], v2, v3);
                    float* qp = qkv + (rr0 + r) * QKV_STRIDE + nb * 128 + d0;
                    *reinterpret_cast<float2*>(qp)     = make_float2(v0 + bb.x, v1 + bb.y);
                    *reinterpret_cast<float2*>(qp + 2) = make_float2(v2 + bb.z, v3 + bb.w);
                }
            }
        }
        __syncthreads();

        // Scores: S[tt2][i][j] -> probs[..][2j] (raw)
        for (int o = tid; o < 1152; o += THREADS) {
            int tt2 = (o >= 576);
            int rem = o - tt2 * 576;
            int i = rem / 24;
            int j = rem - i * 24;
            const u64* qp = reinterpret_cast<const u64*>(qkv + (2 * i + tt2) * QKV_STRIDE);
            const u64* kp = reinterpret_cast<const u64*>(qkv + (2 * j + tt2) * QKV_STRIDE + 128);
            u64 accp = 0ull;
            #pragma unroll 8
            for (int c2 = 0; c2 < 64; c2++) fma2(accp, qp[c2], kp[c2]);
            float s0, s1;
            up2(accp, s0, s1);
            probs[(tt2 * 24 + i) * PR_STRIDE + 2 * j] = (s0 + s1) * SCALE;
        }
        __syncthreads();

        // Softmax rows; write duplicated probs
        if (tid < 48) {
            int tt2 = tid & 1, i = tid >> 1;
            float* pr = probs + (tt2 * 24 + i) * PR_STRIDE;
            float m = pr[0];
            #pragma unroll
            for (int j = 1; j < 24; j++) m = fmaxf(m, pr[2 * j]);
            float s = 0.f;
            float e[24];
            #pragma unroll
            for (int j = 0; j < 24; j++) { e[j] = __expf(pr[2 * j] - m); s += e[j]; }
            float inv = 1.0f / s;
            #pragma unroll
            for (int j = 0; j < 24; j++) {
                float p = e[j] * inv;
                *reinterpret_cast<float2*>(pr + 2 * j) = make_float2(p, p);
            }
        }
        __syncthreads();

        // AV: aout(dup) = attn @ v  -> overwrite this tg's tok rows
        {
            int tt2 = warp >> 3;
            int i0  = (warp & 7) * 3;
            const int d0 = lane * 4;
            u64 acc[3][2];
            #pragma unroll
            for (int ii = 0; ii < 3; ii++) { acc[ii][0] = 0ull; acc[ii][1] = 0ull; }
            const float* pr0 = probs + (tt2 * 24 + i0) * PR_STRIDE;
            #pragma unroll 3
            for (int j2 = 0; j2 < 12; j2++) {
                const u64* va = reinterpret_cast<const u64*>(
                    qkv + (4 * j2 + tt2) * QKV_STRIDE + 256 + d0);
                const u64* vb = reinterpret_cast<const u64*>(
                    qkv + (4 * j2 + 2 + tt2) * QKV_STRIDE + 256 + d0);
                u64 v0a = va[0], v0b = va[1];
                u64 v1a = vb[0], v1b = vb[1];
                #pragma unroll
                for (int ii = 0; ii < 3; ii++) {
                    ulonglong2 p = *reinterpret_cast<const ulonglong2*>(
                        pr0 + ii * PR_STRIDE + 4 * j2);
                    fma2(acc[ii][0], p.x, v0a);
                    fma2(acc[ii][1], p.x, v0b);
                    fma2(acc[ii][0], p.y, v1a);
                    fma2(acc[ii][1], p.y, v1b);
                }
            }
            #pragma unroll
            for (int ii = 0; ii < 3; ii++) {
                float v0, v1, v2, v3;
                up2(acc[ii][0], v0, v1);
                up2(acc[ii][1], v2, v3);
                float* ap = tok + ((i0 + ii) * 4 + tg * 2 + tt2) * AD_STRIDE + 2 * d0;
                *reinterpret_cast<float4*>(ap)     = make_float4(v0, v0, v1, v1);
                *reinterpret_cast<float4*>(ap + 4) = make_float4(v2, v2, v3, v3);
            }
        }
        __syncthreads();
    }

    // ---- Phase 5: proj pout(dup) = aout @ W_proj + b ----
    gemm96_128<true>(W_proj, b_proj, tok, xs, warp, lane);
    __syncthreads();

    // ---- Phase 6: from fout(plain) = pout @ W_from + b -> tok region ----
    gemm96_128<false>(W_from, b_from, xs, tok, warp, lane);
    __syncthreads();

    // ---- Phase 7: residual + coalesced store ----
    for (int cg = tid; cg < CC; cg += THREADS) {
        int k = cg >> 7;
        int c = cg & 127;
        long long gi = xbase + (long long)cg * TLEN;
        float4 xv = *reinterpret_cast<const float4*>(x + gi);
        const float* fp = tok + (k * 4) * FOUT_STRIDE + c;
        float4 ov;
        ov.x = xv.x + fp[0];
        ov.y = xv.y + fp[FOUT_STRIDE];
        ov.z = xv.z + fp[2 * FOUT_STRIDE];
        ov.w = xv.w + fp[3 * FOUT_STRIDE];
        *reinterpret_cast<float4*>(out + gi) = ov;
    }
}

extern "C" void kernel_launch(void* const* d_in, const int* in_sizes, int n_in,
                              void* d_out, int out_size)
{
    (void)in_sizes; (void)n_in; (void)out_size;
    const float* x      = (const float*)d_in[0];
    const float* W_tok  = (const float*)d_in[1];
    const float* b_tok  = (const float*)d_in[2];
    const float* g_norm = (const float*)d_in[3];
    const float* W_qkv  = (const float*)d_in[4];
    const float* b_qkv  = (const float*)d_in[5];
    const float* W_proj = (const float*)d_in[6];
    const float* b_proj = (const float*)d_in[7];
    const float* W_from = (const float*)d_in[8];
    const float* b_from = (const float*)d_in[9];
    float* out = (float*)d_out;

    cudaFuncSetAttribute(wan_joint_attn_kernel,
                         cudaFuncAttributeMaxDynamicSharedMemorySize, SMEM_BYTES);

    dim3 grid(TLEN / TBT, 4);
    wan_joint_attn_kernel<<<grid, THREADS, SMEM_BYTES>>>(
        x, W_tok, b_tok, g_norm, W_qkv, b_qkv, W_proj, b_proj, W_from, b_from, out);
}

// round 7
// speedup vs baseline: 1.8715x; 1.6963x over previous
#include <cuda_runtime.h>
#include <cuda_bf16.h>
#include <cstdint>

#define TLEN 4096
#define KJ   24
#define NBATCH 4
#define MTOT (NBATCH * KJ * TLEN)   // 393216 token rows
#define TPAD 136                     // bf16 elems per smem tile row (272B)

// ---------------- device scratch ----------------
__device__ __align__(256) __nv_bfloat16 g_tok_hi[(size_t)MTOT * 128];
__device__ __align__(256) __nv_bfloat16 g_tok_lo[(size_t)MTOT * 128];
__device__ __align__(256) __nv_bfloat16 g_ao_hi[(size_t)MTOT * 128];
__device__ __align__(256) __nv_bfloat16 g_ao_lo[(size_t)MTOT * 128];
__device__ __align__(256) float         g_qkv[(size_t)MTOT * 384];
__device__ __align__(256) float         g_wc[128 * 128];
__device__ __align__(256) float         g_bc[128];
__device__ __align__(256) __nv_bfloat16 g_wtok_hi[128 * 128], g_wtok_lo[128 * 128];
__device__ __align__(256) __nv_bfloat16 g_wqkv_hi[384 * 128], g_wqkv_lo[384 * 128];
__device__ __align__(256) __nv_bfloat16 g_wc_hi[128 * 128],   g_wc_lo[128 * 128];

typedef unsigned long long u64;

// ---------------- helpers ----------------
static __device__ __forceinline__ uint32_t s2u(const void* p) {
    uint32_t a;
    asm("{ .reg .u64 t; cvta.to.shared.u64 t, %1; cvt.u32.u64 %0, t; }" : "=r"(a) : "l"(p));
    return a;
}
static __device__ __forceinline__ void cp16(uint32_t dst, const void* src) {
    asm volatile("cp.async.cg.shared.global [%0], [%1], 16;" :: "r"(dst), "l"(src));
}
static __device__ __forceinline__ void cp_wait() {
    asm volatile("cp.async.commit_group;");
    asm volatile("cp.async.wait_group 0;" ::: "memory");
}
static __device__ __forceinline__ void split_bf(float v, uint16_t& h, uint16_t& l) {
    __nv_bfloat16 hb = __float2bfloat16(v);
    float r = v - __bfloat162float(hb);
    h = __bfloat16_as_ushort(hb);
    l = __bfloat16_as_ushort(__float2bfloat16(r));
}
static __device__ __forceinline__ void fma2(u64& d, u64 a, u64 b) {
    asm("fma.rn.f32x2 %0, %1, %2, %0;" : "+l"(d) : "l"(a), "l"(b));
}
static __device__ __forceinline__ void up2(u64 v, float& a, float& b) {
    asm("mov.b64 {%0, %1}, %2;" : "=f"(a), "=f"(b) : "l"(v));
}
static __device__ __forceinline__ void ldsm4(uint32_t* r, uint32_t addr) {
    asm volatile("ldmatrix.sync.aligned.m8n8.x4.shared.b16 {%0,%1,%2,%3}, [%4];"
                 : "=r"(r[0]), "=r"(r[1]), "=r"(r[2]), "=r"(r[3]) : "r"(addr));
}
static __device__ __forceinline__ void mma16816(float* c, const uint32_t* a, const uint32_t* b) {
    asm volatile("mma.sync.aligned.m16n8k16.row.col.f32.bf16.bf16.f32 "
                 "{%0,%1,%2,%3}, {%4,%5,%6,%7}, {%8,%9}, {%0,%1,%2,%3};"
                 : "+f"(c[0]), "+f"(c[1]), "+f"(c[2]), "+f"(c[3])
                 : "r"(a[0]), "r"(a[1]), "r"(a[2]), "r"(a[3]), "r"(b[0]), "r"(b[1]));
}

// one K=128 pass: acc += A[m0:m0+32][:] @ B[n0:n0+64][:]^T  (tiles bf16 [128][TPAD])
static __device__ __forceinline__ void gemm_pass(uint32_t aBase, uint32_t bBase,
                                                 float acc[2][8][4], int lane, int m0, int n0) {
    const int ar = m0 + (lane & 15), ac = 8 * (lane >> 4);
    const int br = n0 + (lane & 7) + 8 * (lane >> 4), bc = 8 * ((lane >> 3) & 1);
    #pragma unroll
    for (int ks = 0; ks < 8; ks++) {
        uint32_t a[2][4], b[4][4];
        #pragma unroll
        for (int mt = 0; mt < 2; mt++)
            ldsm4(a[mt], aBase + (uint32_t)((ar + mt * 16) * TPAD + ks * 16 + ac) * 2);
        #pragma unroll
        for (int nt = 0; nt < 4; nt++)
            ldsm4(b[nt], bBase + (uint32_t)((br + nt * 16) * TPAD + ks * 16 + bc) * 2);
        #pragma unroll
        for (int mt = 0; mt < 2; mt++)
            #pragma unroll
            for (int nt = 0; nt < 4; nt++) {
                mma16816(acc[mt][nt * 2],     a[mt], &b[nt][0]);
                mma16816(acc[mt][nt * 2 + 1], a[mt], &b[nt][2]);
            }
    }
}
static __device__ __forceinline__ void gemm3(uint32_t aHi, uint32_t aLo, uint32_t bHi,
                                             uint32_t bLo, float acc[2][8][4],
                                             int lane, int m0, int n0) {
    gemm_pass(aHi, bHi, acc, lane, m0, n0);
    gemm_pass(aHi, bLo, acc, lane, m0, n0);
    gemm_pass(aLo, bHi, acc, lane, m0, n0);
}
// write C fragments (raw) into f32 staging, stride 129
static __device__ __forceinline__ void stash(float* stg, const float acc[2][8][4],
                                             int lane, int m0, int n0) {
    const int r = m0 + (lane >> 2), cq = (lane & 3) * 2;
    #pragma unroll
    for (int mt = 0; mt < 2; mt++)
        #pragma unroll
        for (int n8 = 0; n8 < 8; n8++) {
            const float* c = acc[mt][n8];
            int row = r + mt * 16, col = n0 + n8 * 8 + cq;
            stg[row * 129 + col]           = c[0];
            stg[row * 129 + col + 1]       = c[1];
            stg[(row + 8) * 129 + col]     = c[2];
            stg[(row + 8) * 129 + col + 1] = c[3];
        }
}

// ================= K0a: Wc = W_proj @ W_from, bc = b_proj@W_from + b_from =========
__global__ __launch_bounds__(256) void k0a(const float* __restrict__ Wp,
                                           const float* __restrict__ Wf,
                                           const float* __restrict__ bp,
                                           const float* __restrict__ bf) {
    __shared__ float swp[32 * 128];
    const int tid = threadIdx.x, r0 = blockIdx.x * 32;
    for (int i = tid; i < 32 * 128; i += 256) swp[i] = Wp[(r0 + (i >> 7)) * 128 + (i & 127)];
    __syncthreads();
    const int n = tid & 127, rb = tid >> 7;
    float acc[16];
    #pragma unroll
    for (int q = 0; q < 16; q++) acc[q] = 0.f;
    for (int m = 0; m < 128; m++) {
        float wf = Wf[m * 128 + n];
        #pragma unroll
        for (int q = 0; q < 16; q++) acc[q] += swp[(rb * 16 + q) * 128 + m] * wf;
    }
    #pragma unroll
    for (int q = 0; q < 16; q++) g_wc[(r0 + rb * 16 + q) * 128 + n] = acc[q];
    if (blockIdx.x == 0 && tid < 128) {
        float a = bf[tid];
        for (int m = 0; m < 128; m++) a += bp[m] * Wf[m * 128 + tid];
        g_bc[tid] = a;
    }
}

// ================= K0b: transpose + hi/lo split weights =================
__global__ __launch_bounds__(256) void k0b(const float* __restrict__ Wt,
                                           const float* __restrict__ Wq) {
    const int i = blockIdx.x * 256 + threadIdx.x;
    uint16_t h, l;
    if (i < 16384) {
        int n = i >> 7, k = i & 127;
        split_bf(Wt[k * 128 + n], h, l);
        g_wtok_hi[i] = __ushort_as_bfloat16(h); g_wtok_lo[i] = __ushort_as_bfloat16(l);
        split_bf(g_wc[k * 128 + n], h, l);
        g_wc_hi[i] = __ushort_as_bfloat16(h);   g_wc_lo[i] = __ushort_as_bfloat16(l);
    }
    if (i < 49152) {
        int n = i >> 7, k = i & 127;
        split_bf(Wq[k * 384 + n], h, l);
        g_wqkv_hi[i] = __ushort_as_bfloat16(h); g_wqkv_lo[i] = __ushort_as_bfloat16(l);
    }
}

// ================= K1: tok = x^T @ W_tok + b, RMSNorm, split-store ===============
#define K1_BIAS 0
#define K1_G    512
#define K1_AXS  1024                 // x staging f32 [128][132]; reused: STG f32 [128][129]
#define K1_AHI  68608                // 4 bf16 tiles [128][TPAD], 34816 B each
#define K1_ALO  103424
#define K1_BHI  138240
#define K1_BLO  173056
#define K1_SMEM 207872

__global__ __launch_bounds__(256, 1)
void k1_tok(const float* __restrict__ x, const float* __restrict__ b_tok,
            const float* __restrict__ g_norm) {
    extern __shared__ char sm[];
    const int tid = threadIdx.x, warp = tid >> 5, lane = tid & 31;
    const int b = blockIdx.z, kj = blockIdx.y, t0 = blockIdx.x * 128;
    const uint32_t sb = s2u(sm);

    for (int idx = tid; idx < 4096; idx += 256) {       // x -> staging [c][t]
        int c = idx >> 5, t16 = (idx & 31) * 4;
        const float* src = x + ((size_t)(b * 3072 + kj * 128 + c)) * 4096 + t0 + t16;
        cp16(sb + K1_AXS + (uint32_t)(c * 132 + t16) * 4, src);
    }
    for (int idx = tid; idx < 2048; idx += 256) {       // B tiles (padded rows)
        int row = idx >> 4, c8 = (idx & 15) * 8;
        uint32_t off = (uint32_t)(row * TPAD + c8) * 2;
        cp16(sb + K1_BHI + off, g_wtok_hi + row * 128 + c8);
        cp16(sb + K1_BLO + off, g_wtok_lo + row * 128 + c8);
    }
    if (tid < 128) {
        *(float*)(sm + K1_BIAS + tid * 4) = b_tok[tid];
        *(float*)(sm + K1_G + tid * 4)    = g_norm[tid];
    }
    cp_wait();
    __syncthreads();

    // convert staging -> split A tiles (rows = t)
    {
        const int t = tid & 127, half = tid >> 7;
        const float* ax = (const float*)(sm + K1_AXS);
        for (int c4 = half * 16; c4 < half * 16 + 16; c4++) {
            int c = c4 * 4;
            float v0 = ax[(c + 0) * 132 + t], v1 = ax[(c + 1) * 132 + t];
            float v2 = ax[(c + 2) * 132 + t], v3 = ax[(c + 3) * 132 + t];
            uint16_t h0, l0, h1, l1, h2, l2, h3, l3;
            split_bf(v0, h0, l0); split_bf(v1, h1, l1);
            split_bf(v2, h2, l2); split_bf(v3, h3, l3);
            uint32_t off = (uint32_t)(t * TPAD + c) * 2;
            *(uint2*)(sm + K1_AHI + off) = make_uint2(h0 | ((uint32_t)h1 << 16), h2 | ((uint32_t)h3 << 16));
            *(uint2*)(sm + K1_ALO + off) = make_uint2(l0 | ((uint32_t)l1 << 16), l2 | ((uint32_t)l3 << 16));
        }
    }
    __syncthreads();

    float acc[2][8][4];
    #pragma unroll
    for (int i = 0; i < 2; i++)
        #pragma unroll
        for (int j = 0; j < 8; j++)
            #pragma unroll
            for (int q = 0; q < 4; q++) acc[i][j][q] = 0.f;
    const int m0 = (warp & 3) * 32, n0 = (warp >> 2) * 64;
    gemm3(sb + K1_AHI, sb + K1_ALO, sb + K1_BHI, sb + K1_BLO, acc, lane, m0, n0);
    stash((float*)(sm + K1_AXS), acc, lane, m0, n0);
    __syncthreads();

    // RMSNorm + split (tiles dead -> SHI/SLO reuse AHI/ALO regions)
    uint32_t* shi = (uint32_t*)(sm + K1_AHI);
    uint32_t* slo = (uint32_t*)(sm + K1_ALO);
    if (tid < 128) {
        const int row = tid;
        const float* stg  = (const float*)(sm + K1_AXS);
        const float* bias = (const float*)(sm + K1_BIAS);
        const float* gw   = (const float*)(sm + K1_G);
        float ss = 0.f;
        #pragma unroll 4
        for (int c = 0; c < 128; c++) {
            float v = stg[row * 129 + c] + bias[c];
            ss += v * v;
        }
        float inv = rsqrtf(ss * (1.0f / 128.0f) + 1e-5f);
        #pragma unroll 4
        for (int c2 = 0; c2 < 64; c2++) {
            int c = c2 * 2;
            float v0 = (stg[row * 129 + c]     + bias[c])     * inv * gw[c];
            float v1 = (stg[row * 129 + c + 1] + bias[c + 1]) * inv * gw[c + 1];
            uint16_t h0, l0, h1, l1;
            split_bf(v0, h0, l0); split_bf(v1, h1, l1);
            shi[row * 65 + c2] = h0 | ((uint32_t)h1 << 16);
            slo[row * 65 + c2] = l0 | ((uint32_t)l1 << 16);
        }
    }
    __syncthreads();
    {
        uint32_t* dhi = (uint32_t*)g_tok_hi;
        uint32_t* dlo = (uint32_t*)g_tok_lo;
        for (int idx = tid; idx < 8192; idx += 256) {
            int row = idx >> 6, w = idx & 63;
            size_t rid = ((size_t)b * 4096 + t0 + row) * 24 + kj;
            dhi[rid * 64 + w] = shi[row * 65 + w];
            dlo[rid * 64 + w] = slo[row * 65 + w];
        }
    }
}

// ================= K2: qkv = tok @ W_qkv + b (3 N-tiles, direct store) ===========
#define K2_BIAS 0
#define K2_AHI  1536
#define K2_ALO  36352
#define K2_BHI  71168
#define K2_BLO  105984
#define K2_SMEM 140800

__global__ __launch_bounds__(256, 1)
void k2_qkv(const float* __restrict__ b_qkv) {
    extern __shared__ char sm[];
    const int tid = threadIdx.x, warp = tid >> 5, lane = tid & 31;
    const size_t rid0 = (size_t)blockIdx.x * 128;
    const uint32_t sb = s2u(sm);

    for (int idx = tid; idx < 2048; idx += 256) {
        int row = idx >> 4, c8 = (idx & 15) * 8;
        uint32_t off = (uint32_t)(row * TPAD + c8) * 2;
        cp16(sb + K2_AHI + off, g_tok_hi + (rid0 + row) * 128 + c8);
        cp16(sb + K2_ALO + off, g_tok_lo + (rid0 + row) * 128 + c8);
        cp16(sb + K2_BHI + off, g_wqkv_hi + row * 128 + c8);
        cp16(sb + K2_BLO + off, g_wqkv_lo + row * 128 + c8);
    }
    for (int i = tid; i < 384; i += 256) *(float*)(sm + K2_BIAS + i * 4) = b_qkv[i];
    cp_wait();
    __syncthreads();

    const int m0 = (warp & 3) * 32, n0 = (warp >> 2) * 64;
    const float* bias = (const float*)(sm + K2_BIAS);

    for (int nt = 0; nt < 3; nt++) {
        float acc[2][8][4];
        #pragma unroll
        for (int i = 0; i < 2; i++)
            #pragma unroll
            for (int j = 0; j < 8; j++)
                #pragma unroll
                for (int q = 0; q < 4; q++) acc[i][j][q] = 0.f;
        gemm3(sb + K2_AHI, sb + K2_ALO, sb + K2_BHI, sb + K2_BLO, acc, lane, m0, n0);

        // direct store to g_qkv (+bias)
        {
            const int r = m0 + (lane >> 2), cq = (lane & 3) * 2;
            #pragma unroll
            for (int mt = 0; mt < 2; mt++)
                #pragma unroll
                for (int n8 = 0; n8 < 8; n8++) {
                    const float* c = acc[mt][n8];
                    int col = nt * 128 + n0 + n8 * 8 + cq;
                    float b0 = bias[col], b1 = bias[col + 1];
                    size_t ra = (rid0 + r + mt * 16) * 384 + col;
                    size_t rb = (rid0 + r + mt * 16 + 8) * 384 + col;
                    *reinterpret_cast<float2*>(g_qkv + ra) = make_float2(c[0] + b0, c[1] + b1);
                    *reinterpret_cast<float2*>(g_qkv + rb) = make_float2(c[2] + b0, c[3] + b1);
                }
        }
        if (nt < 2) {
            __syncthreads();   // all warps done reading B before overwrite
            for (int idx = tid; idx < 2048; idx += 256) {
                int row = idx >> 4, c8 = (idx & 15) * 8;
                uint32_t off = (uint32_t)(row * TPAD + c8) * 2;
                cp16(sb + K2_BHI + off, g_wqkv_hi + ((nt + 1) * 128 + row) * 128 + c8);
                cp16(sb + K2_BLO + off, g_wqkv_lo + ((nt + 1) * 128 + row) * 128 + c8);
            }
            cp_wait();
            __syncthreads();
        }
    }
}

// ================= K3: attention (fp32 FFMA2), split-store ao =================
#define QS 386
#define PRS 52
#define K3_PROBS (96 * QS)
#define K3_SMEM  ((96 * QS + 96 * PRS) * 4)

__global__ __launch_bounds__(512, 1)
void k3_attn() {
    extern __shared__ float smf[];
    float* qkv = smf;
    float* probs = smf + K3_PROBS;
    const int tid = threadIdx.x, warp = tid >> 5, lane = tid & 31;
    const int b = blockIdx.y, t0 = blockIdx.x * 4;
    const size_t rid0 = ((size_t)b * 4096 + t0) * 24;

    for (int idx = tid; idx < 9216; idx += 512) {
        int row = idx / 96, rem = idx - row * 96;
        float4 v = *reinterpret_cast<const float4*>(g_qkv + (rid0 + row) * 384 + rem * 4);
        float* d = qkv + row * QS + rem * 4;
        *reinterpret_cast<float2*>(d)     = make_float2(v.x, v.y);
        *reinterpret_cast<float2*>(d + 2) = make_float2(v.z, v.w);
    }
    __syncthreads();

    for (int o = tid; o < 2304; o += 512) {
        int tl = o / 576, rem = o - tl * 576;
        int i = rem / 24, j = rem - i * 24;
        const u64* qp = reinterpret_cast<const u64*>(qkv + (tl * 24 + i) * QS);
        const u64* kp = reinterpret_cast<const u64*>(qkv + (tl * 24 + j) * QS + 128);
        u64 acc = 0ull;
        #pragma unroll 8
        for (int c2 = 0; c2 < 64; c2++) fma2(acc, qp[c2], kp[c2]);
        float s0, s1;
        up2(acc, s0, s1);
        probs[(tl * 24 + i) * PRS + 2 * j] = (s0 + s1) * 0.08838834764831845f;
    }
    __syncthreads();

    if (tid < 96) {
        int tl = tid / 24, i = tid - tl * 24;
        float* pr = probs + (tl * 24 + i) * PRS;
        float m = pr[0];
        #pragma unroll
        for (int j = 1; j < 24; j++) m = fmaxf(m, pr[2 * j]);
        float s = 0.f, e[24];
        #pragma unroll
        for (int j = 0; j < 24; j++) { e[j] = __expf(pr[2 * j] - m); s += e[j]; }
        float inv = 1.0f / s;
        #pragma unroll
        for (int j = 0; j < 24; j++) {
            float p = e[j] * inv;
            *reinterpret_cast<float2*>(pr + 2 * j) = make_float2(p, p);
        }
    }
    __syncthreads();

    {
        const int tl = warp >> 2, i0 = (warp & 3) * 6, d0 = lane * 4;
        u64 acc[6][2];
        #pragma unroll
        for (int ii = 0; ii < 6; ii++) { acc[ii][0] = 0ull; acc[ii][1] = 0ull; }
        const float* pr0 = probs + (tl * 24 + i0) * PRS;
        #pragma unroll 4
        for (int j = 0; j < 24; j++) {
            const u64* vp = reinterpret_cast<const u64*>(qkv + (tl * 24 + j) * QS + 256 + d0);
            u64 va = vp[0], vb = vp[1];
            #pragma unroll
            for (int ii = 0; ii < 6; ii++) {
                float p = pr0[ii * PRS + 2 * j];
                u64 p2;
                asm("mov.b64 %0, {%1, %1};" : "=l"(p2) : "f"(p));
                fma2(acc[ii][0], p2, va);
                fma2(acc[ii][1], p2, vb);
            }
        }
        uint32_t* dhi = (uint32_t*)g_ao_hi;
        uint32_t* dlo = (uint32_t*)g_ao_lo;
        #pragma unroll
        for (int ii = 0; ii < 6; ii++) {
            float v0, v1, v2, v3;
            up2(acc[ii][0], v0, v1);
            up2(acc[ii][1], v2, v3);
            uint16_t h0, l0, h1, l1, h2, l2, h3, l3;
            split_bf(v0, h0, l0); split_bf(v1, h1, l1);
            split_bf(v2, h2, l2); split_bf(v3, h3, l3);
            size_t rid = rid0 + tl * 24 + i0 + ii;
            dhi[rid * 64 + lane * 2]     = h0 | ((uint32_t)h1 << 16);
            dhi[rid * 64 + lane * 2 + 1] = h2 | ((uint32_t)h3 << 16);
            dlo[rid * 64 + lane * 2]     = l0 | ((uint32_t)l1 << 16);
            dlo[rid * 64 + lane * 2 + 1] = l2 | ((uint32_t)l3 << 16);
        }
    }
}

// ================= K4: out = x + ao @ Wc + bc (transposed store) =================
#define K4_BIAS 0
#define K4_STG  512                 // f32 [128][129]
#define K4_AHI  66560
#define K4_ALO  101376
#define K4_BHI  136192
#define K4_BLO  171008
#define K4_SMEM 205824

__global__ __launch_bounds__(256, 1)
void k4_out(const float* __restrict__ x, float* __restrict__ out) {
    extern __shared__ char sm[];
    const int tid = threadIdx.x, warp = tid >> 5, lane = tid & 31;
    const int b = blockIdx.z, kj = blockIdx.y, t0 = blockIdx.x * 128;
    const uint32_t sb = s2u(sm);

    for (int idx = tid; idx < 2048; idx += 256) {
        int row = idx >> 4, c8 = (idx & 15) * 8;
        uint32_t off = (uint32_t)(row * TPAD + c8) * 2;
        size_t rid = ((size_t)b * 4096 + t0 + row) * 24 + kj;
        cp16(sb + K4_AHI + off, g_ao_hi + rid * 128 + c8);
        cp16(sb + K4_ALO + off, g_ao_lo + rid * 128 + c8);
        cp16(sb + K4_BHI + off, g_wc_hi + row * 128 + c8);
        cp16(sb + K4_BLO + off, g_wc_lo + row * 128 + c8);
    }
    if (tid < 128) *(float*)(sm + K4_BIAS + tid * 4) = g_bc[tid];
    cp_wait();
    __syncthreads();

    float acc[2][8][4];
    #pragma unroll
    for (int i = 0; i < 2; i++)
        #pragma unroll
        for (int j = 0; j < 8; j++)
            #pragma unroll
            for (int q = 0; q < 4; q++) acc[i][j][q] = 0.f;
    const int m0 = (warp & 3) * 32, n0 = (warp >> 2) * 64;
    gemm3(sb + K4_AHI, sb + K4_ALO, sb + K4_BHI, sb + K4_BLO, acc, lane, m0, n0);
    stash((float*)(sm + K4_STG), acc, lane, m0, n0);
    __syncthreads();

    {
        const float* stg  = (const float*)(sm + K4_STG);
        const float* bias = (const float*)(sm + K4_BIAS);
        for (int o = tid; o < 4096; o += 256) {
            int c = o >> 5, tq = o & 31;
            float bc = bias[c];
            size_t gb = ((size_t)(b * 3072 + kj * 128 + c)) * 4096 + t0;
            #pragma unroll
            for (int j = 0; j < 4; j++) {
                int t = tq + 32 * j;
                out[gb + t] = x[gb + t] + stg[t * 129 + c] + bc;
            }
        }
    }
}

// ================= host =================
extern "C" void kernel_launch(void* const* d_in, const int* in_sizes, int n_in,
                              void* d_out, int out_size)
{
    (void)in_sizes; (void)n_in; (void)out_size;
    const float* x      = (const float*)d_in[0];
    const float* W_tok  = (const float*)d_in[1];
    const float* b_tok  = (const float*)d_in[2];
    const float* g_norm = (const float*)d_in[3];
    const float* W_qkv  = (const float*)d_in[4];
    const float* b_qkv  = (const float*)d_in[5];
    const float* W_proj = (const float*)d_in[6];
    const float* b_proj = (const float*)d_in[7];
    const float* W_from = (const float*)d_in[8];
    const float* b_from = (const float*)d_in[9];
    float* out = (float*)d_out;

    cudaFuncSetAttribute(k1_tok, cudaFuncAttributeMaxDynamicSharedMemorySize, K1_SMEM);
    cudaFuncSetAttribute(k2_qkv, cudaFuncAttributeMaxDynamicSharedMemorySize, K2_SMEM);
    cudaFuncSetAttribute(k3_attn, cudaFuncAttributeMaxDynamicSharedMemorySize, K3_SMEM);
    cudaFuncSetAttribute(k4_out, cudaFuncAttributeMaxDynamicSharedMemorySize, K4_SMEM);

    k0a<<<4, 256>>>(W_proj, W_from, b_proj, b_from);
    k0b<<<192, 256>>>(W_tok, W_qkv);
    {
        dim3 g(32, 24, 4);
        k1_tok<<<g, 256, K1_SMEM>>>(x, b_tok, g_norm);
    }
    k2_qkv<<<MTOT / 128, 256, K2_SMEM>>>(b_qkv);
    {
        dim3 g(1024, 4);
        k3_attn<<<g, 512, K3_SMEM>>>();
    }
    {
        dim3 g(32, 24, 4);
        k4_out<<<g, 256, K4_SMEM>>>(x, out);
    }
}

// round 9
// speedup vs baseline: 1.9140x; 1.0227x over previous
#include <cuda_runtime.h>
#include <cuda_bf16.h>
#include <cstdint>

#define TLEN 4096
#define KJ   24
#define NBATCH 4
#define MTOT (NBATCH * KJ * TLEN)   // 393216 token rows
#define TPAD 136                     // bf16 elems per smem tile row (272B)

// ---------------- device scratch ----------------
__device__ __align__(256) __nv_bfloat16 g_tok_hi[(size_t)MTOT * 128];
__device__ __align__(256) __nv_bfloat16 g_tok_lo[(size_t)MTOT * 128];
__device__ __align__(256) __nv_bfloat16 g_ao_hi[(size_t)MTOT * 128];
__device__ __align__(256) __nv_bfloat16 g_ao_lo[(size_t)MTOT * 128];
__device__ __align__(256) float         g_qkv[(size_t)MTOT * 384];
__device__ __align__(256) float         g_wc[128 * 128];
__device__ __align__(256) float         g_bc[128];
__device__ __align__(256) __nv_bfloat16 g_wtok_hi[128 * 128], g_wtok_lo[128 * 128];
__device__ __align__(256) __nv_bfloat16 g_wqkv_hi[384 * 128], g_wqkv_lo[384 * 128];
__device__ __align__(256) __nv_bfloat16 g_wc_hi[128 * 128],   g_wc_lo[128 * 128];

typedef unsigned long long u64;

// ---------------- helpers ----------------
static __device__ __forceinline__ uint32_t s2u(const void* p) {
    uint32_t a;
    asm("{ .reg .u64 t; cvta.to.shared.u64 t, %1; cvt.u32.u64 %0, t; }" : "=r"(a) : "l"(p));
    return a;
}
static __device__ __forceinline__ void cp16(uint32_t dst, const void* src) {
    asm volatile("cp.async.cg.shared.global [%0], [%1], 16;" :: "r"(dst), "l"(src));
}
static __device__ __forceinline__ void cp_commit() {
    asm volatile("cp.async.commit_group;");
}
static __device__ __forceinline__ void cp_wait0() {
    asm volatile("cp.async.wait_group 0;" ::: "memory");
}
static __device__ __forceinline__ void split_bf(float v, uint16_t& h, uint16_t& l) {
    __nv_bfloat16 hb = __float2bfloat16(v);
    float r = v - __bfloat162float(hb);
    h = __bfloat16_as_ushort(hb);
    l = __bfloat16_as_ushort(__float2bfloat16(r));
}
static __device__ __forceinline__ void fma2(u64& d, u64 a, u64 b) {
    asm("fma.rn.f32x2 %0, %1, %2, %0;" : "+l"(d) : "l"(a), "l"(b));
}
static __device__ __forceinline__ void up2(u64 v, float& a, float& b) {
    asm("mov.b64 {%0, %1}, %2;" : "=f"(a), "=f"(b) : "l"(v));
}
static __device__ __forceinline__ void ldsm4(uint32_t* r, uint32_t addr) {
    asm volatile("ldmatrix.sync.aligned.m8n8.x4.shared.b16 {%0,%1,%2,%3}, [%4];"
                 : "=r"(r[0]), "=r"(r[1]), "=r"(r[2]), "=r"(r[3]) : "r"(addr));
}
static __device__ __forceinline__ void mma16816(float* c, const uint32_t* a, const uint32_t* b) {
    asm volatile("mma.sync.aligned.m16n8k16.row.col.f32.bf16.bf16.f32 "
                 "{%0,%1,%2,%3}, {%4,%5,%6,%7}, {%8,%9}, {%0,%1,%2,%3};"
                 : "+f"(c[0]), "+f"(c[1]), "+f"(c[2]), "+f"(c[3])
                 : "r"(a[0]), "r"(a[1]), "r"(a[2]), "r"(a[3]), "r"(b[0]), "r"(b[1]));
}

// one K=128 pass of a 32x32 warp tile: acc += A[m0:m0+32][:] @ B[n0:n0+32][:]^T
static __device__ __forceinline__ void gemm_pass(uint32_t aBase, uint32_t bBase,
                                                 float acc[2][4][4], int lane, int m0, int n0) {
    const int ar = m0 + (lane & 15), ac = 8 * (lane >> 4);
    const int br = n0 + (lane & 7) + 8 * (lane >> 4), bc = 8 * ((lane >> 3) & 1);
    #pragma unroll
    for (int ks = 0; ks < 8; ks++) {
        uint32_t a[2][4], b[2][4];
        #pragma unroll
        for (int mt = 0; mt < 2; mt++)
            ldsm4(a[mt], aBase + (uint32_t)((ar + mt * 16) * TPAD + ks * 16 + ac) * 2);
        #pragma unroll
        for (int nt = 0; nt < 2; nt++)
            ldsm4(b[nt], bBase + (uint32_t)((br + nt * 16) * TPAD + ks * 16 + bc) * 2);
        #pragma unroll
        for (int mt = 0; mt < 2; mt++)
            #pragma unroll
            for (int nt = 0; nt < 2; nt++) {
                mma16816(acc[mt][nt * 2],     a[mt], &b[nt][0]);
                mma16816(acc[mt][nt * 2 + 1], a[mt], &b[nt][2]);
            }
    }
}
static __device__ __forceinline__ void gemm3(uint32_t aHi, uint32_t aLo, uint32_t bHi,
                                             uint32_t bLo, float acc[2][4][4],
                                             int lane, int m0, int n0) {
    gemm_pass(aHi, bHi, acc, lane, m0, n0);
    gemm_pass(aHi, bLo, acc, lane, m0, n0);
    gemm_pass(aLo, bHi, acc, lane, m0, n0);
}
// write C fragments (raw) into f32 staging, stride 129
static __device__ __forceinline__ void stash(float* stg, const float acc[2][4][4],
                                             int lane, int m0, int n0) {
    const int r = m0 + (lane >> 2), cq = (lane & 3) * 2;
    #pragma unroll
    for (int mt = 0; mt < 2; mt++)
        #pragma unroll
        for (int n8 = 0; n8 < 4; n8++) {
            const float* c = acc[mt][n8];
            int row = r + mt * 16, col = n0 + n8 * 8 + cq;
            stg[row * 129 + col]           = c[0];
            stg[row * 129 + col + 1]       = c[1];
            stg[(row + 8) * 129 + col]     = c[2];
            stg[(row + 8) * 129 + col + 1] = c[3];
        }
}

// ================= K0a: Wc = W_proj @ W_from, bc = b_proj@W_from + b_from =========
__global__ __launch_bounds__(256) void k0a(const float* __restrict__ Wp,
                                           const float* __restrict__ Wf,
                                           const float* __restrict__ bp,
                                           const float* __restrict__ bf) {
    __shared__ float swp[32 * 128];
    const int tid = threadIdx.x, r0 = blockIdx.x * 32;
    for (int i = tid; i < 32 * 128; i += 256) swp[i] = Wp[(r0 + (i >> 7)) * 128 + (i & 127)];
    __syncthreads();
    const int n = tid & 127, rb = tid >> 7;
    float acc[16];
    #pragma unroll
    for (int q = 0; q < 16; q++) acc[q] = 0.f;
    for (int m = 0; m < 128; m++) {
        float wf = Wf[m * 128 + n];
        #pragma unroll
        for (int q = 0; q < 16; q++) acc[q] += swp[(rb * 16 + q) * 128 + m] * wf;
    }
    #pragma unroll
    for (int q = 0; q < 16; q++) g_wc[(r0 + rb * 16 + q) * 128 + n] = acc[q];
    if (blockIdx.x == 0 && tid < 128) {
        float a = bf[tid];
        for (int m = 0; m < 128; m++) a += bp[m] * Wf[m * 128 + tid];
        g_bc[tid] = a;
    }
}

// ================= K0b: transpose + hi/lo split weights =================
__global__ __launch_bounds__(256) void k0b(const float* __restrict__ Wt,
                                           const float* __restrict__ Wq) {
    const int i = blockIdx.x * 256 + threadIdx.x;
    uint16_t h, l;
    if (i < 16384) {
        int n = i >> 7, k = i & 127;
        split_bf(Wt[k * 128 + n], h, l);
        g_wtok_hi[i] = __ushort_as_bfloat16(h); g_wtok_lo[i] = __ushort_as_bfloat16(l);
        split_bf(g_wc[k * 128 + n], h, l);
        g_wc_hi[i] = __ushort_as_bfloat16(h);   g_wc_lo[i] = __ushort_as_bfloat16(l);
    }
    if (i < 49152) {
        int n = i >> 7, k = i & 127;
        split_bf(Wq[k * 384 + n], h, l);
        g_wqkv_hi[i] = __ushort_as_bfloat16(h); g_wqkv_lo[i] = __ushort_as_bfloat16(l);
    }
}

// ================= K1: tok = x^T @ W_tok + b, RMSNorm, split-store ===============
#define K1_BIAS 0
#define K1_G    512
#define K1_AXS  1024                 // x staging f32 [128][132]; reused: STG f32 [128][129]
#define K1_AHI  68608                // bf16 tiles [128][TPAD] = 34816 B each
#define K1_ALO  103424
#define K1_BHI  138240
#define K1_BLO  173056
#define K1_SMEM 207872

__global__ __launch_bounds__(512, 1)
void k1_tok(const float* __restrict__ x, const float* __restrict__ b_tok,
            const float* __restrict__ g_norm) {
    extern __shared__ char sm[];
    const int tid = threadIdx.x, warp = tid >> 5, lane = tid & 31;
    const int b = blockIdx.z, kj = blockIdx.y, t0 = blockIdx.x * 128;
    const uint32_t sb = s2u(sm);

    for (int idx = tid; idx < 4096; idx += 512) {       // x -> staging [c][t]
        int c = idx >> 5, t16 = (idx & 31) * 4;
        const float* src = x + ((size_t)(b * 3072 + kj * 128 + c)) * 4096 + t0 + t16;
        cp16(sb + K1_AXS + (uint32_t)(c * 132 + t16) * 4, src);
    }
    for (int idx = tid; idx < 2048; idx += 512) {       // B tiles (padded rows)
        int row = idx >> 4, c8 = (idx & 15) * 8;
        uint32_t off = (uint32_t)(row * TPAD + c8) * 2;
        cp16(sb + K1_BHI + off, g_wtok_hi + row * 128 + c8);
        cp16(sb + K1_BLO + off, g_wtok_lo + row * 128 + c8);
    }
    if (tid < 128) {
        *(float*)(sm + K1_BIAS + tid * 4) = b_tok[tid];
        *(float*)(sm + K1_G + tid * 4)    = g_norm[tid];
    }
    cp_commit();
    cp_wait0();
    __syncthreads();

    // convert staging -> split A tiles (rows = t)
    {
        const int t = tid & 127, quarter = tid >> 7;
        const float* ax = (const float*)(sm + K1_AXS);
        for (int c4 = quarter * 8; c4 < quarter * 8 + 8; c4++) {
            int c = c4 * 4;
            float v0 = ax[(c + 0) * 132 + t], v1 = ax[(c + 1) * 132 + t];
            float v2 = ax[(c + 2) * 132 + t], v3 = ax[(c + 3) * 132 + t];
            uint16_t h0, l0, h1, l1, h2, l2, h3, l3;
            split_bf(v0, h0, l0); split_bf(v1, h1, l1);
            split_bf(v2, h2, l2); split_bf(v3, h3, l3);
            uint32_t off = (uint32_t)(t * TPAD + c) * 2;
            *(uint2*)(sm + K1_AHI + off) = make_uint2(h0 | ((uint32_t)h1 << 16), h2 | ((uint32_t)h3 << 16));
            *(uint2*)(sm + K1_ALO + off) = make_uint2(l0 | ((uint32_t)l1 << 16), l2 | ((uint32_t)l3 << 16));
        }
    }
    __syncthreads();

    float acc[2][4][4];
    #pragma unroll
    for (int i = 0; i < 2; i++)
        #pragma unroll
        for (int j = 0; j < 4; j++)
            #pragma unroll
            for (int q = 0; q < 4; q++) acc[i][j][q] = 0.f;
    const int m0 = (warp & 3) * 32, n0 = (warp >> 2) * 32;
    gemm3(sb + K1_AHI, sb + K1_ALO, sb + K1_BHI, sb + K1_BLO, acc, lane, m0, n0);
    __syncthreads();
    stash((float*)(sm + K1_AXS), acc, lane, m0, n0);
    __syncthreads();

    // RMSNorm + split: 4 threads per row
    uint32_t* shi = (uint32_t*)(sm + K1_AHI);
    uint32_t* slo = (uint32_t*)(sm + K1_ALO);
    {
        const int row = tid >> 2, sub = tid & 3;
        const float* stg  = (const float*)(sm + K1_AXS);
        const float* bias = (const float*)(sm + K1_BIAS);
        const float* gw   = (const float*)(sm + K1_G);
        float ss = 0.f;
        #pragma unroll 8
        for (int c = sub * 32; c < sub * 32 + 32; c++) {
            float v = stg[row * 129 + c] + bias[c];
            ss += v * v;
        }
        ss += __shfl_xor_sync(0xffffffffu, ss, 1);
        ss += __shfl_xor_sync(0xffffffffu, ss, 2);
        float inv = rsqrtf(ss * (1.0f / 128.0f) + 1e-5f);
        #pragma unroll 4
        for (int c2 = 0; c2 < 16; c2++) {
            int c = sub * 32 + c2 * 2;
            float v0 = (stg[row * 129 + c]     + bias[c])     * inv * gw[c];
            float v1 = (stg[row * 129 + c + 1] + bias[c + 1]) * inv * gw[c + 1];
            uint16_t h0, l0, h1, l1;
            split_bf(v0, h0, l0); split_bf(v1, h1, l1);
            shi[row * 65 + sub * 16 + c2] = h0 | ((uint32_t)h1 << 16);
            slo[row * 65 + sub * 16 + c2] = l0 | ((uint32_t)l1 << 16);
        }
    }
    __syncthreads();
    {
        uint32_t* dhi = (uint32_t*)g_tok_hi;
        uint32_t* dlo = (uint32_t*)g_tok_lo;
        for (int idx = tid; idx < 8192; idx += 512) {
            int row = idx >> 6, w = idx & 63;
            size_t rid = ((size_t)b * 4096 + t0 + row) * 24 + kj;
            dhi[rid * 64 + w] = shi[row * 65 + w];
            dlo[rid * 64 + w] = slo[row * 65 + w];
        }
    }
}

// ================= K2: qkv = tok @ W_qkv + b (3 N-tiles, B double-buffered) ======
#define K2_BIAS 0
#define K2_AHI  1536
#define K2_ALO  36352
#define K2_B0HI 71168
#define K2_B0LO 105984
#define K2_B1HI 140800
#define K2_B1LO 175616
#define K2_SMEM 210432

__global__ __launch_bounds__(512, 1)
void k2_qkv(const float* __restrict__ b_qkv) {
    extern __shared__ char sm[];
    const int tid = threadIdx.x, warp = tid >> 5, lane = tid & 31;
    const size_t rid0 = (size_t)blockIdx.x * 128;
    const uint32_t sb = s2u(sm);
    const uint32_t bHi[2] = { sb + K2_B0HI, sb + K2_B1HI };
    const uint32_t bLo[2] = { sb + K2_B0LO, sb + K2_B1LO };

    for (int idx = tid; idx < 2048; idx += 512) {
        int row = idx >> 4, c8 = (idx & 15) * 8;
        uint32_t off = (uint32_t)(row * TPAD + c8) * 2;
        cp16(sb + K2_AHI + off, g_tok_hi + (rid0 + row) * 128 + c8);
        cp16(sb + K2_ALO + off, g_tok_lo + (rid0 + row) * 128 + c8);
        cp16(bHi[0] + off, g_wqkv_hi + row * 128 + c8);
        cp16(bLo[0] + off, g_wqkv_lo + row * 128 + c8);
    }
    for (int i = tid; i < 384; i += 512) *(float*)(sm + K2_BIAS + i * 4) = b_qkv[i];
    cp_commit();
    cp_wait0();
    __syncthreads();

    const int m0 = (warp & 3) * 32, n0 = (warp >> 2) * 32;
    const float* bias = (const float*)(sm + K2_BIAS);

    for (int nt = 0; nt < 3; nt++) {
        if (nt < 2) {   // prefetch next B into alternate buffer during compute
            for (int idx = tid; idx < 2048; idx += 512) {
                int row = idx >> 4, c8 = (idx & 15) * 8;
                uint32_t off = (uint32_t)(row * TPAD + c8) * 2;
                cp16(bHi[(nt + 1) & 1] + off, g_wqkv_hi + ((nt + 1) * 128 + row) * 128 + c8);
                cp16(bLo[(nt + 1) & 1] + off, g_wqkv_lo + ((nt + 1) * 128 + row) * 128 + c8);
            }
            cp_commit();
        }
        float acc[2][4][4];
        #pragma unroll
        for (int i = 0; i < 2; i++)
            #pragma unroll
            for (int j = 0; j < 4; j++)
                #pragma unroll
                for (int q = 0; q < 4; q++) acc[i][j][q] = 0.f;
        gemm3(sb + K2_AHI, sb + K2_ALO, bHi[nt & 1], bLo[nt & 1], acc, lane, m0, n0);

        // direct store to g_qkv (+bias)
        {
            const int r = m0 + (lane >> 2), cq = (lane & 3) * 2;
            #pragma unroll
            for (int mt = 0; mt < 2; mt++)
                #pragma unroll
                for (int n8 = 0; n8 < 4; n8++) {
                    const float* c = acc[mt][n8];
                    int col = nt * 128 + n0 + n8 * 8 + cq;
                    float b0 = bias[col], b1 = bias[col + 1];
                    size_t ra = (rid0 + r + mt * 16) * 384 + col;
                    size_t rb = (rid0 + r + mt * 16 + 8) * 384 + col;
                    *reinterpret_cast<float2*>(g_qkv + ra) = make_float2(c[0] + b0, c[1] + b1);
                    *reinterpret_cast<float2*>(g_qkv + rb) = make_float2(c[2] + b0, c[3] + b1);
                }
        }
        if (nt < 2) {
            cp_wait0();
            __syncthreads();
        }
    }
}

// ================= K3: attention (fp32 FFMA2), split-store ao =================
#define QS 386
#define PRS 52
#define K3_PROBS (96 * QS)
#define K3_SMEM  ((96 * QS + 96 * PRS) * 4)

__global__ __launch_bounds__(512, 1)
void k3_attn() {
    extern __shared__ float smf[];
    float* qkv = smf;
    float* probs = smf + K3_PROBS;
    const int tid = threadIdx.x, warp = tid >> 5, lane = tid & 31;
    const int b = blockIdx.y, t0 = blockIdx.x * 4;
    const size_t rid0 = ((size_t)b * 4096 + t0) * 24;

    for (int idx = tid; idx < 9216; idx += 512) {
        int row = idx / 96, rem = idx - row * 96;
        float4 v = *reinterpret_cast<const float4*>(g_qkv + (rid0 + row) * 384 + rem * 4);
        float* d = qkv + row * QS + rem * 4;
        *reinterpret_cast<float2*>(d)     = make_float2(v.x, v.y);
        *reinterpret_cast<float2*>(d + 2) = make_float2(v.z, v.w);
    }
    __syncthreads();

    // scores: 576 2x2 tiles over tl in 0..3 (12x12 tiles per tl)
    for (int o = tid; o < 576; o += 512) {
        int tl = o / 144, rem = o - tl * 144;
        int ti = rem / 12, tj = rem - ti * 12;
        int i = 2 * ti, j = 2 * tj;
        const u64* q0 = reinterpret_cast<const u64*>(qkv + (tl * 24 + i) * QS);
        const u64* q1 = reinterpret_cast<const u64*>(qkv + (tl * 24 + i + 1) * QS);
        const u64* k0 = reinterpret_cast<const u64*>(qkv + (tl * 24 + j) * QS + 128);
        const u64* k1 = reinterpret_cast<const u64*>(qkv + (tl * 24 + j + 1) * QS + 128);
        u64 a00 = 0ull, a01 = 0ull, a10 = 0ull, a11 = 0ull;
        #pragma unroll 8
        for (int c2 = 0; c2 < 64; c2++) {
            u64 qa = q0[c2], qb = q1[c2], ka = k0[c2], kb = k1[c2];
            fma2(a00, qa, ka);
            fma2(a01, qa, kb);
            fma2(a10, qb, ka);
            fma2(a11, qb, kb);
        }
        float s0, s1;
        const float SC = 0.08838834764831845f;
        float* pr = probs + (tl * 24 + i) * PRS;
        up2(a00, s0, s1); pr[2 * j]             = (s0 + s1) * SC;
        up2(a01, s0, s1); pr[2 * (j + 1)]       = (s0 + s1) * SC;
        up2(a10, s0, s1); pr[PRS + 2 * j]       = (s0 + s1) * SC;
        up2(a11, s0, s1); pr[PRS + 2 * (j + 1)] = (s0 + s1) * SC;
    }
    __syncthreads();

    if (tid < 96) {
        int tl = tid / 24, i = tid - tl * 24;
        float* pr = probs + (tl * 24 + i) * PRS;
        float m = pr[0];
        #pragma unroll
        for (int j = 1; j < 24; j++) m = fmaxf(m, pr[2 * j]);
        float s = 0.f, e[24];
        #pragma unroll
        for (int j = 0; j < 24; j++) { e[j] = __expf(pr[2 * j] - m); s += e[j]; }
        float inv = 1.0f / s;
        #pragma unroll
        for (int j = 0; j < 24; j++) {
            float p = e[j] * inv;
            *reinterpret_cast<float2*>(pr + 2 * j) = make_float2(p, p);
        }
    }
    __syncthreads();

    {
        const int tl = warp >> 2, i0 = (warp & 3) * 6, d0 = lane * 4;
        u64 acc[6][2];
        #pragma unroll
        for (int ii = 0; ii < 6; ii++) { acc[ii][0] = 0ull; acc[ii][1] = 0ull; }
        const float* pr0 = probs + (tl * 24 + i0) * PRS;
        #pragma unroll 4
        for (int j = 0; j < 24; j++) {
            const u64* vp = reinterpret_cast<const u64*>(qkv + (tl * 24 + j) * QS + 256 + d0);
            u64 va = vp[0], vb = vp[1];
            #pragma unroll
            for (int ii = 0; ii < 6; ii++) {
                float p = pr0[ii * PRS + 2 * j];
                u64 p2;
                asm("mov.b64 %0, {%1, %1};" : "=l"(p2) : "f"(p));
                fma2(acc[ii][0], p2, va);
                fma2(acc[ii][1], p2, vb);
            }
        }
        uint32_t* dhi = (uint32_t*)g_ao_hi;
        uint32_t* dlo = (uint32_t*)g_ao_lo;
        #pragma unroll
        for (int ii = 0; ii < 6; ii++) {
            float v0, v1, v2, v3;
            up2(acc[ii][0], v0, v1);
            up2(acc[ii][1], v2, v3);
            uint16_t h0, l0, h1, l1, h2, l2, h3, l3;
            split_bf(v0, h0, l0); split_bf(v1, h1, l1);
            split_bf(v2, h2, l2); split_bf(v3, h3, l3);
            size_t rid = rid0 + tl * 24 + i0 + ii;
            dhi[rid * 64 + lane * 2]     = h0 | ((uint32_t)h1 << 16);
            dhi[rid * 64 + lane * 2 + 1] = h2 | ((uint32_t)h3 << 16);
            dlo[rid * 64 + lane * 2]     = l0 | ((uint32_t)l1 << 16);
            dlo[rid * 64 + lane * 2 + 1] = l2 | ((uint32_t)l3 << 16);
        }
    }
}

// ================= K4: out = x + ao @ Wc + bc (transposed store) =================
#define K4_BIAS 0
#define K4_STG  512                 // f32 [128][129]
#define K4_AHI  66560
#define K4_ALO  101376
#define K4_BHI  136192
#define K4_BLO  171008
#define K4_SMEM 205824

__global__ __launch_bounds__(512, 1)
void k4_out(const float* __restrict__ x, float* __restrict__ out) {
    extern __shared__ char sm[];
    const int tid = threadIdx.x, warp = tid >> 5, lane = tid & 31;
    const int b = blockIdx.z, kj = blockIdx.y, t0 = blockIdx.x * 128;
    const uint32_t sb = s2u(sm);

    for (int idx = tid; idx < 2048; idx += 512) {
        int row = idx >> 4, c8 = (idx & 15) * 8;
        uint32_t off = (uint32_t)(row * TPAD + c8) * 2;
        size_t rid = ((size_t)b * 4096 + t0 + row) * 24 + kj;
        cp16(sb + K4_AHI + off, g_ao_hi + rid * 128 + c8);
        cp16(sb + K4_ALO + off, g_ao_lo + rid * 128 + c8);
        cp16(sb + K4_BHI + off, g_wc_hi + row * 128 + c8);
        cp16(sb + K4_BLO + off, g_wc_lo + row * 128 + c8);
    }
    if (tid < 128) *(float*)(sm + K4_BIAS + tid * 4) = g_bc[tid];
    cp_commit();
    cp_wait0();
    __syncthreads();

    float acc[2][4][4];
    #pragma unroll
    for (int i = 0; i < 2; i++)
        #pragma unroll
        for (int j = 0; j < 4; j++)
            #pragma unroll
            for (int q = 0; q < 4; q++) acc[i][j][q] = 0.f;
    const int m0 = (warp & 3) * 32, n0 = (warp >> 2) * 32;
    gemm3(sb + K4_AHI, sb + K4_ALO, sb + K4_BHI, sb + K4_BLO, acc, lane, m0, n0);
    stash((float*)(sm + K4_STG), acc, lane, m0, n0);
    __syncthreads();

    {
        const float* stg  = (const float*)(sm + K4_STG);
        const float* bias = (const float*)(sm + K4_BIAS);
        for (int o = tid; o < 4096; o += 512) {
            int c = o >> 5, tq = o & 31;
            float bc = bias[c];
            size_t gb = ((size_t)(b * 3072 + kj * 128 + c)) * 4096 + t0;
            #pragma unroll
            for (int j = 0; j < 4; j++) {
                int t = tq + 32 * j;
                out[gb + t] = x[gb + t] + stg[t * 129 + c] + bc;
            }
        }
    }
}

// ================= host =================
extern "C" void kernel_launch(void* const* d_in, const int* in_sizes, int n_in,
                              void* d_out, int out_size)
{
    (void)in_sizes; (void)n_in; (void)out_size;
    const float* x      = (const float*)d_in[0];
    const float* W_tok  = (const float*)d_in[1];
    const float* b_tok  = (const float*)d_in[2];
    const float* g_norm = (const float*)d_in[3];
    const float* W_qkv  = (const float*)d_in[4];
    const float* b_qkv  = (const float*)d_in[5];
    const float* W_proj = (const float*)d_in[6];
    const float* b_proj = (const float*)d_in[7];
    const float* W_from = (const float*)d_in[8];
    const float* b_from = (const float*)d_in[9];
    float* out = (float*)d_out;

    cudaFuncSetAttribute(k1_tok, cudaFuncAttributeMaxDynamicSharedMemorySize, K1_SMEM);
    cudaFuncSetAttribute(k2_qkv, cudaFuncAttributeMaxDynamicSharedMemorySize, K2_SMEM);
    cudaFuncSetAttribute(k3_attn, cudaFuncAttributeMaxDynamicSharedMemorySize, K3_SMEM);
    cudaFuncSetAttribute(k4_out, cudaFuncAttributeMaxDynamicSharedMemorySize, K4_SMEM);

    k0a<<<4, 256>>>(W_proj, W_from, b_proj, b_from);
    k0b<<<192, 256>>>(W_tok, W_qkv);
    {
        dim3 g(32, 24, 4);
        k1_tok<<<g, 512, K1_SMEM>>>(x, b_tok, g_norm);
    }
    k2_qkv<<<MTOT / 128, 512, K2_SMEM>>>(b_qkv);
    {
        dim3 g(1024, 4);
        k3_attn<<<g, 512, K3_SMEM>>>();
    }
    {
        dim3 g(32, 24, 4);
        k4_out<<<g, 512, K4_SMEM>>>(x, out);
    }
}

// round 10
// speedup vs baseline: 2.1779x; 1.1379x over previous
#include <cuda_runtime.h>
#include <cuda_bf16.h>
#include <cstdint>

#define TLEN 4096
#define KJ   24
#define NBATCH 4
#define MTOT (NBATCH * KJ * TLEN)   // 393216 token rows
#define TPAD 136                     // bf16 elems per smem tile row (272B)

// ---------------- device scratch ----------------
__device__ __align__(256) __nv_bfloat16 g_tok_hi[(size_t)MTOT * 128];
__device__ __align__(256) __nv_bfloat16 g_tok_lo[(size_t)MTOT * 128];
__device__ __align__(256) __nv_bfloat16 g_ao_hi[(size_t)MTOT * 128];
__device__ __align__(256) __nv_bfloat16 g_ao_lo[(size_t)MTOT * 128];
__device__ __align__(256) float         g_qkv[(size_t)MTOT * 384];
__device__ __align__(256) float         g_wc[128 * 128];
__device__ __align__(256) float         g_bc[128];
__device__ __align__(256) __nv_bfloat16 g_wtok_hi[128 * 128], g_wtok_lo[128 * 128];
__device__ __align__(256) __nv_bfloat16 g_wqkv_hi[384 * 128], g_wqkv_lo[384 * 128];
__device__ __align__(256) __nv_bfloat16 g_wc_hi[128 * 128],   g_wc_lo[128 * 128];

typedef unsigned long long u64;

// ---------------- helpers ----------------
static __device__ __forceinline__ uint32_t s2u(const void* p) {
    uint32_t a;
    asm("{ .reg .u64 t; cvta.to.shared.u64 t, %1; cvt.u32.u64 %0, t; }" : "=r"(a) : "l"(p));
    return a;
}
static __device__ __forceinline__ void cp16(uint32_t dst, const void* src) {
    asm volatile("cp.async.cg.shared.global [%0], [%1], 16;" :: "r"(dst), "l"(src));
}
static __device__ __forceinline__ void cp_commit() {
    asm volatile("cp.async.commit_group;");
}
static __device__ __forceinline__ void cp_wait0() {
    asm volatile("cp.async.wait_group 0;" ::: "memory");
}
static __device__ __forceinline__ void split_bf(float v, uint16_t& h, uint16_t& l) {
    __nv_bfloat16 hb = __float2bfloat16(v);
    float r = v - __bfloat162float(hb);
    h = __bfloat16_as_ushort(hb);
    l = __bfloat16_as_ushort(__float2bfloat16(r));
}
static __device__ __forceinline__ void fma2(u64& d, u64 a, u64 b) {
    asm("fma.rn.f32x2 %0, %1, %2, %0;" : "+l"(d) : "l"(a), "l"(b));
}
static __device__ __forceinline__ void up2(u64 v, float& a, float& b) {
    asm("mov.b64 {%0, %1}, %2;" : "=f"(a), "=f"(b) : "l"(v));
}
static __device__ __forceinline__ void ldsm4(uint32_t* r, uint32_t addr) {
    asm volatile("ldmatrix.sync.aligned.m8n8.x4.shared.b16 {%0,%1,%2,%3}, [%4];"
                 : "=r"(r[0]), "=r"(r[1]), "=r"(r[2]), "=r"(r[3]) : "r"(addr));
}
static __device__ __forceinline__ void mma16816(float* c, const uint32_t* a, const uint32_t* b) {
    asm volatile("mma.sync.aligned.m16n8k16.row.col.f32.bf16.bf16.f32 "
                 "{%0,%1,%2,%3}, {%4,%5,%6,%7}, {%8,%9}, {%0,%1,%2,%3};"
                 : "+f"(c[0]), "+f"(c[1]), "+f"(c[2]), "+f"(c[3])
                 : "r"(a[0]), "r"(a[1]), "r"(a[2]), "r"(a[3]), "r"(b[0]), "r"(b[1]));
}

// one K=128 pass of a (MT*16)x32 warp tile
template<int MT>
static __device__ __forceinline__ void gemm_pass(uint32_t aBase, uint32_t bBase,
                                                 float acc[MT][4][4], int lane, int m0, int n0) {
    const int ar = m0 + (lane & 15), ac = 8 * (lane >> 4);
    const int br = n0 + (lane & 7) + 8 * (lane >> 4), bc = 8 * ((lane >> 3) & 1);
    #pragma unroll
    for (int ks = 0; ks < 8; ks++) {
        uint32_t a[MT][4], b[2][4];
        #pragma unroll
        for (int mt = 0; mt < MT; mt++)
            ldsm4(a[mt], aBase + (uint32_t)((ar + mt * 16) * TPAD + ks * 16 + ac) * 2);
        #pragma unroll
        for (int nt = 0; nt < 2; nt++)
            ldsm4(b[nt], bBase + (uint32_t)((br + nt * 16) * TPAD + ks * 16 + bc) * 2);
        #pragma unroll
        for (int mt = 0; mt < MT; mt++)
            #pragma unroll
            for (int nt = 0; nt < 2; nt++) {
                mma16816(acc[mt][nt * 2],     a[mt], &b[nt][0]);
                mma16816(acc[mt][nt * 2 + 1], a[mt], &b[nt][2]);
            }
    }
}
template<int MT>
static __device__ __forceinline__ void gemm3(uint32_t aHi, uint32_t aLo, uint32_t bHi,
                                             uint32_t bLo, float acc[MT][4][4],
                                             int lane, int m0, int n0) {
    gemm_pass<MT>(aHi, bHi, acc, lane, m0, n0);
    gemm_pass<MT>(aHi, bLo, acc, lane, m0, n0);
    gemm_pass<MT>(aLo, bHi, acc, lane, m0, n0);
}
// write C fragments (raw) into f32 staging, stride 129
template<int MT>
static __device__ __forceinline__ void stash(float* stg, const float acc[MT][4][4],
                                             int lane, int m0, int n0) {
    const int r = m0 + (lane >> 2), cq = (lane & 3) * 2;
    #pragma unroll
    for (int mt = 0; mt < MT; mt++)
        #pragma unroll
        for (int n8 = 0; n8 < 4; n8++) {
            const float* c = acc[mt][n8];
            int row = r + mt * 16, col = n0 + n8 * 8 + cq;
            stg[row * 129 + col]           = c[0];
            stg[row * 129 + col + 1]       = c[1];
            stg[(row + 8) * 129 + col]     = c[2];
            stg[(row + 8) * 129 + col + 1] = c[3];
        }
}

// ================= K0a: Wc = W_proj @ W_from, bc = b_proj@W_from + b_from =========
__global__ __launch_bounds__(256) void k0a(const float* __restrict__ Wp,
                                           const float* __restrict__ Wf,
                                           const float* __restrict__ bp,
                                           const float* __restrict__ bf) {
    __shared__ float swp[32 * 128];
    const int tid = threadIdx.x, r0 = blockIdx.x * 32;
    for (int i = tid; i < 32 * 128; i += 256) swp[i] = Wp[(r0 + (i >> 7)) * 128 + (i & 127)];
    __syncthreads();
    const int n = tid & 127, rb = tid >> 7;
    float acc[16];
    #pragma unroll
    for (int q = 0; q < 16; q++) acc[q] = 0.f;
    for (int m = 0; m < 128; m++) {
        float wf = Wf[m * 128 + n];
        #pragma unroll
        for (int q = 0; q < 16; q++) acc[q] += swp[(rb * 16 + q) * 128 + m] * wf;
    }
    #pragma unroll
    for (int q = 0; q < 16; q++) g_wc[(r0 + rb * 16 + q) * 128 + n] = acc[q];
    if (blockIdx.x == 0 && tid < 128) {
        float a = bf[tid];
        for (int m = 0; m < 128; m++) a += bp[m] * Wf[m * 128 + tid];
        g_bc[tid] = a;
    }
}

// ================= K0b: transpose + hi/lo split weights =================
__global__ __launch_bounds__(256) void k0b(const float* __restrict__ Wt,
                                           const float* __restrict__ Wq) {
    const int i = blockIdx.x * 256 + threadIdx.x;
    uint16_t h, l;
    if (i < 16384) {
        int n = i >> 7, k = i & 127;
        split_bf(Wt[k * 128 + n], h, l);
        g_wtok_hi[i] = __ushort_as_bfloat16(h); g_wtok_lo[i] = __ushort_as_bfloat16(l);
        split_bf(g_wc[k * 128 + n], h, l);
        g_wc_hi[i] = __ushort_as_bfloat16(h);   g_wc_lo[i] = __ushort_as_bfloat16(l);
    }
    if (i < 49152) {
        int n = i >> 7, k = i & 127;
        split_bf(Wq[k * 384 + n], h, l);
        g_wqkv_hi[i] = __ushort_as_bfloat16(h); g_wqkv_lo[i] = __ushort_as_bfloat16(l);
    }
}

// ================= K1: tok = x^T @ W_tok + b, RMSNorm, split-store ===============
// M = 64 t's per CTA, 256 threads, 2 CTAs/SM. B (W_tok) in 64-row chunks.
#define K1_BIAS 0
#define K1_G    512
#define K1_AXS  1024                 // x staging f32 [128][68]; reused as STG f32 [64][129]
#define K1_AHI  35840                // bf16 tile [64][TPAD] = 17408 B
#define K1_ALO  53248
#define K1_BHI  70656
#define K1_BLO  88064
#define K1_SMEM 105472

__global__ __launch_bounds__(256, 2)
void k1_tok(const float* __restrict__ x, const float* __restrict__ b_tok,
            const float* __restrict__ g_norm) {
    extern __shared__ char sm[];
    const int tid = threadIdx.x, warp = tid >> 5, lane = tid & 31;
    const int b = blockIdx.z, kj = blockIdx.y, t0 = blockIdx.x * 64;
    const uint32_t sb = s2u(sm);

    for (int idx = tid; idx < 2048; idx += 256) {       // x -> staging [c][t], 64 t's
        int c = idx >> 4, t16 = (idx & 15) * 4;
        const float* src = x + ((size_t)(b * 3072 + kj * 128 + c)) * 4096 + t0 + t16;
        cp16(sb + K1_AXS + (uint32_t)(c * 68 + t16) * 4, src);
    }
    for (int idx = tid; idx < 1024; idx += 256) {       // B chunk 0 (rows 0..63)
        int row = idx >> 4, c8 = (idx & 15) * 8;
        uint32_t off = (uint32_t)(row * TPAD + c8) * 2;
        cp16(sb + K1_BHI + off, g_wtok_hi + row * 128 + c8);
        cp16(sb + K1_BLO + off, g_wtok_lo + row * 128 + c8);
    }
    if (tid < 128) {
        *(float*)(sm + K1_BIAS + tid * 4) = b_tok[tid];
        *(float*)(sm + K1_G + tid * 4)    = g_norm[tid];
    }
    cp_commit();
    cp_wait0();
    __syncthreads();

    // convert staging -> split A tiles (rows = t, 64 rows)
    {
        const int t = tid & 63, quarter = tid >> 6;     // 4 quarters x 8 c4-groups
        const float* ax = (const float*)(sm + K1_AXS);
        for (int c4 = quarter * 8; c4 < quarter * 8 + 8; c4++) {
            int c = c4 * 4;
            float v0 = ax[(c + 0) * 68 + t], v1 = ax[(c + 1) * 68 + t];
            float v2 = ax[(c + 2) * 68 + t], v3 = ax[(c + 3) * 68 + t];
            uint16_t h0, l0, h1, l1, h2, l2, h3, l3;
            split_bf(v0, h0, l0); split_bf(v1, h1, l1);
            split_bf(v2, h2, l2); split_bf(v3, h3, l3);
            uint32_t off = (uint32_t)(t * TPAD + c) * 2;
            *(uint2*)(sm + K1_AHI + off) = make_uint2(h0 | ((uint32_t)h1 << 16), h2 | ((uint32_t)h3 << 16));
            *(uint2*)(sm + K1_ALO + off) = make_uint2(l0 | ((uint32_t)l1 << 16), l2 | ((uint32_t)l3 << 16));
        }
    }
    __syncthreads();

    // GEMM: 2 chunks of 64 output cols; warp tile 16x32 (8 warps = 4M x 2N)
    const int m0 = (warp & 3) * 16, n0 = (warp >> 2) * 32;
    for (int nc = 0; nc < 2; nc++) {
        float acc[1][4][4];
        #pragma unroll
        for (int j = 0; j < 4; j++)
            #pragma unroll
            for (int q = 0; q < 4; q++) acc[0][j][q] = 0.f;
        gemm3<1>(sb + K1_AHI, sb + K1_ALO, sb + K1_BHI, sb + K1_BLO, acc, lane, m0, n0);
        stash<1>((float*)(sm + K1_AXS), acc, lane, m0, nc * 64 + n0);
        if (nc == 0) {
            __syncthreads();
            for (int idx = tid; idx < 1024; idx += 256) {   // B chunk 1 (rows 64..127)
                int row = idx >> 4, c8 = (idx & 15) * 8;
                uint32_t off = (uint32_t)(row * TPAD + c8) * 2;
                cp16(sb + K1_BHI + off, g_wtok_hi + (64 + row) * 128 + c8);
                cp16(sb + K1_BLO + off, g_wtok_lo + (64 + row) * 128 + c8);
            }
            cp_commit();
            cp_wait0();
            __syncthreads();
        }
    }
    __syncthreads();

    // RMSNorm + split: 4 threads per row (64 rows)
    uint32_t* shi = (uint32_t*)(sm + K1_AHI);
    uint32_t* slo = (uint32_t*)(sm + K1_ALO);
    {
        const int row = tid >> 2, sub = tid & 3;
        const float* stg  = (const float*)(sm + K1_AXS);
        const float* bias = (const float*)(sm + K1_BIAS);
        const float* gw   = (const float*)(sm + K1_G);
        float ss = 0.f;
        #pragma unroll 8
        for (int c = sub * 32; c < sub * 32 + 32; c++) {
            float v = stg[row * 129 + c] + bias[c];
            ss += v * v;
        }
        ss += __shfl_xor_sync(0xffffffffu, ss, 1);
        ss += __shfl_xor_sync(0xffffffffu, ss, 2);
        float inv = rsqrtf(ss * (1.0f / 128.0f) + 1e-5f);
        #pragma unroll 4
        for (int c2 = 0; c2 < 16; c2++) {
            int c = sub * 32 + c2 * 2;
            float v0 = (stg[row * 129 + c]     + bias[c])     * inv * gw[c];
            float v1 = (stg[row * 129 + c + 1] + bias[c + 1]) * inv * gw[c + 1];
            uint16_t h0, l0, h1, l1;
            split_bf(v0, h0, l0); split_bf(v1, h1, l1);
            shi[row * 65 + sub * 16 + c2] = h0 | ((uint32_t)h1 << 16);
            slo[row * 65 + sub * 16 + c2] = l0 | ((uint32_t)l1 << 16);
        }
    }
    __syncthreads();
    {
        uint32_t* dhi = (uint32_t*)g_tok_hi;
        uint32_t* dlo = (uint32_t*)g_tok_lo;
        for (int idx = tid; idx < 4096; idx += 256) {
            int row = idx >> 6, w = idx & 63;
            size_t rid = ((size_t)b * 4096 + t0 + row) * 24 + kj;
            dhi[rid * 64 + w] = shi[row * 65 + w];
            dlo[rid * 64 + w] = slo[row * 65 + w];
        }
    }
}

// ================= K2: qkv = tok @ W_qkv + b (6 x 64-col chunks) =================
// M = 128 rows per CTA, 256 threads, 2 CTAs/SM.
#define K2_BIAS 0
#define K2_AHI  1536                 // [128][TPAD] = 34816
#define K2_ALO  36352
#define K2_BHI  71168                // 64-row chunk: 17408
#define K2_BLO  88576
#define K2_SMEM 105984

__global__ __launch_bounds__(256, 2)
void k2_qkv(const float* __restrict__ b_qkv) {
    extern __shared__ char sm[];
    const int tid = threadIdx.x, warp = tid >> 5, lane = tid & 31;
    const size_t rid0 = (size_t)blockIdx.x * 128;
    const uint32_t sb = s2u(sm);

    for (int idx = tid; idx < 2048; idx += 256) {
        int row = idx >> 4, c8 = (idx & 15) * 8;
        uint32_t off = (uint32_t)(row * TPAD + c8) * 2;
        cp16(sb + K2_AHI + off, g_tok_hi + (rid0 + row) * 128 + c8);
        cp16(sb + K2_ALO + off, g_tok_lo + (rid0 + row) * 128 + c8);
    }
    for (int idx = tid; idx < 1024; idx += 256) {   // B chunk 0
        int row = idx >> 4, c8 = (idx & 15) * 8;
        uint32_t off = (uint32_t)(row * TPAD + c8) * 2;
        cp16(sb + K2_BHI + off, g_wqkv_hi + row * 128 + c8);
        cp16(sb + K2_BLO + off, g_wqkv_lo + row * 128 + c8);
    }
    for (int i = tid; i < 384; i += 256) *(float*)(sm + K2_BIAS + i * 4) = b_qkv[i];
    cp_commit();
    cp_wait0();
    __syncthreads();

    const int m0 = (warp >> 1) * 32, n0 = (warp & 1) * 32;   // 8 warps = 4M x 2N of 32x32
    const float* bias = (const float*)(sm + K2_BIAS);

    for (int nc = 0; nc < 6; nc++) {
        float acc[2][4][4];
        #pragma unroll
        for (int i = 0; i < 2; i++)
            #pragma unroll
            for (int j = 0; j < 4; j++)
                #pragma unroll
                for (int q = 0; q < 4; q++) acc[i][j][q] = 0.f;
        gemm3<2>(sb + K2_AHI, sb + K2_ALO, sb + K2_BHI, sb + K2_BLO, acc, lane, m0, n0);

        // direct store to g_qkv (+bias)
        {
            const int r = m0 + (lane >> 2), cq = (lane & 3) * 2;
            #pragma unroll
            for (int mt = 0; mt < 2; mt++)
                #pragma unroll
                for (int n8 = 0; n8 < 4; n8++) {
                    const float* c = acc[mt][n8];
                    int col = nc * 64 + n0 + n8 * 8 + cq;
                    float b0 = bias[col], b1 = bias[col + 1];
                    size_t ra = (rid0 + r + mt * 16) * 384 + col;
                    size_t rb = (rid0 + r + mt * 16 + 8) * 384 + col;
                    *reinterpret_cast<float2*>(g_qkv + ra) = make_float2(c[0] + b0, c[1] + b1);
                    *reinterpret_cast<float2*>(g_qkv + rb) = make_float2(c[2] + b0, c[3] + b1);
                }
        }
        if (nc < 5) {
            __syncthreads();
            for (int idx = tid; idx < 1024; idx += 256) {
                int row = idx >> 4, c8 = (idx & 15) * 8;
                uint32_t off = (uint32_t)(row * TPAD + c8) * 2;
                cp16(sb + K2_BHI + off, g_wqkv_hi + ((nc + 1) * 64 + row) * 128 + c8);
                cp16(sb + K2_BLO + off, g_wqkv_lo + ((nc + 1) * 64 + row) * 128 + c8);
            }
            cp_commit();
            cp_wait0();
            __syncthreads();
        }
    }
}

// ================= K3: attention (fp32 FFMA2), split-store ao =================
// 2 t's per CTA, 256 threads, 2 CTAs/SM.
#define QS 386
#define PRS 52
#define K3_PROBS (48 * QS)
#define K3_SMEM  ((48 * QS + 48 * PRS) * 4)

__global__ __launch_bounds__(256, 2)
void k3_attn() {
    extern __shared__ float smf[];
    float* qkv = smf;
    float* probs = smf + K3_PROBS;
    const int tid = threadIdx.x, warp = tid >> 5, lane = tid & 31;
    const int b = blockIdx.y, t0 = blockIdx.x * 2;
    const size_t rid0 = ((size_t)b * 4096 + t0) * 24;

    for (int idx = tid; idx < 4608; idx += 256) {   // 48 rows x 96 float4
        int row = idx / 96, rem = idx - row * 96;
        float4 v = *reinterpret_cast<const float4*>(g_qkv + (rid0 + row) * 384 + rem * 4);
        float* d = qkv + row * QS + rem * 4;
        *reinterpret_cast<float2*>(d)     = make_float2(v.x, v.y);
        *reinterpret_cast<float2*>(d + 2) = make_float2(v.z, v.w);
    }
    __syncthreads();

    // scores: 288 2x2 tiles (2 tl x 12 x 12)
    for (int o = tid; o < 288; o += 256) {
        int tl = o / 144, rem = o - tl * 144;
        int ti = rem / 12, tj = rem - ti * 12;
        int i = 2 * ti, j = 2 * tj;
        const u64* q0 = reinterpret_cast<const u64*>(qkv + (tl * 24 + i) * QS);
        const u64* q1 = reinterpret_cast<const u64*>(qkv + (tl * 24 + i + 1) * QS);
        const u64* k0 = reinterpret_cast<const u64*>(qkv + (tl * 24 + j) * QS + 128);
        const u64* k1 = reinterpret_cast<const u64*>(qkv + (tl * 24 + j + 1) * QS + 128);
        u64 a00 = 0ull, a01 = 0ull, a10 = 0ull, a11 = 0ull;
        #pragma unroll 8
        for (int c2 = 0; c2 < 64; c2++) {
            u64 qa = q0[c2], qb = q1[c2], ka = k0[c2], kb = k1[c2];
            fma2(a00, qa, ka);
            fma2(a01, qa, kb);
            fma2(a10, qb, ka);
            fma2(a11, qb, kb);
        }
        float s0, s1;
        const float SC = 0.08838834764831845f;
        float* pr = probs + (tl * 24 + i) * PRS;
        up2(a00, s0, s1); pr[2 * j]             = (s0 + s1) * SC;
        up2(a01, s0, s1); pr[2 * (j + 1)]       = (s0 + s1) * SC;
        up2(a10, s0, s1); pr[PRS + 2 * j]       = (s0 + s1) * SC;
        up2(a11, s0, s1); pr[PRS + 2 * (j + 1)] = (s0 + s1) * SC;
    }
    __syncthreads();

    if (tid < 48) {
        int tl = tid / 24, i = tid - tl * 24;
        float* pr = probs + (tl * 24 + i) * PRS;
        float m = pr[0];
        #pragma unroll
        for (int j = 1; j < 24; j++) m = fmaxf(m, pr[2 * j]);
        float s = 0.f, e[24];
        #pragma unroll
        for (int j = 0; j < 24; j++) { e[j] = __expf(pr[2 * j] - m); s += e[j]; }
        float inv = 1.0f / s;
        #pragma unroll
        for (int j = 0; j < 24; j++) {
            float p = e[j] * inv;
            *reinterpret_cast<float2*>(pr + 2 * j) = make_float2(p, p);
        }
    }
    __syncthreads();

    {
        const int tl = warp >> 2, i0 = (warp & 3) * 6, d0 = lane * 4;
        u64 acc[6][2];
        #pragma unroll
        for (int ii = 0; ii < 6; ii++) { acc[ii][0] = 0ull; acc[ii][1] = 0ull; }
        const float* pr0 = probs + (tl * 24 + i0) * PRS;
        #pragma unroll 4
        for (int j = 0; j < 24; j++) {
            const u64* vp = reinterpret_cast<const u64*>(qkv + (tl * 24 + j) * QS + 256 + d0);
            u64 va = vp[0], vb = vp[1];
            #pragma unroll
            for (int ii = 0; ii < 6; ii++) {
                float p = pr0[ii * PRS + 2 * j];
                u64 p2;
                asm("mov.b64 %0, {%1, %1};" : "=l"(p2) : "f"(p));
                fma2(acc[ii][0], p2, va);
                fma2(acc[ii][1], p2, vb);
            }
        }
        uint32_t* dhi = (uint32_t*)g_ao_hi;
        uint32_t* dlo = (uint32_t*)g_ao_lo;
        #pragma unroll
        for (int ii = 0; ii < 6; ii++) {
            float v0, v1, v2, v3;
            up2(acc[ii][0], v0, v1);
            up2(acc[ii][1], v2, v3);
            uint16_t h0, l0, h1, l1, h2, l2, h3, l3;
            split_bf(v0, h0, l0); split_bf(v1, h1, l1);
            split_bf(v2, h2, l2); split_bf(v3, h3, l3);
            size_t rid = rid0 + tl * 24 + i0 + ii;
            dhi[rid * 64 + lane * 2]     = h0 | ((uint32_t)h1 << 16);
            dhi[rid * 64 + lane * 2 + 1] = h2 | ((uint32_t)h3 << 16);
            dlo[rid * 64 + lane * 2]     = l0 | ((uint32_t)l1 << 16);
            dlo[rid * 64 + lane * 2 + 1] = l2 | ((uint32_t)l3 << 16);
        }
    }
}

// ================= K4: out = x + ao @ Wc + bc (transposed store) =================
// M = 64 t's per CTA, 256 threads, 2 CTAs/SM. B (Wc) in 64-row chunks.
#define K4_BIAS 0
#define K4_STG  512                 // f32 [64][129] = 33024
#define K4_AHI  33536
#define K4_ALO  50944
#define K4_BHI  68352
#define K4_BLO  85760
#define K4_SMEM 103168

__global__ __launch_bounds__(256, 2)
void k4_out(const float* __restrict__ x, float* __restrict__ out) {
    extern __shared__ char sm[];
    const int tid = threadIdx.x, warp = tid >> 5, lane = tid & 31;
    const int b = blockIdx.z, kj = blockIdx.y, t0 = blockIdx.x * 64;
    const uint32_t sb = s2u(sm);

    for (int idx = tid; idx < 1024; idx += 256) {       // A (ao rows, 64 t's)
        int row = idx >> 4, c8 = (idx & 15) * 8;
        uint32_t off = (uint32_t)(row * TPAD + c8) * 2;
        size_t rid = ((size_t)b * 4096 + t0 + row) * 24 + kj;
        cp16(sb + K4_AHI + off, g_ao_hi + rid * 128 + c8);
        cp16(sb + K4_ALO + off, g_ao_lo + rid * 128 + c8);
    }
    for (int idx = tid; idx < 1024; idx += 256) {       // B chunk 0
        int row = idx >> 4, c8 = (idx & 15) * 8;
        uint32_t off = (uint32_t)(row * TPAD + c8) * 2;
        cp16(sb + K4_BHI + off, g_wc_hi + row * 128 + c8);
        cp16(sb + K4_BLO + off, g_wc_lo + row * 128 + c8);
    }
    if (tid < 128) *(float*)(sm + K4_BIAS + tid * 4) = g_bc[tid];
    cp_commit();
    cp_wait0();
    __syncthreads();

    const int m0 = (warp & 3) * 16, n0 = (warp >> 2) * 32;
    for (int nc = 0; nc < 2; nc++) {
        float acc[1][4][4];
        #pragma unroll
        for (int j = 0; j < 4; j++)
            #pragma unroll
            for (int q = 0; q < 4; q++) acc[0][j][q] = 0.f;
        gemm3<1>(sb + K4_AHI, sb + K4_ALO, sb + K4_BHI, sb + K4_BLO, acc, lane, m0, n0);
        stash<1>((float*)(sm + K4_STG), acc, lane, m0, nc * 64 + n0);
        if (nc == 0) {
            __syncthreads();
            for (int idx = tid; idx < 1024; idx += 256) {
                int row = idx >> 4, c8 = (idx & 15) * 8;
                uint32_t off = (uint32_t)(row * TPAD + c8) * 2;
                cp16(sb + K4_BHI + off, g_wc_hi + (64 + row) * 128 + c8);
                cp16(sb + K4_BLO + off, g_wc_lo + (64 + row) * 128 + c8);
            }
            cp_commit();
            cp_wait0();
            __syncthreads();
        }
    }
    __syncthreads();

    {
        const float* stg  = (const float*)(sm + K4_STG);
        const float* bias = (const float*)(sm + K4_BIAS);
        for (int o = tid; o < 2048; o += 256) {
            int c = o >> 4, tq = o & 15;
            float bc = bias[c];
            size_t gb = ((size_t)(b * 3072 + kj * 128 + c)) * 4096 + t0;
            #pragma unroll
            for (int j = 0; j < 4; j++) {
                int t = tq + 16 * j;
                out[gb + t] = x[gb + t] + stg[t * 129 + c] + bc;
            }
        }
    }
}

// ================= host =================
extern "C" void kernel_launch(void* const* d_in, const int* in_sizes, int n_in,
                              void* d_out, int out_size)
{
    (void)in_sizes; (void)n_in; (void)out_size;
    const float* x      = (const float*)d_in[0];
    const float* W_tok  = (const float*)d_in[1];
    const float* b_tok  = (const float*)d_in[2];
    const float* g_norm = (const float*)d_in[3];
    const float* W_qkv  = (const float*)d_in[4];
    const float* b_qkv  = (const float*)d_in[5];
    const float* W_proj = (const float*)d_in[6];
    const float* b_proj = (const float*)d_in[7];
    const float* W_from = (const float*)d_in[8];
    const float* b_from = (const float*)d_in[9];
    float* out = (float*)d_out;

    cudaFuncSetAttribute(k1_tok, cudaFuncAttributeMaxDynamicSharedMemorySize, K1_SMEM);
    cudaFuncSetAttribute(k2_qkv, cudaFuncAttributeMaxDynamicSharedMemorySize, K2_SMEM);
    cudaFuncSetAttribute(k3_attn, cudaFuncAttributeMaxDynamicSharedMemorySize, K3_SMEM);
    cudaFuncSetAttribute(k4_out, cudaFuncAttributeMaxDynamicSharedMemorySize, K4_SMEM);

    k0a<<<4, 256>>>(W_proj, W_from, b_proj, b_from);
    k0b<<<192, 256>>>(W_tok, W_qkv);
    {
        dim3 g(64, 24, 4);
        k1_tok<<<g, 256, K1_SMEM>>>(x, b_tok, g_norm);
    }
    k2_qkv<<<MTOT / 128, 256, K2_SMEM>>>(b_qkv);
    {
        dim3 g(2048, 4);
        k3_attn<<<g, 256, K3_SMEM>>>();
    }
    {
        dim3 g(64, 24, 4);
        k4_out<<<g, 256, K4_SMEM>>>(x, out);
    }
}

// round 11
// speedup vs baseline: 2.4159x; 1.1093x over previous
#include <cuda_runtime.h>
#include <cuda_bf16.h>
#include <cstdint>

#define TLEN 4096
#define KJ   24
#define NBATCH 4
#define MTOT (NBATCH * KJ * TLEN)   // 393216 token rows
#define TPAD 136                     // bf16 elems per smem tile row (272B)

// ---------------- device scratch ----------------
__device__ __align__(256) __nv_bfloat16 g_tok_hi[(size_t)MTOT * 128];
__device__ __align__(256) __nv_bfloat16 g_tok_lo[(size_t)MTOT * 128];
__device__ __align__(256) __nv_bfloat16 g_ao_hi[(size_t)MTOT * 128];
__device__ __align__(256) __nv_bfloat16 g_ao_lo[(size_t)MTOT * 128];
__device__ __align__(256) float         g_wc[128 * 128];
__device__ __align__(256) float         g_bc[128];
__device__ __align__(256) __nv_bfloat16 g_wtok_hi[128 * 128], g_wtok_lo[128 * 128];
__device__ __align__(256) __nv_bfloat16 g_wqkv_hi[384 * 128], g_wqkv_lo[384 * 128];
__device__ __align__(256) __nv_bfloat16 g_wc_hi[128 * 128],   g_wc_lo[128 * 128];

typedef unsigned long long u64;

// ---------------- helpers ----------------
static __device__ __forceinline__ uint32_t s2u(const void* p) {
    uint32_t a;
    asm("{ .reg .u64 t; cvta.to.shared.u64 t, %1; cvt.u32.u64 %0, t; }" : "=r"(a) : "l"(p));
    return a;
}
static __device__ __forceinline__ void cp16(uint32_t dst, const void* src) {
    asm volatile("cp.async.cg.shared.global [%0], [%1], 16;" :: "r"(dst), "l"(src));
}
static __device__ __forceinline__ void cp_commit() {
    asm volatile("cp.async.commit_group;");
}
static __device__ __forceinline__ void cp_wait0() {
    asm volatile("cp.async.wait_group 0;" ::: "memory");
}
static __device__ __forceinline__ void split_bf(float v, uint16_t& h, uint16_t& l) {
    __nv_bfloat16 hb = __float2bfloat16(v);
    float r = v - __bfloat162float(hb);
    h = __bfloat16_as_ushort(hb);
    l = __bfloat16_as_ushort(__float2bfloat16(r));
}
static __device__ __forceinline__ void fma2(u64& d, u64 a, u64 b) {
    asm("fma.rn.f32x2 %0, %1, %2, %0;" : "+l"(d) : "l"(a), "l"(b));
}
static __device__ __forceinline__ void up2(u64 v, float& a, float& b) {
    asm("mov.b64 {%0, %1}, %2;" : "=f"(a), "=f"(b) : "l"(v));
}
static __device__ __forceinline__ void ldsm4(uint32_t* r, uint32_t addr) {
    asm volatile("ldmatrix.sync.aligned.m8n8.x4.shared.b16 {%0,%1,%2,%3}, [%4];"
                 : "=r"(r[0]), "=r"(r[1]), "=r"(r[2]), "=r"(r[3]) : "r"(addr));
}
static __device__ __forceinline__ void mma16816(float* c, const uint32_t* a, const uint32_t* b) {
    asm volatile("mma.sync.aligned.m16n8k16.row.col.f32.bf16.bf16.f32 "
                 "{%0,%1,%2,%3}, {%4,%5,%6,%7}, {%8,%9}, {%0,%1,%2,%3};"
                 : "+f"(c[0]), "+f"(c[1]), "+f"(c[2]), "+f"(c[3])
                 : "r"(a[0]), "r"(a[1]), "r"(a[2]), "r"(a[3]), "r"(b[0]), "r"(b[1]));
}

// one K=128 pass of a (MT*16)x(NT*16) warp tile
template<int MT, int NT>
static __device__ __forceinline__ void gemm_pass(uint32_t aBase, uint32_t bBase,
                                                 float acc[MT][2 * NT][4],
                                                 int lane, int m0, int n0) {
    const int ar = m0 + (lane & 15), ac = 8 * (lane >> 4);
    const int br = (lane & 7) + 8 * (lane >> 4), bc = 8 * ((lane >> 3) & 1);
    #pragma unroll
    for (int ks = 0; ks < 8; ks++) {
        uint32_t a[MT][4], b[NT][4];
        #pragma unroll
        for (int mt = 0; mt < MT; mt++)
            ldsm4(a[mt], aBase + (uint32_t)((ar + mt * 16) * TPAD + ks * 16 + ac) * 2);
        #pragma unroll
        for (int nt = 0; nt < NT; nt++)
            ldsm4(b[nt], bBase + (uint32_t)((n0 + nt * 16 + br) * TPAD + ks * 16 + bc) * 2);
        #pragma unroll
        for (int mt = 0; mt < MT; mt++)
            #pragma unroll
            for (int nt = 0; nt < NT; nt++) {
                mma16816(acc[mt][nt * 2],     a[mt], &b[nt][0]);
                mma16816(acc[mt][nt * 2 + 1], a[mt], &b[nt][2]);
            }
    }
}
template<int MT, int NT>
static __device__ __forceinline__ void gemm3(uint32_t aHi, uint32_t aLo, uint32_t bHi,
                                             uint32_t bLo, float acc[MT][2 * NT][4],
                                             int lane, int m0, int n0) {
    gemm_pass<MT, NT>(aHi, bHi, acc, lane, m0, n0);
    gemm_pass<MT, NT>(aHi, bLo, acc, lane, m0, n0);
    gemm_pass<MT, NT>(aLo, bHi, acc, lane, m0, n0);
}
// write C fragments (raw) into f32 staging, stride 129
template<int MT, int NT>
static __device__ __forceinline__ void stash(float* stg, const float acc[MT][2 * NT][4],
                                             int lane, int m0, int n0) {
    const int r = m0 + (lane >> 2), cq = (lane & 3) * 2;
    #pragma unroll
    for (int mt = 0; mt < MT; mt++)
        #pragma unroll
        for (int n8 = 0; n8 < 2 * NT; n8++) {
            const float* c = acc[mt][n8];
            int row = r + mt * 16, col = n0 + n8 * 8 + cq;
            stg[row * 129 + col]           = c[0];
            stg[row * 129 + col + 1]       = c[1];
            stg[(row + 8) * 129 + col]     = c[2];
            stg[(row + 8) * 129 + col + 1] = c[3];
        }
}

// ================= K0a: Wc = W_proj @ W_from, bc = b_proj@W_from + b_from =========
__global__ __launch_bounds__(256) void k0a(const float* __restrict__ Wp,
                                           const float* __restrict__ Wf,
                                           const float* __restrict__ bp,
                                           const float* __restrict__ bf) {
    __shared__ float swp[32 * 128];
    const int tid = threadIdx.x, r0 = blockIdx.x * 32;
    for (int i = tid; i < 32 * 128; i += 256) swp[i] = Wp[(r0 + (i >> 7)) * 128 + (i & 127)];
    __syncthreads();
    const int n = tid & 127, rb = tid >> 7;
    float acc[16];
    #pragma unroll
    for (int q = 0; q < 16; q++) acc[q] = 0.f;
    for (int m = 0; m < 128; m++) {
        float wf = Wf[m * 128 + n];
        #pragma unroll
        for (int q = 0; q < 16; q++) acc[q] += swp[(rb * 16 + q) * 128 + m] * wf;
    }
    #pragma unroll
    for (int q = 0; q < 16; q++) g_wc[(r0 + rb * 16 + q) * 128 + n] = acc[q];
    if (blockIdx.x == 0 && tid < 128) {
        float a = bf[tid];
        for (int m = 0; m < 128; m++) a += bp[m] * Wf[m * 128 + tid];
        g_bc[tid] = a;
    }
}

// ================= K0b: transpose + hi/lo split weights =================
__global__ __launch_bounds__(256) void k0b(const float* __restrict__ Wt,
                                           const float* __restrict__ Wq) {
    const int i = blockIdx.x * 256 + threadIdx.x;
    uint16_t h, l;
    if (i < 16384) {
        int n = i >> 7, k = i & 127;
        split_bf(Wt[k * 128 + n], h, l);
        g_wtok_hi[i] = __ushort_as_bfloat16(h); g_wtok_lo[i] = __ushort_as_bfloat16(l);
        split_bf(g_wc[k * 128 + n], h, l);
        g_wc_hi[i] = __ushort_as_bfloat16(h);   g_wc_lo[i] = __ushort_as_bfloat16(l);
    }
    if (i < 49152) {
        int n = i >> 7, k = i & 127;
        split_bf(Wq[k * 384 + n], h, l);
        g_wqkv_hi[i] = __ushort_as_bfloat16(h); g_wqkv_lo[i] = __ushort_as_bfloat16(l);
    }
}

// ================= K1: tok = x^T @ W_tok + b, RMSNorm, split-store ===============
// M = 64 t's per CTA, 256 threads, 2 CTAs/SM. B (W_tok) in 64-row chunks.
#define K1_BIAS 0
#define K1_G    512
#define K1_AXS  1024                 // x staging f32 [128][68]; reused as STG f32 [64][129]
#define K1_AHI  35840                // bf16 tile [64][TPAD] = 17408 B
#define K1_ALO  53248
#define K1_BHI  70656
#define K1_BLO  88064
#define K1_SMEM 105472

__global__ __launch_bounds__(256, 2)
void k1_tok(const float* __restrict__ x, const float* __restrict__ b_tok,
            const float* __restrict__ g_norm) {
    extern __shared__ char sm[];
    const int tid = threadIdx.x, warp = tid >> 5, lane = tid & 31;
    const int b = blockIdx.z, kj = blockIdx.y, t0 = blockIdx.x * 64;
    const uint32_t sb = s2u(sm);

    for (int idx = tid; idx < 2048; idx += 256) {       // x -> staging [c][t], 64 t's
        int c = idx >> 4, t16 = (idx & 15) * 4;
        const float* src = x + ((size_t)(b * 3072 + kj * 128 + c)) * 4096 + t0 + t16;
        cp16(sb + K1_AXS + (uint32_t)(c * 68 + t16) * 4, src);
    }
    for (int idx = tid; idx < 1024; idx += 256) {       // B chunk 0 (rows 0..63)
        int row = idx >> 4, c8 = (idx & 15) * 8;
        uint32_t off = (uint32_t)(row * TPAD + c8) * 2;
        cp16(sb + K1_BHI + off, g_wtok_hi + row * 128 + c8);
        cp16(sb + K1_BLO + off, g_wtok_lo + row * 128 + c8);
    }
    if (tid < 128) {
        *(float*)(sm + K1_BIAS + tid * 4) = b_tok[tid];
        *(float*)(sm + K1_G + tid * 4)    = g_norm[tid];
    }
    cp_commit();
    cp_wait0();
    __syncthreads();

    // convert staging -> split A tiles (rows = t, 64 rows)
    {
        const int t = tid & 63, quarter = tid >> 6;
        const float* ax = (const float*)(sm + K1_AXS);
        for (int c4 = quarter * 8; c4 < quarter * 8 + 8; c4++) {
            int c = c4 * 4;
            float v0 = ax[(c + 0) * 68 + t], v1 = ax[(c + 1) * 68 + t];
            float v2 = ax[(c + 2) * 68 + t], v3 = ax[(c + 3) * 68 + t];
            uint16_t h0, l0, h1, l1, h2, l2, h3, l3;
            split_bf(v0, h0, l0); split_bf(v1, h1, l1);
            split_bf(v2, h2, l2); split_bf(v3, h3, l3);
            uint32_t off = (uint32_t)(t * TPAD + c) * 2;
            *(uint2*)(sm + K1_AHI + off) = make_uint2(h0 | ((uint32_t)h1 << 16), h2 | ((uint32_t)h3 << 16));
            *(uint2*)(sm + K1_ALO + off) = make_uint2(l0 | ((uint32_t)l1 << 16), l2 | ((uint32_t)l3 << 16));
        }
    }
    __syncthreads();

    // GEMM: 2 chunks of 64 output cols; warp tile 16x32 (8 warps = 4M x 2N)
    const int m0 = (warp & 3) * 16, n0 = (warp >> 2) * 32;
    for (int nc = 0; nc < 2; nc++) {
        float acc[1][4][4];
        #pragma unroll
        for (int j = 0; j < 4; j++)
            #pragma unroll
            for (int q = 0; q < 4; q++) acc[0][j][q] = 0.f;
        gemm3<1, 2>(sb + K1_AHI, sb + K1_ALO, sb + K1_BHI, sb + K1_BLO, acc, lane, m0, n0);
        stash<1, 2>((float*)(sm + K1_AXS), acc, lane, m0, nc * 64 + n0);
        if (nc == 0) {
            __syncthreads();
            for (int idx = tid; idx < 1024; idx += 256) {   // B chunk 1 (rows 64..127)
                int row = idx >> 4, c8 = (idx & 15) * 8;
                uint32_t off = (uint32_t)(row * TPAD + c8) * 2;
                cp16(sb + K1_BHI + off, g_wtok_hi + (64 + row) * 128 + c8);
                cp16(sb + K1_BLO + off, g_wtok_lo + (64 + row) * 128 + c8);
            }
            cp_commit();
            cp_wait0();
            __syncthreads();
        }
    }
    __syncthreads();

    // RMSNorm + split: 4 threads per row (64 rows)
    uint32_t* shi = (uint32_t*)(sm + K1_AHI);
    uint32_t* slo = (uint32_t*)(sm + K1_ALO);
    {
        const int row = tid >> 2, sub = tid & 3;
        const float* stg  = (const float*)(sm + K1_AXS);
        const float* bias = (const float*)(sm + K1_BIAS);
        const float* gw   = (const float*)(sm + K1_G);
        float ss = 0.f;
        #pragma unroll 8
        for (int c = sub * 32; c < sub * 32 + 32; c++) {
            float v = stg[row * 129 + c] + bias[c];
            ss += v * v;
        }
        ss += __shfl_xor_sync(0xffffffffu, ss, 1);
        ss += __shfl_xor_sync(0xffffffffu, ss, 2);
        float inv = rsqrtf(ss * (1.0f / 128.0f) + 1e-5f);
        #pragma unroll 4
        for (int c2 = 0; c2 < 16; c2++) {
            int c = sub * 32 + c2 * 2;
            float v0 = (stg[row * 129 + c]     + bias[c])     * inv * gw[c];
            float v1 = (stg[row * 129 + c + 1] + bias[c + 1]) * inv * gw[c + 1];
            uint16_t h0, l0, h1, l1;
            split_bf(v0, h0, l0); split_bf(v1, h1, l1);
            shi[row * 65 + sub * 16 + c2] = h0 | ((uint32_t)h1 << 16);
            slo[row * 65 + sub * 16 + c2] = l0 | ((uint32_t)l1 << 16);
        }
    }
    __syncthreads();
    {
        uint32_t* dhi = (uint32_t*)g_tok_hi;
        uint32_t* dlo = (uint32_t*)g_tok_lo;
        for (int idx = tid; idx < 4096; idx += 256) {
            int row = idx >> 6, w = idx & 63;
            size_t rid = ((size_t)b * 4096 + t0 + row) * 24 + kj;
            dhi[rid * 64 + w] = shi[row * 65 + w];
            dlo[rid * 64 + w] = slo[row * 65 + w];
        }
    }
}

// ================= K23: fused qkv GEMM + attention (qkv stays in smem) ===========
// M = 96 rows = 4 complete t-groups per CTA. 384 threads, 1 CTA/SM.
#define QS 386
#define PRS 52
#define J_BIAS 0                     // 384 f32
#define J_AHI  1536                  // [96][TPAD] bf16 = 26112
#define J_ALO  27648
#define J_B    53760                 // single-split B chunk [64][TPAD] = 17408
#define J_QKV  71168                 // f32 [96][QS] = 148224
#define K23_SMEM 219392
#define J_PROBS J_AHI                // probs overlay (A dead after GEMM): 4*24*52*4 = 19968

__global__ __launch_bounds__(384, 1)
void k23(const float* __restrict__ b_qkv) {
    extern __shared__ char sm[];
    const int tid = threadIdx.x, warp = tid >> 5, lane = tid & 31;
    const int b = blockIdx.y, t0 = blockIdx.x * 4;
    const size_t rid0 = ((size_t)b * 4096 + t0) * 24;
    const uint32_t sb = s2u(sm);

    // load A tiles (96 rows) + bias
    for (int idx = tid; idx < 1536; idx += 384) {
        int row = idx >> 4, c8 = (idx & 15) * 8;
        uint32_t off = (uint32_t)(row * TPAD + c8) * 2;
        cp16(sb + J_AHI + off, g_tok_hi + (rid0 + row) * 128 + c8);
        cp16(sb + J_ALO + off, g_tok_lo + (rid0 + row) * 128 + c8);
    }
    if (tid < 384) *(float*)(sm + J_BIAS + tid * 4) = b_qkv[tid];
    cp_commit();
    cp_wait0();
    __syncthreads();

    // GEMM: 6 chunks of 64 cols; 12 warps = 3M(32) x 4N(16)
    const int m0 = (warp % 3) * 32, n0 = (warp / 3) * 16;
    float* qkv = (float*)(sm + J_QKV);
    const float* bias = (const float*)(sm + J_BIAS);

    for (int nc = 0; nc < 6; nc++) {
        // B_hi chunk (rows nc*64 .. +63)
        for (int idx = tid; idx < 1024; idx += 384) {
            int row = idx >> 4, c8 = (idx & 15) * 8;
            cp16(sb + J_B + (uint32_t)(row * TPAD + c8) * 2,
                 g_wqkv_hi + (nc * 64 + row) * 128 + c8);
        }
        cp_commit();
        cp_wait0();
        __syncthreads();

        float acc[2][2][4];
        #pragma unroll
        for (int i = 0; i < 2; i++)
            #pragma unroll
            for (int j = 0; j < 2; j++)
                #pragma unroll
                for (int q = 0; q < 4; q++) acc[i][j][q] = 0.f;
        gemm_pass<2, 1>(sb + J_AHI, sb + J_B, acc, lane, m0, n0);   // hi*hi
        gemm_pass<2, 1>(sb + J_ALO, sb + J_B, acc, lane, m0, n0);   // lo*hi
        __syncthreads();

        // B_lo chunk
        for (int idx = tid; idx < 1024; idx += 384) {
            int row = idx >> 4, c8 = (idx & 15) * 8;
            cp16(sb + J_B + (uint32_t)(row * TPAD + c8) * 2,
                 g_wqkv_lo + (nc * 64 + row) * 128 + c8);
        }
        cp_commit();
        cp_wait0();
        __syncthreads();
        gemm_pass<2, 1>(sb + J_AHI, sb + J_B, acc, lane, m0, n0);   // hi*lo

        // epilogue -> qkv smem (+bias)
        {
            const int r = m0 + (lane >> 2), cq = (lane & 3) * 2;
            #pragma unroll
            for (int mt = 0; mt < 2; mt++)
                #pragma unroll
                for (int n8 = 0; n8 < 2; n8++) {
                    const float* c = acc[mt][n8];
                    int col = nc * 64 + n0 + n8 * 8 + cq;
                    int row = r + mt * 16;
                    qkv[row * QS + col]           = c[0] + bias[col];
                    qkv[row * QS + col + 1]       = c[1] + bias[col + 1];
                    qkv[(row + 8) * QS + col]     = c[2] + bias[col];
                    qkv[(row + 8) * QS + col + 1] = c[3] + bias[col + 1];
                }
        }
        __syncthreads();
    }

    // ---- attention (probs overlay A region) ----
    float* probs = (float*)(sm + J_PROBS);

    for (int o = tid; o < 576; o += 384) {     // 4 tl x 12 x 12 2x2 tiles
        int tl = o / 144, rem = o - tl * 144;
        int ti = rem / 12, tj = rem - ti * 12;
        int i = 2 * ti, j = 2 * tj;
        const u64* q0 = reinterpret_cast<const u64*>(qkv + (tl * 24 + i) * QS);
        const u64* q1 = reinterpret_cast<const u64*>(qkv + (tl * 24 + i + 1) * QS);
        const u64* k0 = reinterpret_cast<const u64*>(qkv + (tl * 24 + j) * QS + 128);
        const u64* k1 = reinterpret_cast<const u64*>(qkv + (tl * 24 + j + 1) * QS + 128);
        u64 a00 = 0ull, a01 = 0ull, a10 = 0ull, a11 = 0ull;
        #pragma unroll 8
        for (int c2 = 0; c2 < 64; c2++) {
            u64 qa = q0[c2], qb = q1[c2], ka = k0[c2], kb = k1[c2];
            fma2(a00, qa, ka);
            fma2(a01, qa, kb);
            fma2(a10, qb, ka);
            fma2(a11, qb, kb);
        }
        float s0, s1;
        const float SC = 0.08838834764831845f;
        float* pr = probs + (tl * 24 + i) * PRS;
        up2(a00, s0, s1); pr[2 * j]             = (s0 + s1) * SC;
        up2(a01, s0, s1); pr[2 * (j + 1)]       = (s0 + s1) * SC;
        up2(a10, s0, s1); pr[PRS + 2 * j]       = (s0 + s1) * SC;
        up2(a11, s0, s1); pr[PRS + 2 * (j + 1)] = (s0 + s1) * SC;
    }
    __syncthreads();

    if (tid < 96) {
        int tl = tid / 24, i = tid - tl * 24;
        float* pr = probs + (tl * 24 + i) * PRS;
        float m = pr[0];
        #pragma unroll
        for (int j = 1; j < 24; j++) m = fmaxf(m, pr[2 * j]);
        float s = 0.f, e[24];
        #pragma unroll
        for (int j = 0; j < 24; j++) { e[j] = __expf(pr[2 * j] - m); s += e[j]; }
        float inv = 1.0f / s;
        #pragma unroll
        for (int j = 0; j < 24; j++) {
            float p = e[j] * inv;
            *reinterpret_cast<float2*>(pr + 2 * j) = make_float2(p, p);
        }
    }
    __syncthreads();

    // AV: 12 warps: tl = warp/3, 8 joints per warp
    {
        const int tl = warp / 3, i0 = (warp % 3) * 8, d0 = lane * 4;
        u64 acc[8][2];
        #pragma unroll
        for (int ii = 0; ii < 8; ii++) { acc[ii][0] = 0ull; acc[ii][1] = 0ull; }
        const float* pr0 = probs + (tl * 24 + i0) * PRS;
        #pragma unroll 4
        for (int j = 0; j < 24; j++) {
            const u64* vp = reinterpret_cast<const u64*>(qkv + (tl * 24 + j) * QS + 256 + d0);
            u64 va = vp[0], vb = vp[1];
            #pragma unroll
            for (int ii = 0; ii < 8; ii++) {
                float p = pr0[ii * PRS + 2 * j];
                u64 p2;
                asm("mov.b64 %0, {%1, %1};" : "=l"(p2) : "f"(p));
                fma2(acc[ii][0], p2, va);
                fma2(acc[ii][1], p2, vb);
            }
        }
        uint32_t* dhi = (uint32_t*)g_ao_hi;
        uint32_t* dlo = (uint32_t*)g_ao_lo;
        #pragma unroll
        for (int ii = 0; ii < 8; ii++) {
            float v0, v1, v2, v3;
            up2(acc[ii][0], v0, v1);
            up2(acc[ii][1], v2, v3);
            uint16_t h0, l0, h1, l1, h2, l2, h3, l3;
            split_bf(v0, h0, l0); split_bf(v1, h1, l1);
            split_bf(v2, h2, l2); split_bf(v3, h3, l3);
            size_t rid = rid0 + tl * 24 + i0 + ii;
            dhi[rid * 64 + lane * 2]     = h0 | ((uint32_t)h1 << 16);
            dhi[rid * 64 + lane * 2 + 1] = h2 | ((uint32_t)h3 << 16);
            dlo[rid * 64 + lane * 2]     = l0 | ((uint32_t)l1 << 16);
            dlo[rid * 64 + lane * 2 + 1] = l2 | ((uint32_t)l3 << 16);
        }
    }
}

// ================= K4: out = x + ao @ Wc + bc (transposed store) =================
// M = 64 t's per CTA, 256 threads, 2 CTAs/SM. B (Wc) in 64-row chunks.
#define K4_BIAS 0
#define K4_STG  512                 // f32 [64][129] = 33024
#define K4_AHI  33536
#define K4_ALO  50944
#define K4_BHI  68352
#define K4_BLO  85760
#define K4_SMEM 103168

__global__ __launch_bounds__(256, 2)
void k4_out(const float* __restrict__ x, float* __restrict__ out) {
    extern __shared__ char sm[];
    const int tid = threadIdx.x, warp = tid >> 5, lane = tid & 31;
    const int b = blockIdx.z, kj = blockIdx.y, t0 = blockIdx.x * 64;
    const uint32_t sb = s2u(sm);

    for (int idx = tid; idx < 1024; idx += 256) {       // A (ao rows, 64 t's)
        int row = idx >> 4, c8 = (idx & 15) * 8;
        uint32_t off = (uint32_t)(row * TPAD + c8) * 2;
        size_t rid = ((size_t)b * 4096 + t0 + row) * 24 + kj;
        cp16(sb + K4_AHI + off, g_ao_hi + rid * 128 + c8);
        cp16(sb + K4_ALO + off, g_ao_lo + rid * 128 + c8);
    }
    for (int idx = tid; idx < 1024; idx += 256) {       // B chunk 0
        int row = idx >> 4, c8 = (idx & 15) * 8;
        uint32_t off = (uint32_t)(row * TPAD + c8) * 2;
        cp16(sb + K4_BHI + off, g_wc_hi + row * 128 + c8);
        cp16(sb + K4_BLO + off, g_wc_lo + row * 128 + c8);
    }
    if (tid < 128) *(float*)(sm + K4_BIAS + tid * 4) = g_bc[tid];
    cp_commit();
    cp_wait0();
    __syncthreads();

    const int m0 = (warp & 3) * 16, n0 = (warp >> 2) * 32;
    for (int nc = 0; nc < 2; nc++) {
        float acc[1][4][4];
        #pragma unroll
        for (int j = 0; j < 4; j++)
            #pragma unroll
            for (int q = 0; q < 4; q++) acc[0][j][q] = 0.f;
        gemm3<1, 2>(sb + K4_AHI, sb + K4_ALO, sb + K4_BHI, sb + K4_BLO, acc, lane, m0, n0);
        stash<1, 2>((float*)(sm + K4_STG), acc, lane, m0, nc * 64 + n0);
        if (nc == 0) {
            __syncthreads();
            for (int idx = tid; idx < 1024; idx += 256) {
                int row = idx >> 4, c8 = (idx & 15) * 8;
                uint32_t off = (uint32_t)(row * TPAD + c8) * 2;
                cp16(sb + K4_BHI + off, g_wc_hi + (64 + row) * 128 + c8);
                cp16(sb + K4_BLO + off, g_wc_lo + (64 + row) * 128 + c8);
            }
            cp_commit();
            cp_wait0();
            __syncthreads();
        }
    }
    __syncthreads();

    {
        const float* stg  = (const float*)(sm + K4_STG);
        const float* bias = (const float*)(sm + K4_BIAS);
        for (int o = tid; o < 2048; o += 256) {
            int c = o >> 4, tq = o & 15;
            float bc = bias[c];
            size_t gb = ((size_t)(b * 3072 + kj * 128 + c)) * 4096 + t0;
            #pragma unroll
            for (int j = 0; j < 4; j++) {
                int t = tq + 16 * j;
                out[gb + t] = x[gb + t] + stg[t * 129 + c] + bc;
            }
        }
    }
}

// ================= host =================
extern "C" void kernel_launch(void* const* d_in, const int* in_sizes, int n_in,
                              void* d_out, int out_size)
{
    (void)in_sizes; (void)n_in; (void)out_size;
    const float* x      = (const float*)d_in[0];
    const float* W_tok  = (const float*)d_in[1];
    const float* b_tok  = (const float*)d_in[2];
    const float* g_norm = (const float*)d_in[3];
    const float* W_qkv  = (const float*)d_in[4];
    const float* b_qkv  = (const float*)d_in[5];
    const float* W_proj = (const float*)d_in[6];
    const float* b_proj = (const float*)d_in[7];
    const float* W_from = (const float*)d_in[8];
    const float* b_from = (const float*)d_in[9];
    float* out = (float*)d_out;

    cudaFuncSetAttribute(k1_tok, cudaFuncAttributeMaxDynamicSharedMemorySize, K1_SMEM);
    cudaFuncSetAttribute(k23,    cudaFuncAttributeMaxDynamicSharedMemorySize, K23_SMEM);
    cudaFuncSetAttribute(k4_out, cudaFuncAttributeMaxDynamicSharedMemorySize, K4_SMEM);

    k0a<<<4, 256>>>(W_proj, W_from, b_proj, b_from);
    k0b<<<192, 256>>>(W_tok, W_qkv);
    {
        dim3 g(64, 24, 4);
        k1_tok<<<g, 256, K1_SMEM>>>(x, b_tok, g_norm);
    }
    {
        dim3 g(1024, 4);
        k23<<<g, 384, K23_SMEM>>>(b_qkv);
    }
    {
        dim3 g(64, 24, 4);
        k4_out<<<g, 256, K4_SMEM>>>(x, out);
    }
}

// round 13
// speedup vs baseline: 2.4680x; 1.0216x over previous
#include <cuda_runtime.h>
#include <cuda_bf16.h>
#include <cstdint>

#define TLEN 4096
#define KJ   24
#define NBATCH 4
#define MTOT (NBATCH * KJ * TLEN)   // 393216 token rows
#define TPAD 136                     // bf16 elems per smem tile row (272B)

// ---------------- device scratch ----------------
__device__ __align__(256) __nv_bfloat16 g_tok_hi[(size_t)MTOT * 128];
__device__ __align__(256) __nv_bfloat16 g_tok_lo[(size_t)MTOT * 128];
__device__ __align__(256) __nv_bfloat16 g_ao_hi[(size_t)MTOT * 128];
__device__ __align__(256) __nv_bfloat16 g_ao_lo[(size_t)MTOT * 128];
__device__ __align__(256) float         g_wc[128 * 128];
__device__ __align__(256) float         g_bc[128];
__device__ __align__(256) __nv_bfloat16 g_wtok_hi[128 * 128], g_wtok_lo[128 * 128];
__device__ __align__(256) __nv_bfloat16 g_wqkv_hi[384 * 128], g_wqkv_lo[384 * 128];
__device__ __align__(256) __nv_bfloat16 g_wc_hi[128 * 128],   g_wc_lo[128 * 128];

typedef unsigned long long u64;

// ---------------- helpers ----------------
static __device__ __forceinline__ uint32_t s2u(const void* p) {
    uint32_t a;
    asm("{ .reg .u64 t; cvta.to.shared.u64 t, %1; cvt.u32.u64 %0, t; }" : "=r"(a) : "l"(p));
    return a;
}
static __device__ __forceinline__ void cp16(uint32_t dst, const void* src) {
    asm volatile("cp.async.cg.shared.global [%0], [%1], 16;" :: "r"(dst), "l"(src));
}
static __device__ __forceinline__ void cp_commit() {
    asm volatile("cp.async.commit_group;");
}
static __device__ __forceinline__ void cp_wait0() {
    asm volatile("cp.async.wait_group 0;" ::: "memory");
}
static __device__ __forceinline__ void split_bf(float v, uint16_t& h, uint16_t& l) {
    __nv_bfloat16 hb = __float2bfloat16(v);
    float r = v - __bfloat162float(hb);
    h = __bfloat16_as_ushort(hb);
    l = __bfloat16_as_ushort(__float2bfloat16(r));
}
static __device__ __forceinline__ void fma2(u64& d, u64 a, u64 b) {
    asm("fma.rn.f32x2 %0, %1, %2, %0;" : "+l"(d) : "l"(a), "l"(b));
}
static __device__ __forceinline__ void up2(u64 v, float& a, float& b) {
    asm("mov.b64 {%0, %1}, %2;" : "=f"(a), "=f"(b) : "l"(v));
}
static __device__ __forceinline__ void ldsm4(uint32_t* r, uint32_t addr) {
    asm volatile("ldmatrix.sync.aligned.m8n8.x4.shared.b16 {%0,%1,%2,%3}, [%4];"
                 : "=r"(r[0]), "=r"(r[1]), "=r"(r[2]), "=r"(r[3]) : "r"(addr));
}
static __device__ __forceinline__ void mma16816(float* c, const uint32_t* a, const uint32_t* b) {
    asm volatile("mma.sync.aligned.m16n8k16.row.col.f32.bf16.bf16.f32 "
                 "{%0,%1,%2,%3}, {%4,%5,%6,%7}, {%8,%9}, {%0,%1,%2,%3};"
                 : "+f"(c[0]), "+f"(c[1]), "+f"(c[2]), "+f"(c[3])
                 : "r"(a[0]), "r"(a[1]), "r"(a[2]), "r"(a[3]), "r"(b[0]), "r"(b[1]));
}

// one K=128 pass of a (MT*16)x(NT*16) warp tile
template<int MT, int NT>
static __device__ __forceinline__ void gemm_pass(uint32_t aBase, uint32_t bBase,
                                                 float acc[MT][2 * NT][4],
                                                 int lane, int m0, int n0) {
    const int ar = m0 + (lane & 15), ac = 8 * (lane >> 4);
    const int br = (lane & 7) + 8 * (lane >> 4), bc = 8 * ((lane >> 3) & 1);
    #pragma unroll
    for (int ks = 0; ks < 8; ks++) {
        uint32_t a[MT][4], b[NT][4];
        #pragma unroll
        for (int mt = 0; mt < MT; mt++)
            ldsm4(a[mt], aBase + (uint32_t)((ar + mt * 16) * TPAD + ks * 16 + ac) * 2);
        #pragma unroll
        for (int nt = 0; nt < NT; nt++)
            ldsm4(b[nt], bBase + (uint32_t)((n0 + nt * 16 + br) * TPAD + ks * 16 + bc) * 2);
        #pragma unroll
        for (int mt = 0; mt < MT; mt++)
            #pragma unroll
            for (int nt = 0; nt < NT; nt++) {
                mma16816(acc[mt][nt * 2],     a[mt], &b[nt][0]);
                mma16816(acc[mt][nt * 2 + 1], a[mt], &b[nt][2]);
            }
    }
}
template<int MT, int NT>
static __device__ __forceinline__ void gemm3(uint32_t aHi, uint32_t aLo, uint32_t bHi,
                                             uint32_t bLo, float acc[MT][2 * NT][4],
                                             int lane, int m0, int n0) {
    gemm_pass<MT, NT>(aHi, bHi, acc, lane, m0, n0);
    gemm_pass<MT, NT>(aHi, bLo, acc, lane, m0, n0);
    gemm_pass<MT, NT>(aLo, bHi, acc, lane, m0, n0);
}
// write C fragments (raw) into f32 staging, stride 129
template<int MT, int NT>
static __device__ __forceinline__ void stash(float* stg, const float acc[MT][2 * NT][4],
                                             int lane, int m0, int n0) {
    const int r = m0 + (lane >> 2), cq = (lane & 3) * 2;
    #pragma unroll
    for (int mt = 0; mt < MT; mt++)
        #pragma unroll
        for (int n8 = 0; n8 < 2 * NT; n8++) {
            const float* c = acc[mt][n8];
            int row = r + mt * 16, col = n0 + n8 * 8 + cq;
            stg[row * 129 + col]           = c[0];
            stg[row * 129 + col + 1]       = c[1];
            stg[(row + 8) * 129 + col]     = c[2];
            stg[(row + 8) * 129 + col + 1] = c[3];
        }
}

// ================= K0a: Wc = W_proj @ W_from, bc = b_proj@W_from + b_from =========
__global__ __launch_bounds__(256) void k0a(const float* __restrict__ Wp,
                                           const float* __restrict__ Wf,
                                           const float* __restrict__ bp,
                                           const float* __restrict__ bf) {
    __shared__ float swp[32 * 128];
    const int tid = threadIdx.x, r0 = blockIdx.x * 32;
    for (int i = tid; i < 32 * 128; i += 256) swp[i] = Wp[(r0 + (i >> 7)) * 128 + (i & 127)];
    __syncthreads();
    const int n = tid & 127, rb = tid >> 7;
    float acc[16];
    #pragma unroll
    for (int q = 0; q < 16; q++) acc[q] = 0.f;
    for (int m = 0; m < 128; m++) {
        float wf = Wf[m * 128 + n];
        #pragma unroll
        for (int q = 0; q < 16; q++) acc[q] += swp[(rb * 16 + q) * 128 + m] * wf;
    }
    #pragma unroll
    for (int q = 0; q < 16; q++) g_wc[(r0 + rb * 16 + q) * 128 + n] = acc[q];
    if (blockIdx.x == 0 && tid < 128) {
        float a = bf[tid];
        for (int m = 0; m < 128; m++) a += bp[m] * Wf[m * 128 + tid];
        g_bc[tid] = a;
    }
}

// ================= K0b: transpose + hi/lo split weights =================
__global__ __launch_bounds__(256) void k0b(const float* __restrict__ Wt,
                                           const float* __restrict__ Wq) {
    const int i = blockIdx.x * 256 + threadIdx.x;
    uint16_t h, l;
    if (i < 16384) {
        int n = i >> 7, k = i & 127;
        split_bf(Wt[k * 128 + n], h, l);
        g_wtok_hi[i] = __ushort_as_bfloat16(h); g_wtok_lo[i] = __ushort_as_bfloat16(l);
        split_bf(g_wc[k * 128 + n], h, l);
        g_wc_hi[i] = __ushort_as_bfloat16(h);   g_wc_lo[i] = __ushort_as_bfloat16(l);
    }
    if (i < 49152) {
        int n = i >> 7, k = i & 127;
        split_bf(Wq[k * 384 + n], h, l);
        g_wqkv_hi[i] = __ushort_as_bfloat16(h); g_wqkv_lo[i] = __ushort_as_bfloat16(l);
    }
}

// ================= K1: tok = x^T @ W_tok + b, RMSNorm, split-store ===============
#define K1_BIAS 0
#define K1_G    512
#define K1_AXS  1024
#define K1_AHI  35840
#define K1_ALO  53248
#define K1_BHI  70656
#define K1_BLO  88064
#define K1_SMEM 105472

__global__ __launch_bounds__(256, 2)
void k1_tok(const float* __restrict__ x, const float* __restrict__ b_tok,
            const float* __restrict__ g_norm) {
    extern __shared__ char sm[];
    const int tid = threadIdx.x, warp = tid >> 5, lane = tid & 31;
    const int b = blockIdx.z, kj = blockIdx.y, t0 = blockIdx.x * 64;
    const uint32_t sb = s2u(sm);

    for (int idx = tid; idx < 2048; idx += 256) {
        int c = idx >> 4, t16 = (idx & 15) * 4;
        const float* src = x + ((size_t)(b * 3072 + kj * 128 + c)) * 4096 + t0 + t16;
        cp16(sb + K1_AXS + (uint32_t)(c * 68 + t16) * 4, src);
    }
    for (int idx = tid; idx < 1024; idx += 256) {
        int row = idx >> 4, c8 = (idx & 15) * 8;
        uint32_t off = (uint32_t)(row * TPAD + c8) * 2;
        cp16(sb + K1_BHI + off, g_wtok_hi + row * 128 + c8);
        cp16(sb + K1_BLO + off, g_wtok_lo + row * 128 + c8);
    }
    if (tid < 128) {
        *(float*)(sm + K1_BIAS + tid * 4) = b_tok[tid];
        *(float*)(sm + K1_G + tid * 4)    = g_norm[tid];
    }
    cp_commit();
    cp_wait0();
    __syncthreads();

    {
        const int t = tid & 63, quarter = tid >> 6;
        const float* ax = (const float*)(sm + K1_AXS);
        for (int c4 = quarter * 8; c4 < quarter * 8 + 8; c4++) {
            int c = c4 * 4;
            float v0 = ax[(c + 0) * 68 + t], v1 = ax[(c + 1) * 68 + t];
            float v2 = ax[(c + 2) * 68 + t], v3 = ax[(c + 3) * 68 + t];
            uint16_t h0, l0, h1, l1, h2, l2, h3, l3;
            split_bf(v0, h0, l0); split_bf(v1, h1, l1);
            split_bf(v2, h2, l2); split_bf(v3, h3, l3);
            uint32_t off = (uint32_t)(t * TPAD + c) * 2;
            *(uint2*)(sm + K1_AHI + off) = make_uint2(h0 | ((uint32_t)h1 << 16), h2 | ((uint32_t)h3 << 16));
            *(uint2*)(sm + K1_ALO + off) = make_uint2(l0 | ((uint32_t)l1 << 16), l2 | ((uint32_t)l3 << 16));
        }
    }
    __syncthreads();

    const int m0 = (warp & 3) * 16, n0 = (warp >> 2) * 32;
    for (int nc = 0; nc < 2; nc++) {
        float acc[1][4][4];
        #pragma unroll
        for (int j = 0; j < 4; j++)
            #pragma unroll
            for (int q = 0; q < 4; q++) acc[0][j][q] = 0.f;
        gemm3<1, 2>(sb + K1_AHI, sb + K1_ALO, sb + K1_BHI, sb + K1_BLO, acc, lane, m0, n0);
        stash<1, 2>((float*)(sm + K1_AXS), acc, lane, m0, nc * 64 + n0);
        if (nc == 0) {
            __syncthreads();
            for (int idx = tid; idx < 1024; idx += 256) {
                int row = idx >> 4, c8 = (idx & 15) * 8;
                uint32_t off = (uint32_t)(row * TPAD + c8) * 2;
                cp16(sb + K1_BHI + off, g_wtok_hi + (64 + row) * 128 + c8);
                cp16(sb + K1_BLO + off, g_wtok_lo + (64 + row) * 128 + c8);
            }
            cp_commit();
            cp_wait0();
            __syncthreads();
        }
    }
    __syncthreads();

    uint32_t* shi = (uint32_t*)(sm + K1_AHI);
    uint32_t* slo = (uint32_t*)(sm + K1_ALO);
    {
        const int row = tid >> 2, sub = tid & 3;
        const float* stg  = (const float*)(sm + K1_AXS);
        const float* bias = (const float*)(sm + K1_BIAS);
        const float* gw   = (const float*)(sm + K1_G);
        float ss = 0.f;
        #pragma unroll 8
        for (int c = sub * 32; c < sub * 32 + 32; c++) {
            float v = stg[row * 129 + c] + bias[c];
            ss += v * v;
        }
        ss += __shfl_xor_sync(0xffffffffu, ss, 1);
        ss += __shfl_xor_sync(0xffffffffu, ss, 2);
        float inv = rsqrtf(ss * (1.0f / 128.0f) + 1e-5f);
        #pragma unroll 4
        for (int c2 = 0; c2 < 16; c2++) {
            int c = sub * 32 + c2 * 2;
            float v0 = (stg[row * 129 + c]     + bias[c])     * inv * gw[c];
            float v1 = (stg[row * 129 + c + 1] + bias[c + 1]) * inv * gw[c + 1];
            uint16_t h0, l0, h1, l1;
            split_bf(v0, h0, l0); split_bf(v1, h1, l1);
            shi[row * 65 + sub * 16 + c2] = h0 | ((uint32_t)h1 << 16);
            slo[row * 65 + sub * 16 + c2] = l0 | ((uint32_t)l1 << 16);
        }
    }
    __syncthreads();
    {
        uint32_t* dhi = (uint32_t*)g_tok_hi;
        uint32_t* dlo = (uint32_t*)g_tok_lo;
        for (int idx = tid; idx < 4096; idx += 256) {
            int row = idx >> 6, w = idx & 63;
            size_t rid = ((size_t)b * 4096 + t0 + row) * 24 + kj;
            dhi[rid * 64 + w] = shi[row * 65 + w];
            dlo[rid * 64 + w] = slo[row * 65 + w];
        }
    }
}

// ================= K23: fused qkv GEMM + attention (qkv stays in smem) ===========
// M = 96 rows = 4 complete t-groups per CTA. 384 threads, 1 CTA/SM.
// A_hi fragments hoisted to registers: passes hi*hi and hi*lo do 1 ldsm / 4 mma.
#define QS 386
#define PRS 52
#define J_BIAS 0                     // 384 f32
#define J_AHI  1536                  // [96][TPAD] bf16 = 26112
#define J_ALO  27648
#define J_B    53760                 // single-split B chunk [64][TPAD] = 17408
#define J_QKV  71168                 // f32 [96][QS] = 148224
#define K23_SMEM 219392
#define J_PROBS J_AHI                // probs overlay: 4*24*52*4 = 19968

__global__ __launch_bounds__(384, 1)
void k23(const float* __restrict__ b_qkv) {
    extern __shared__ char sm[];
    const int tid = threadIdx.x, warp = tid >> 5, lane = tid & 31;
    const int b = blockIdx.y, t0 = blockIdx.x * 4;
    const size_t rid0 = ((size_t)b * 4096 + t0) * 24;
    const uint32_t sb = s2u(sm);

    // load A tiles (96 rows) + bias
    for (int idx = tid; idx < 1536; idx += 384) {
        int row = idx >> 4, c8 = (idx & 15) * 8;
        uint32_t off = (uint32_t)(row * TPAD + c8) * 2;
        cp16(sb + J_AHI + off, g_tok_hi + (rid0 + row) * 128 + c8);
        cp16(sb + J_ALO + off, g_tok_lo + (rid0 + row) * 128 + c8);
    }
    *(float*)(sm + J_BIAS + tid * 4) = b_qkv[tid];
    cp_commit();
    cp_wait0();
    __syncthreads();

    // 12 warps = 3M(32) x 4N(16)
    const int m0 = (warp % 3) * 32, n0 = (warp / 3) * 16;
    const int ar = m0 + (lane & 15), ac = 8 * (lane >> 4);
    const int br = (lane & 7) + 8 * (lane >> 4), bc = 8 * ((lane >> 3) & 1);
    float* qkv = (float*)(sm + J_QKV);
    const float* bias = (const float*)(sm + J_BIAS);

    // hoist A_hi fragments (64 regs)
    uint32_t ahi[2][8][4];
    #pragma unroll
    for (int ks = 0; ks < 8; ks++) {
        ldsm4(ahi[0][ks], sb + J_AHI + (uint32_t)(ar * TPAD + ks * 16 + ac) * 2);
        ldsm4(ahi[1][ks], sb + J_AHI + (uint32_t)((ar + 16) * TPAD + ks * 16 + ac) * 2);
    }

    for (int nc = 0; nc < 6; nc++) {
        // B_hi chunk
        for (int idx = tid; idx < 1024; idx += 384) {
            int row = idx >> 4, c8 = (idx & 15) * 8;
            cp16(sb + J_B + (uint32_t)(row * TPAD + c8) * 2,
                 g_wqkv_hi + (nc * 64 + row) * 128 + c8);
        }
        cp_commit();
        cp_wait0();
        __syncthreads();

        float acc[2][2][4];
        #pragma unroll
        for (int i = 0; i < 2; i++)
            #pragma unroll
            for (int j = 0; j < 2; j++)
                #pragma unroll
                for (int q = 0; q < 4; q++) acc[i][j][q] = 0.f;

        // pass1: hi*hi (A from regs)
        #pragma unroll
        for (int ks = 0; ks < 8; ks++) {
            uint32_t bfr[4];
            ldsm4(bfr, sb + J_B + (uint32_t)((n0 + br) * TPAD + ks * 16 + bc) * 2);
            mma16816(acc[0][0], ahi[0][ks], &bfr[0]);
            mma16816(acc[0][1], ahi[0][ks], &bfr[2]);
            mma16816(acc[1][0], ahi[1][ks], &bfr[0]);
            mma16816(acc[1][1], ahi[1][ks], &bfr[2]);
        }
        // pass2: lo*hi
        #pragma unroll
        for (int ks = 0; ks < 8; ks++) {
            uint32_t a0[4], a1[4], bfr[4];
            ldsm4(a0, sb + J_ALO + (uint32_t)(ar * TPAD + ks * 16 + ac) * 2);
            ldsm4(a1, sb + J_ALO + (uint32_t)((ar + 16) * TPAD + ks * 16 + ac) * 2);
            ldsm4(bfr, sb + J_B + (uint32_t)((n0 + br) * TPAD + ks * 16 + bc) * 2);
            mma16816(acc[0][0], a0, &bfr[0]);
            mma16816(acc[0][1], a0, &bfr[2]);
            mma16816(acc[1][0], a1, &bfr[0]);
            mma16816(acc[1][1], a1, &bfr[2]);
        }
        __syncthreads();

        // B_lo chunk
        for (int idx = tid; idx < 1024; idx += 384) {
            int row = idx >> 4, c8 = (idx & 15) * 8;
            cp16(sb + J_B + (uint32_t)(row * TPAD + c8) * 2,
                 g_wqkv_lo + (nc * 64 + row) * 128 + c8);
        }
        cp_commit();
        cp_wait0();
        __syncthreads();

        // pass3: hi*lo (A from regs)
        #pragma unroll
        for (int ks = 0; ks < 8; ks++) {
            uint32_t bfr[4];
            ldsm4(bfr, sb + J_B + (uint32_t)((n0 + br) * TPAD + ks * 16 + bc) * 2);
            mma16816(acc[0][0], ahi[0][ks], &bfr[0]);
            mma16816(acc[0][1], ahi[0][ks], &bfr[2]);
            mma16816(acc[1][0], ahi[1][ks], &bfr[0]);
            mma16816(acc[1][1], ahi[1][ks], &bfr[2]);
        }

        // epilogue -> qkv smem (+bias)
        {
            const int r = m0 + (lane >> 2), cq = (lane & 3) * 2;
            #pragma unroll
            for (int mt = 0; mt < 2; mt++)
                #pragma unroll
                for (int n8 = 0; n8 < 2; n8++) {
                    const float* c = acc[mt][n8];
                    int col = nc * 64 + n0 + n8 * 8 + cq;
                    int row = r + mt * 16;
                    qkv[row * QS + col]           = c[0] + bias[col];
                    qkv[row * QS + col + 1]       = c[1] + bias[col + 1];
                    qkv[(row + 8) * QS + col]     = c[2] + bias[col];
                    qkv[(row + 8) * QS + col + 1] = c[3] + bias[col + 1];
                }
        }
        __syncthreads();
    }

    // ---- attention (probs overlay A region; A_hi lives in regs now) ----
    float* probs = (float*)(sm + J_PROBS);

    // scores: 2q x 4k tiles; 4 tl x 12 x 6 = 288 tiles
    if (tid < 288) {
        int tl = tid / 72, rem = tid - tl * 72;
        int ti = rem / 6, tj = rem - ti * 6;
        int i = 2 * ti, j = 4 * tj;
        const u64* q0 = reinterpret_cast<const u64*>(qkv + (tl * 24 + i) * QS);
        const u64* q1 = reinterpret_cast<const u64*>(qkv + (tl * 24 + i + 1) * QS);
        const u64* k0 = reinterpret_cast<const u64*>(qkv + (tl * 24 + j) * QS + 128);
        const u64* k1 = reinterpret_cast<const u64*>(qkv + (tl * 24 + j + 1) * QS + 128);
        const u64* k2 = reinterpret_cast<const u64*>(qkv + (tl * 24 + j + 2) * QS + 128);
        const u64* k3 = reinterpret_cast<const u64*>(qkv + (tl * 24 + j + 3) * QS + 128);
        u64 a0[4] = {0ull, 0ull, 0ull, 0ull};
        u64 a1[4] = {0ull, 0ull, 0ull, 0ull};
        #pragma unroll 8
        for (int c2 = 0; c2 < 64; c2++) {
            u64 qa = q0[c2], qb = q1[c2];
            u64 k0v = k0[c2], k1v = k1[c2], k2v = k2[c2], k3v = k3[c2];
            fma2(a0[0], qa, k0v); fma2(a0[1], qa, k1v);
            fma2(a0[2], qa, k2v); fma2(a0[3], qa, k3v);
            fma2(a1[0], qb, k0v); fma2(a1[1], qb, k1v);
            fma2(a1[2], qb, k2v); fma2(a1[3], qb, k3v);
        }
        const float SC = 0.08838834764831845f;
        float* pr = probs + (tl * 24 + i) * PRS;
        float s0, s1;
        #pragma unroll
        for (int jj = 0; jj < 4; jj++) {
            up2(a0[jj], s0, s1); pr[2 * (j + jj)]       = (s0 + s1) * SC;
            up2(a1[jj], s0, s1); pr[PRS + 2 * (j + jj)] = (s0 + s1) * SC;
        }
    }
    __syncthreads();

    if (tid < 96) {
        int tl = tid / 24, i = tid - tl * 24;
        float* pr = probs + (tl * 24 + i) * PRS;
        float m = pr[0];
        #pragma unroll
        for (int j = 1; j < 24; j++) m = fmaxf(m, pr[2 * j]);
        float s = 0.f, e[24];
        #pragma unroll
        for (int j = 0; j < 24; j++) { e[j] = __expf(pr[2 * j] - m); s += e[j]; }
        float inv = 1.0f / s;
        #pragma unroll
        for (int j = 0; j < 24; j++) {
            float p = e[j] * inv;
            *reinterpret_cast<float2*>(pr + 2 * j) = make_float2(p, p);
        }
    }
    __syncthreads();

    // AV: 12 warps: tl = warp/3, 8 joints per warp; probs loaded as dup pairs
    {
        const int tl = warp / 3, i0 = (warp % 3) * 8, d0 = lane * 4;
        u64 acc[8][2];
        #pragma unroll
        for (int ii = 0; ii < 8; ii++) { acc[ii][0] = 0ull; acc[ii][1] = 0ull; }
        const float* pr0 = probs + (tl * 24 + i0) * PRS;
        #pragma unroll 3
        for (int j2 = 0; j2 < 12; j2++) {
            const u64* vp0 = reinterpret_cast<const u64*>(qkv + (tl * 24 + 2 * j2) * QS + 256 + d0);
            const u64* vp1 = reinterpret_cast<const u64*>(qkv + (tl * 24 + 2 * j2 + 1) * QS + 256 + d0);
            u64 va0 = vp0[0], vb0 = vp0[1];
            u64 va1 = vp1[0], vb1 = vp1[1];
            #pragma unroll
            for (int ii = 0; ii < 8; ii++) {
                ulonglong2 p = *reinterpret_cast<const ulonglong2*>(pr0 + ii * PRS + 4 * j2);
                fma2(acc[ii][0], p.x, va0); fma2(acc[ii][1], p.x, vb0);
                fma2(acc[ii][0], p.y, va1); fma2(acc[ii][1], p.y, vb1);
            }
        }
        uint32_t* dhi = (uint32_t*)g_ao_hi;
        uint32_t* dlo = (uint32_t*)g_ao_lo;
        #pragma unroll
        for (int ii = 0; ii < 8; ii++) {
            float v0, v1, v2, v3;
            up2(acc[ii][0], v0, v1);
            up2(acc[ii][1], v2, v3);
            uint16_t h0, l0, h1, l1, h2, l2, h3, l3;
            split_bf(v0, h0, l0); split_bf(v1, h1, l1);
            split_bf(v2, h2, l2); split_bf(v3, h3, l3);
            size_t rid = rid0 + tl * 24 + i0 + ii;
            dhi[rid * 64 + lane * 2]     = h0 | ((uint32_t)h1 << 16);
            dhi[rid * 64 + lane * 2 + 1] = h2 | ((uint32_t)h3 << 16);
            dlo[rid * 64 + lane * 2]     = l0 | ((uint32_t)l1 << 16);
            dlo[rid * 64 + lane * 2 + 1] = l2 | ((uint32_t)l3 << 16);
        }
    }
}

// ================= K4: out = x + ao @ Wc + bc (transposed store) =================
#define K4_BIAS 0
#define K4_STG  512
#define K4_AHI  33536
#define K4_ALO  50944
#define K4_BHI  68352
#define K4_BLO  85760
#define K4_SMEM 103168

__global__ __launch_bounds__(256, 2)
void k4_out(const float* __restrict__ x, float* __restrict__ out) {
    extern __shared__ char sm[];
    const int tid = threadIdx.x, warp = tid >> 5, lane = tid & 31;
    const int b = blockIdx.z, kj = blockIdx.y, t0 = blockIdx.x * 64;
    const uint32_t sb = s2u(sm);

    for (int idx = tid; idx < 1024; idx += 256) {
        int row = idx >> 4, c8 = (idx & 15) * 8;
        uint32_t off = (uint32_t)(row * TPAD + c8) * 2;
        size_t rid = ((size_t)b * 4096 + t0 + row) * 24 + kj;
        cp16(sb + K4_AHI + off, g_ao_hi + rid * 128 + c8);
        cp16(sb + K4_ALO + off, g_ao_lo + rid * 128 + c8);
    }
    for (int idx = tid; idx < 1024; idx += 256) {
        int row = idx >> 4, c8 = (idx & 15) * 8;
        uint32_t off = (uint32_t)(row * TPAD + c8) * 2;
        cp16(sb + K4_BHI + off, g_wc_hi + row * 128 + c8);
        cp16(sb + K4_BLO + off, g_wc_lo + row * 128 + c8);
    }
    if (tid < 128) *(float*)(sm + K4_BIAS + tid * 4) = g_bc[tid];
    cp_commit();
    cp_wait0();
    __syncthreads();

    const int m0 = (warp & 3) * 16, n0 = (warp >> 2) * 32;
    for (int nc = 0; nc < 2; nc++) {
        float acc[1][4][4];
        #pragma unroll
        for (int j = 0; j < 4; j++)
            #pragma unroll
            for (int q = 0; q < 4; q++) acc[0][j][q] = 0.f;
        gemm3<1, 2>(sb + K4_AHI, sb + K4_ALO, sb + K4_BHI, sb + K4_BLO, acc, lane, m0, n0);
        stash<1, 2>((float*)(sm + K4_STG), acc, lane, m0, nc * 64 + n0);
        if (nc == 0) {
            __syncthreads();
            for (int idx = tid; idx < 1024; idx += 256) {
                int row = idx >> 4, c8 = (idx & 15) * 8;
                uint32_t off = (uint32_t)(row * TPAD + c8) * 2;
                cp16(sb + K4_BHI + off, g_wc_hi + (64 + row) * 128 + c8);
                cp16(sb + K4_BLO + off, g_wc_lo + (64 + row) * 128 + c8);
            }
            cp_commit();
            cp_wait0();
            __syncthreads();
        }
    }
    __syncthreads();

    {
        const float* stg  = (const float*)(sm + K4_STG);
        const float* bias = (const float*)(sm + K4_BIAS);
        for (int o = tid; o < 2048; o += 256) {
            int c = o >> 4, tq = o & 15;
            float bc = bias[c];
            size_t gb = ((size_t)(b * 3072 + kj * 128 + c)) * 4096 + t0;
            #pragma unroll
            for (int j = 0; j < 4; j++) {
                int t = tq + 16 * j;
                out[gb + t] = x[gb + t] + stg[t * 129 + c] + bc;
            }
        }
    }
}

// ================= host =================
extern "C" void kernel_launch(void* const* d_in, const int* in_sizes, int n_in,
                              void* d_out, int out_size)
{
    (void)in_sizes; (void)n_in; (void)out_size;
    const float* x      = (const float*)d_in[0];
    const float* W_tok  = (const float*)d_in[1];
    const float* b_tok  = (const float*)d_in[2];
    const float* g_norm = (const float*)d_in[3];
    const float* W_qkv  = (const float*)d_in[4];
    const float* b_qkv  = (const float*)d_in[5];
    const float* W_proj = (const float*)d_in[6];
    const float* b_proj = (const float*)d_in[7];
    const float* W_from = (const float*)d_in[8];
    const float* b_from = (const float*)d_in[9];
    float* out = (float*)d_out;

    cudaFuncSetAttribute(k1_tok, cudaFuncAttributeMaxDynamicSharedMemorySize, K1_SMEM);
    cudaFuncSetAttribute(k23,    cudaFuncAttributeMaxDynamicSharedMemorySize, K23_SMEM);
    cudaFuncSetAttribute(k4_out, cudaFuncAttributeMaxDynamicSharedMemorySize, K4_SMEM);

    k0a<<<4, 256>>>(W_proj, W_from, b_proj, b_from);
    k0b<<<192, 256>>>(W_tok, W_qkv);
    {
        dim3 g(64, 24, 4);
        k1_tok<<<g, 256, K1_SMEM>>>(x, b_tok, g_norm);
    }
    {
        dim3 g(1024, 4);
        k23<<<g, 384, K23_SMEM>>>(b_qkv);
    }
    {
        dim3 g(64, 24, 4);
        k4_out<<<g, 256, K4_SMEM>>>(x, out);
    }
}

// round 14
// speedup vs baseline: 2.6056x; 1.0557x over previous
#include <cuda_runtime.h>
#include <cuda_bf16.h>
#include <cstdint>

#define TLEN 4096
#define KJ   24
#define NBATCH 4
#define MTOT (NBATCH * KJ * TLEN)   // 393216 token rows
#define TPAD 136                     // bf16 elems per smem tile row (272B)

// ---------------- device scratch ----------------
__device__ __align__(256) __nv_bfloat16 g_tok_hi[(size_t)MTOT * 128];
__device__ __align__(256) __nv_bfloat16 g_tok_lo[(size_t)MTOT * 128];
__device__ __align__(256) __nv_bfloat16 g_ao_hi[(size_t)MTOT * 128];
__device__ __align__(256) __nv_bfloat16 g_ao_lo[(size_t)MTOT * 128];
__device__ __align__(256) float         g_wc[128 * 128];
__device__ __align__(256) float         g_bc[128];
__device__ __align__(256) __nv_bfloat16 g_wtok_hi[128 * 128], g_wtok_lo[128 * 128];
__device__ __align__(256) __nv_bfloat16 g_wqkv_hi[384 * 128], g_wqkv_lo[384 * 128];
__device__ __align__(256) __nv_bfloat16 g_wc_hi[128 * 128],   g_wc_lo[128 * 128];

typedef unsigned long long u64;

// ---------------- helpers ----------------
static __device__ __forceinline__ uint32_t s2u(const void* p) {
    uint32_t a;
    asm("{ .reg .u64 t; cvta.to.shared.u64 t, %1; cvt.u32.u64 %0, t; }" : "=r"(a) : "l"(p));
    return a;
}
static __device__ __forceinline__ void cp16(uint32_t dst, const void* src) {
    asm volatile("cp.async.cg.shared.global [%0], [%1], 16;" :: "r"(dst), "l"(src));
}
static __device__ __forceinline__ void cp_commit() {
    asm volatile("cp.async.commit_group;");
}
static __device__ __forceinline__ void cp_wait0() {
    asm volatile("cp.async.wait_group 0;" ::: "memory");
}
template<int N>
static __device__ __forceinline__ void cp_waitg() {
    asm volatile("cp.async.wait_group %0;" :: "n"(N) : "memory");
}
static __device__ __forceinline__ void split_bf(float v, uint16_t& h, uint16_t& l) {
    __nv_bfloat16 hb = __float2bfloat16(v);
    float r = v - __bfloat162float(hb);
    h = __bfloat16_as_ushort(hb);
    l = __bfloat16_as_ushort(__float2bfloat16(r));
}
static __device__ __forceinline__ void fma2(u64& d, u64 a, u64 b) {
    asm("fma.rn.f32x2 %0, %1, %2, %0;" : "+l"(d) : "l"(a), "l"(b));
}
static __device__ __forceinline__ void up2(u64 v, float& a, float& b) {
    asm("mov.b64 {%0, %1}, %2;" : "=f"(a), "=f"(b) : "l"(v));
}
static __device__ __forceinline__ void ldsm4(uint32_t* r, uint32_t addr) {
    asm volatile("ldmatrix.sync.aligned.m8n8.x4.shared.b16 {%0,%1,%2,%3}, [%4];"
                 : "=r"(r[0]), "=r"(r[1]), "=r"(r[2]), "=r"(r[3]) : "r"(addr));
}
static __device__ __forceinline__ void mma16816(float* c, const uint32_t* a, const uint32_t* b) {
    asm volatile("mma.sync.aligned.m16n8k16.row.col.f32.bf16.bf16.f32 "
                 "{%0,%1,%2,%3}, {%4,%5,%6,%7}, {%8,%9}, {%0,%1,%2,%3};"
                 : "+f"(c[0]), "+f"(c[1]), "+f"(c[2]), "+f"(c[3])
                 : "r"(a[0]), "r"(a[1]), "r"(a[2]), "r"(a[3]), "r"(b[0]), "r"(b[1]));
}

// one K=128 pass of a (MT*16)x(NT*16) warp tile
template<int MT, int NT>
static __device__ __forceinline__ void gemm_pass(uint32_t aBase, uint32_t bBase,
                                                 float acc[MT][2 * NT][4],
                                                 int lane, int m0, int n0) {
    const int ar = m0 + (lane & 15), ac = 8 * (lane >> 4);
    const int br = (lane & 7) + 8 * (lane >> 4), bc = 8 * ((lane >> 3) & 1);
    #pragma unroll
    for (int ks = 0; ks < 8; ks++) {
        uint32_t a[MT][4], b[NT][4];
        #pragma unroll
        for (int mt = 0; mt < MT; mt++)
            ldsm4(a[mt], aBase + (uint32_t)((ar + mt * 16) * TPAD + ks * 16 + ac) * 2);
        #pragma unroll
        for (int nt = 0; nt < NT; nt++)
            ldsm4(b[nt], bBase + (uint32_t)((n0 + nt * 16 + br) * TPAD + ks * 16 + bc) * 2);
        #pragma unroll
        for (int mt = 0; mt < MT; mt++)
            #pragma unroll
            for (int nt = 0; nt < NT; nt++) {
                mma16816(acc[mt][nt * 2],     a[mt], &b[nt][0]);
                mma16816(acc[mt][nt * 2 + 1], a[mt], &b[nt][2]);
            }
    }
}
template<int MT, int NT>
static __device__ __forceinline__ void gemm3(uint32_t aHi, uint32_t aLo, uint32_t bHi,
                                             uint32_t bLo, float acc[MT][2 * NT][4],
                                             int lane, int m0, int n0) {
    gemm_pass<MT, NT>(aHi, bHi, acc, lane, m0, n0);
    gemm_pass<MT, NT>(aHi, bLo, acc, lane, m0, n0);
    gemm_pass<MT, NT>(aLo, bHi, acc, lane, m0, n0);
}
// write C fragments (raw) into f32 staging, stride 129
template<int MT, int NT>
static __device__ __forceinline__ void stash(float* stg, const float acc[MT][2 * NT][4],
                                             int lane, int m0, int n0) {
    const int r = m0 + (lane >> 2), cq = (lane & 3) * 2;
    #pragma unroll
    for (int mt = 0; mt < MT; mt++)
        #pragma unroll
        for (int n8 = 0; n8 < 2 * NT; n8++) {
            const float* c = acc[mt][n8];
            int row = r + mt * 16, col = n0 + n8 * 8 + cq;
            stg[row * 129 + col]           = c[0];
            stg[row * 129 + col + 1]       = c[1];
            stg[(row + 8) * 129 + col]     = c[2];
            stg[(row + 8) * 129 + col + 1] = c[3];
        }
}

// ================= K0a: Wc = W_proj @ W_from, bc = b_proj@W_from + b_from =========
__global__ __launch_bounds__(256) void k0a(const float* __restrict__ Wp,
                                           const float* __restrict__ Wf,
                                           const float* __restrict__ bp,
                                           const float* __restrict__ bf) {
    __shared__ float swp[32 * 128];
    const int tid = threadIdx.x, r0 = blockIdx.x * 32;
    for (int i = tid; i < 32 * 128; i += 256) swp[i] = Wp[(r0 + (i >> 7)) * 128 + (i & 127)];
    __syncthreads();
    const int n = tid & 127, rb = tid >> 7;
    float acc[16];
    #pragma unroll
    for (int q = 0; q < 16; q++) acc[q] = 0.f;
    for (int m = 0; m < 128; m++) {
        float wf = Wf[m * 128 + n];
        #pragma unroll
        for (int q = 0; q < 16; q++) acc[q] += swp[(rb * 16 + q) * 128 + m] * wf;
    }
    #pragma unroll
    for (int q = 0; q < 16; q++) g_wc[(r0 + rb * 16 + q) * 128 + n] = acc[q];
    if (blockIdx.x == 0 && tid < 128) {
        float a = bf[tid];
        for (int m = 0; m < 128; m++) a += bp[m] * Wf[m * 128 + tid];
        g_bc[tid] = a;
    }
}

// ================= K0b: transpose + hi/lo split weights =================
__global__ __launch_bounds__(256) void k0b(const float* __restrict__ Wt,
                                           const float* __restrict__ Wq) {
    const int i = blockIdx.x * 256 + threadIdx.x;
    uint16_t h, l;
    if (i < 16384) {
        int n = i >> 7, k = i & 127;
        split_bf(Wt[k * 128 + n], h, l);
        g_wtok_hi[i] = __ushort_as_bfloat16(h); g_wtok_lo[i] = __ushort_as_bfloat16(l);
        split_bf(g_wc[k * 128 + n], h, l);
        g_wc_hi[i] = __ushort_as_bfloat16(h);   g_wc_lo[i] = __ushort_as_bfloat16(l);
    }
    if (i < 49152) {
        int n = i >> 7, k = i & 127;
        split_bf(Wq[k * 384 + n], h, l);
        g_wqkv_hi[i] = __ushort_as_bfloat16(h); g_wqkv_lo[i] = __ushort_as_bfloat16(l);
    }
}

// ================= K1: tok = x^T @ W_tok + b, RMSNorm, split-store ===============
#define K1_BIAS 0
#define K1_G    512
#define K1_AXS  1024
#define K1_AHI  35840
#define K1_ALO  53248
#define K1_BHI  70656
#define K1_BLO  88064
#define K1_SMEM 105472

__global__ __launch_bounds__(256, 2)
void k1_tok(const float* __restrict__ x, const float* __restrict__ b_tok,
            const float* __restrict__ g_norm) {
    extern __shared__ char sm[];
    const int tid = threadIdx.x, warp = tid >> 5, lane = tid & 31;
    const int b = blockIdx.z, kj = blockIdx.y, t0 = blockIdx.x * 64;
    const uint32_t sb = s2u(sm);

    for (int idx = tid; idx < 2048; idx += 256) {
        int c = idx >> 4, t16 = (idx & 15) * 4;
        const float* src = x + ((size_t)(b * 3072 + kj * 128 + c)) * 4096 + t0 + t16;
        cp16(sb + K1_AXS + (uint32_t)(c * 68 + t16) * 4, src);
    }
    for (int idx = tid; idx < 1024; idx += 256) {
        int row = idx >> 4, c8 = (idx & 15) * 8;
        uint32_t off = (uint32_t)(row * TPAD + c8) * 2;
        cp16(sb + K1_BHI + off, g_wtok_hi + row * 128 + c8);
        cp16(sb + K1_BLO + off, g_wtok_lo + row * 128 + c8);
    }
    if (tid < 128) {
        *(float*)(sm + K1_BIAS + tid * 4) = b_tok[tid];
        *(float*)(sm + K1_G + tid * 4)    = g_norm[tid];
    }
    cp_commit();
    cp_wait0();
    __syncthreads();

    {
        const int t = tid & 63, quarter = tid >> 6;
        const float* ax = (const float*)(sm + K1_AXS);
        for (int c4 = quarter * 8; c4 < quarter * 8 + 8; c4++) {
            int c = c4 * 4;
            float v0 = ax[(c + 0) * 68 + t], v1 = ax[(c + 1) * 68 + t];
            float v2 = ax[(c + 2) * 68 + t], v3 = ax[(c + 3) * 68 + t];
            uint16_t h0, l0, h1, l1, h2, l2, h3, l3;
            split_bf(v0, h0, l0); split_bf(v1, h1, l1);
            split_bf(v2, h2, l2); split_bf(v3, h3, l3);
            uint32_t off = (uint32_t)(t * TPAD + c) * 2;
            *(uint2*)(sm + K1_AHI + off) = make_uint2(h0 | ((uint32_t)h1 << 16), h2 | ((uint32_t)h3 << 16));
            *(uint2*)(sm + K1_ALO + off) = make_uint2(l0 | ((uint32_t)l1 << 16), l2 | ((uint32_t)l3 << 16));
        }
    }
    __syncthreads();

    const int m0 = (warp & 3) * 16, n0 = (warp >> 2) * 32;
    for (int nc = 0; nc < 2; nc++) {
        float acc[1][4][4];
        #pragma unroll
        for (int j = 0; j < 4; j++)
            #pragma unroll
            for (int q = 0; q < 4; q++) acc[0][j][q] = 0.f;
        gemm3<1, 2>(sb + K1_AHI, sb + K1_ALO, sb + K1_BHI, sb + K1_BLO, acc, lane, m0, n0);
        stash<1, 2>((float*)(sm + K1_AXS), acc, lane, m0, nc * 64 + n0);
        if (nc == 0) {
            __syncthreads();
            for (int idx = tid; idx < 1024; idx += 256) {
                int row = idx >> 4, c8 = (idx & 15) * 8;
                uint32_t off = (uint32_t)(row * TPAD + c8) * 2;
                cp16(sb + K1_BHI + off, g_wtok_hi + (64 + row) * 128 + c8);
                cp16(sb + K1_BLO + off, g_wtok_lo + (64 + row) * 128 + c8);
            }
            cp_commit();
            cp_wait0();
            __syncthreads();
        }
    }
    __syncthreads();

    uint32_t* shi = (uint32_t*)(sm + K1_AHI);
    uint32_t* slo = (uint32_t*)(sm + K1_ALO);
    {
        const int row = tid >> 2, sub = tid & 3;
        const float* stg  = (const float*)(sm + K1_AXS);
        const float* bias = (const float*)(sm + K1_BIAS);
        const float* gw   = (const float*)(sm + K1_G);
        float ss = 0.f;
        #pragma unroll 8
        for (int c = sub * 32; c < sub * 32 + 32; c++) {
            float v = stg[row * 129 + c] + bias[c];
            ss += v * v;
        }
        ss += __shfl_xor_sync(0xffffffffu, ss, 1);
        ss += __shfl_xor_sync(0xffffffffu, ss, 2);
        float inv = rsqrtf(ss * (1.0f / 128.0f) + 1e-5f);
        #pragma unroll 4
        for (int c2 = 0; c2 < 16; c2++) {
            int c = sub * 32 + c2 * 2;
            float v0 = (stg[row * 129 + c]     + bias[c])     * inv * gw[c];
            float v1 = (stg[row * 129 + c + 1] + bias[c + 1]) * inv * gw[c + 1];
            uint16_t h0, l0, h1, l1;
            split_bf(v0, h0, l0); split_bf(v1, h1, l1);
            shi[row * 65 + sub * 16 + c2] = h0 | ((uint32_t)h1 << 16);
            slo[row * 65 + sub * 16 + c2] = l0 | ((uint32_t)l1 << 16);
        }
    }
    __syncthreads();
    {
        uint32_t* dhi = (uint32_t*)g_tok_hi;
        uint32_t* dlo = (uint32_t*)g_tok_lo;
        for (int idx = tid; idx < 4096; idx += 256) {
            int row = idx >> 6, w = idx & 63;
            size_t rid = ((size_t)b * 4096 + t0 + row) * 24 + kj;
            dhi[rid * 64 + w] = shi[row * 65 + w];
            dlo[rid * 64 + w] = slo[row * 65 + w];
        }
    }
}

// ================= K23: fused qkv GEMM + attention, pipelined B loads ============
// M = 96 rows = 4 complete t-groups per CTA. 384 threads, 1 CTA/SM.
// A_hi fragments hoisted to registers; A_hi smem region reused as B ring slot 1.
// B loads (hi/lo per chunk) fully overlapped with compute via cp.async groups.
#define QS 386
#define PRS 52
#define J_BIAS 0                     // 384 f32
#define J_S1   1536                  // B slot1 (initially A_hi tile) [96][TPAD]=26112
#define J_ALO  27648                 // A_lo [96][TPAD] = 26112
#define J_S0   53760                 // B slot0 [64][TPAD] = 17408
#define J_QKV  71168                 // f32 [96][QS] = 148224
#define K23_SMEM 219392
#define J_PROBS J_S1                 // probs overlay after GEMM: 4*24*52*4 = 19968

__global__ __launch_bounds__(384, 1)
void k23(const float* __restrict__ b_qkv) {
    extern __shared__ char sm[];
    const int tid = threadIdx.x, warp = tid >> 5, lane = tid & 31;
    const int b = blockIdx.y, t0 = blockIdx.x * 4;
    const size_t rid0 = ((size_t)b * 4096 + t0) * 24;
    const uint32_t sb = s2u(sm);

    // load A tiles (A_hi -> slot1 region, A_lo) + B_hi(chunk0) -> slot0 + bias
    for (int idx = tid; idx < 1536; idx += 384) {
        int row = idx >> 4, c8 = (idx & 15) * 8;
        uint32_t off = (uint32_t)(row * TPAD + c8) * 2;
        cp16(sb + J_S1 + off,  g_tok_hi + (rid0 + row) * 128 + c8);
        cp16(sb + J_ALO + off, g_tok_lo + (rid0 + row) * 128 + c8);
    }
    for (int idx = tid; idx < 1024; idx += 384) {
        int row = idx >> 4, c8 = (idx & 15) * 8;
        cp16(sb + J_S0 + (uint32_t)(row * TPAD + c8) * 2, g_wqkv_hi + row * 128 + c8);
    }
    *(float*)(sm + J_BIAS + tid * 4) = b_qkv[tid];
    cp_commit();
    cp_wait0();
    __syncthreads();

    // 12 warps = 3M(32) x 4N(16)
    const int m0 = (warp % 3) * 32, n0 = (warp / 3) * 16;
    const int ar = m0 + (lane & 15), ac = 8 * (lane >> 4);
    const int br = (lane & 7) + 8 * (lane >> 4), bc = 8 * ((lane >> 3) & 1);
    float* qkv = (float*)(sm + J_QKV);
    const float* bias = (const float*)(sm + J_BIAS);

    // hoist A_hi fragments (64 regs) from slot1 region, then free it for B ring
    uint32_t ahi[2][8][4];
    #pragma unroll
    for (int ks = 0; ks < 8; ks++) {
        ldsm4(ahi[0][ks], sb + J_S1 + (uint32_t)(ar * TPAD + ks * 16 + ac) * 2);
        ldsm4(ahi[1][ks], sb + J_S1 + (uint32_t)((ar + 16) * TPAD + ks * 16 + ac) * 2);
    }
    __syncthreads();   // all warps done reading A_hi smem

    // issue lo0 -> slot1 (overlaps chunk0 pass1/2)
    for (int idx = tid; idx < 1024; idx += 384) {
        int row = idx >> 4, c8 = (idx & 15) * 8;
        cp16(sb + J_S1 + (uint32_t)(row * TPAD + c8) * 2, g_wqkv_lo + row * 128 + c8);
    }
    cp_commit();

    for (int nc = 0; nc < 6; nc++) {
        if (nc > 0) {
            cp_waitg<1>();      // hi(nc) landed in slot0
            __syncthreads();
        }

        float acc[2][2][4];
        #pragma unroll
        for (int i = 0; i < 2; i++)
            #pragma unroll
            for (int j = 0; j < 2; j++)
                #pragma unroll
                for (int q = 0; q < 4; q++) acc[i][j][q] = 0.f;

        // pass1: hi*hi (A from regs, B slot0)
        #pragma unroll
        for (int ks = 0; ks < 8; ks++) {
            uint32_t bfr[4];
            ldsm4(bfr, sb + J_S0 + (uint32_t)((n0 + br) * TPAD + ks * 16 + bc) * 2);
            mma16816(acc[0][0], ahi[0][ks], &bfr[0]);
            mma16816(acc[0][1], ahi[0][ks], &bfr[2]);
            mma16816(acc[1][0], ahi[1][ks], &bfr[0]);
            mma16816(acc[1][1], ahi[1][ks], &bfr[2]);
        }
        // pass2: lo*hi (A_lo smem, B slot0)
        #pragma unroll
        for (int ks = 0; ks < 8; ks++) {
            uint32_t a0[4], a1[4], bfr[4];
            ldsm4(a0, sb + J_ALO + (uint32_t)(ar * TPAD + ks * 16 + ac) * 2);
            ldsm4(a1, sb + J_ALO + (uint32_t)((ar + 16) * TPAD + ks * 16 + ac) * 2);
            ldsm4(bfr, sb + J_S0 + (uint32_t)((n0 + br) * TPAD + ks * 16 + bc) * 2);
            mma16816(acc[0][0], a0, &bfr[0]);
            mma16816(acc[0][1], a0, &bfr[2]);
            mma16816(acc[1][0], a1, &bfr[0]);
            mma16816(acc[1][1], a1, &bfr[2]);
        }
        __syncthreads();       // all warps done with slot0

        if (nc < 5) {          // prefetch hi(nc+1) -> slot0, overlaps pass3
            for (int idx = tid; idx < 1024; idx += 384) {
                int row = idx >> 4, c8 = (idx & 15) * 8;
                cp16(sb + J_S0 + (uint32_t)(row * TPAD + c8) * 2,
                     g_wqkv_hi + ((nc + 1) * 64 + row) * 128 + c8);
            }
            cp_commit();
            cp_waitg<1>();     // lo(nc) landed in slot1 (hi(nc+1) may be pending)
        } else {
            cp_waitg<0>();     // lo(5) landed
        }
        __syncthreads();

        // pass3: hi*lo (A from regs, B slot1)
        #pragma unroll
        for (int ks = 0; ks < 8; ks++) {
            uint32_t bfr[4];
            ldsm4(bfr, sb + J_S1 + (uint32_t)((n0 + br) * TPAD + ks * 16 + bc) * 2);
            mma16816(acc[0][0], ahi[0][ks], &bfr[0]);
            mma16816(acc[0][1], ahi[0][ks], &bfr[2]);
            mma16816(acc[1][0], ahi[1][ks], &bfr[0]);
            mma16816(acc[1][1], ahi[1][ks], &bfr[2]);
        }

        // epilogue -> qkv smem (+bias)
        {
            const int r = m0 + (lane >> 2), cq = (lane & 3) * 2;
            #pragma unroll
            for (int mt = 0; mt < 2; mt++)
                #pragma unroll
                for (int n8 = 0; n8 < 2; n8++) {
                    const float* c = acc[mt][n8];
                    int col = nc * 64 + n0 + n8 * 8 + cq;
                    int row = r + mt * 16;
                    qkv[row * QS + col]           = c[0] + bias[col];
                    qkv[row * QS + col + 1]       = c[1] + bias[col + 1];
                    qkv[(row + 8) * QS + col]     = c[2] + bias[col];
                    qkv[(row + 8) * QS + col + 1] = c[3] + bias[col + 1];
                }
        }
        __syncthreads();       // all warps done with slot1

        if (nc < 5) {          // prefetch lo(nc+1) -> slot1, overlaps next pass1/2
            for (int idx = tid; idx < 1024; idx += 384) {
                int row = idx >> 4, c8 = (idx & 15) * 8;
                cp16(sb + J_S1 + (uint32_t)(row * TPAD + c8) * 2,
                     g_wqkv_lo + ((nc + 1) * 64 + row) * 128 + c8);
            }
            cp_commit();
        }
    }

    // ---- attention (probs overlay slot1 region) ----
    float* probs = (float*)(sm + J_PROBS);

    // scores: 2q x 4k tiles; 4 tl x 12 x 6 = 288 tiles
    if (tid < 288) {
        int tl = tid / 72, rem = tid - tl * 72;
        int ti = rem / 6, tj = rem - ti * 6;
        int i = 2 * ti, j = 4 * tj;
        const u64* q0 = reinterpret_cast<const u64*>(qkv + (tl * 24 + i) * QS);
        const u64* q1 = reinterpret_cast<const u64*>(qkv + (tl * 24 + i + 1) * QS);
        const u64* k0 = reinterpret_cast<const u64*>(qkv + (tl * 24 + j) * QS + 128);
        const u64* k1 = reinterpret_cast<const u64*>(qkv + (tl * 24 + j + 1) * QS + 128);
        const u64* k2 = reinterpret_cast<const u64*>(qkv + (tl * 24 + j + 2) * QS + 128);
        const u64* k3 = reinterpret_cast<const u64*>(qkv + (tl * 24 + j + 3) * QS + 128);
        u64 a0[4] = {0ull, 0ull, 0ull, 0ull};
        u64 a1[4] = {0ull, 0ull, 0ull, 0ull};
        #pragma unroll 8
        for (int c2 = 0; c2 < 64; c2++) {
            u64 qa = q0[c2], qb = q1[c2];
            u64 k0v = k0[c2], k1v = k1[c2], k2v = k2[c2], k3v = k3[c2];
            fma2(a0[0], qa, k0v); fma2(a0[1], qa, k1v);
            fma2(a0[2], qa, k2v); fma2(a0[3], qa, k3v);
            fma2(a1[0], qb, k0v); fma2(a1[1], qb, k1v);
            fma2(a1[2], qb, k2v); fma2(a1[3], qb, k3v);
        }
        const float SC = 0.08838834764831845f;
        float* pr = probs + (tl * 24 + i) * PRS;
        float s0, s1;
        #pragma unroll
        for (int jj = 0; jj < 4; jj++) {
            up2(a0[jj], s0, s1); pr[2 * (j + jj)]       = (s0 + s1) * SC;
            up2(a1[jj], s0, s1); pr[PRS + 2 * (j + jj)] = (s0 + s1) * SC;
        }
    }
    __syncthreads();

    if (tid < 96) {
        int tl = tid / 24, i = tid - tl * 24;
        float* pr = probs + (tl * 24 + i) * PRS;
        float m = pr[0];
        #pragma unroll
        for (int j = 1; j < 24; j++) m = fmaxf(m, pr[2 * j]);
        float s = 0.f, e[24];
        #pragma unroll
        for (int j = 0; j < 24; j++) { e[j] = __expf(pr[2 * j] - m); s += e[j]; }
        float inv = 1.0f / s;
        #pragma unroll
        for (int j = 0; j < 24; j++) {
            float p = e[j] * inv;
            *reinterpret_cast<float2*>(pr + 2 * j) = make_float2(p, p);
        }
    }
    __syncthreads();

    // AV: 12 warps: tl = warp/3, 8 joints per warp; probs loaded as dup pairs
    {
        const int tl = warp / 3, i0 = (warp % 3) * 8, d0 = lane * 4;
        u64 acc[8][2];
        #pragma unroll
        for (int ii = 0; ii < 8; ii++) { acc[ii][0] = 0ull; acc[ii][1] = 0ull; }
        const float* pr0 = probs + (tl * 24 + i0) * PRS;
        #pragma unroll 3
        for (int j2 = 0; j2 < 12; j2++) {
            const u64* vp0 = reinterpret_cast<const u64*>(qkv + (tl * 24 + 2 * j2) * QS + 256 + d0);
            const u64* vp1 = reinterpret_cast<const u64*>(qkv + (tl * 24 + 2 * j2 + 1) * QS + 256 + d0);
            u64 va0 = vp0[0], vb0 = vp0[1];
            u64 va1 = vp1[0], vb1 = vp1[1];
            #pragma unroll
            for (int ii = 0; ii < 8; ii++) {
                ulonglong2 p = *reinterpret_cast<const ulonglong2*>(pr0 + ii * PRS + 4 * j2);
                fma2(acc[ii][0], p.x, va0); fma2(acc[ii][1], p.x, vb0);
                fma2(acc[ii][0], p.y, va1); fma2(acc[ii][1], p.y, vb1);
            }
        }
        uint32_t* dhi = (uint32_t*)g_ao_hi;
        uint32_t* dlo = (uint32_t*)g_ao_lo;
        #pragma unroll
        for (int ii = 0; ii < 8; ii++) {
            float v0, v1, v2, v3;
            up2(acc[ii][0], v0, v1);
            up2(acc[ii][1], v2, v3);
            uint16_t h0, l0, h1, l1, h2, l2, h3, l3;
            split_bf(v0, h0, l0); split_bf(v1, h1, l1);
            split_bf(v2, h2, l2); split_bf(v3, h3, l3);
            size_t rid = rid0 + tl * 24 + i0 + ii;
            dhi[rid * 64 + lane * 2]     = h0 | ((uint32_t)h1 << 16);
            dhi[rid * 64 + lane * 2 + 1] = h2 | ((uint32_t)h3 << 16);
            dlo[rid * 64 + lane * 2]     = l0 | ((uint32_t)l1 << 16);
            dlo[rid * 64 + lane * 2 + 1] = l2 | ((uint32_t)l3 << 16);
        }
    }
}

// ================= K4: out = x + ao @ Wc + bc (transposed store) =================
#define K4_BIAS 0
#define K4_STG  512
#define K4_AHI  33536
#define K4_ALO  50944
#define K4_BHI  68352
#define K4_BLO  85760
#define K4_SMEM 103168

__global__ __launch_bounds__(256, 2)
void k4_out(const float* __restrict__ x, float* __restrict__ out) {
    extern __shared__ char sm[];
    const int tid = threadIdx.x, warp = tid >> 5, lane = tid & 31;
    const int b = blockIdx.z, kj = blockIdx.y, t0 = blockIdx.x * 64;
    const uint32_t sb = s2u(sm);

    for (int idx = tid; idx < 1024; idx += 256) {
        int row = idx >> 4, c8 = (idx & 15) * 8;
        uint32_t off = (uint32_t)(row * TPAD + c8) * 2;
        size_t rid = ((size_t)b * 4096 + t0 + row) * 24 + kj;
        cp16(sb + K4_AHI + off, g_ao_hi + rid * 128 + c8);
        cp16(sb + K4_ALO + off, g_ao_lo + rid * 128 + c8);
    }
    for (int idx = tid; idx < 1024; idx += 256) {
        int row = idx >> 4, c8 = (idx & 15) * 8;
        uint32_t off = (uint32_t)(row * TPAD + c8) * 2;
        cp16(sb + K4_BHI + off, g_wc_hi + row * 128 + c8);
        cp16(sb + K4_BLO + off, g_wc_lo + row * 128 + c8);
    }
    if (tid < 128) *(float*)(sm + K4_BIAS + tid * 4) = g_bc[tid];
    cp_commit();
    cp_wait0();
    __syncthreads();

    const int m0 = (warp & 3) * 16, n0 = (warp >> 2) * 32;
    for (int nc = 0; nc < 2; nc++) {
        float acc[1][4][4];
        #pragma unroll
        for (int j = 0; j < 4; j++)
            #pragma unroll
            for (int q = 0; q < 4; q++) acc[0][j][q] = 0.f;
        gemm3<1, 2>(sb + K4_AHI, sb + K4_ALO, sb + K4_BHI, sb + K4_BLO, acc, lane, m0, n0);
        stash<1, 2>((float*)(sm + K4_STG), acc, lane, m0, nc * 64 + n0);
        if (nc == 0) {
            __syncthreads();
            for (int idx = tid; idx < 1024; idx += 256) {
                int row = idx >> 4, c8 = (idx & 15) * 8;
                uint32_t off = (uint32_t)(row * TPAD + c8) * 2;
                cp16(sb + K4_BHI + off, g_wc_hi + (64 + row) * 128 + c8);
                cp16(sb + K4_BLO + off, g_wc_lo + (64 + row) * 128 + c8);
            }
            cp_commit();
            cp_wait0();
            __syncthreads();
        }
    }
    __syncthreads();

    {
        const float* stg  = (const float*)(sm + K4_STG);
        const float* bias = (const float*)(sm + K4_BIAS);
        for (int o = tid; o < 2048; o += 256) {
            int c = o >> 4, tq = o & 15;
            float bc = bias[c];
            size_t gb = ((size_t)(b * 3072 + kj * 128 + c)) * 4096 + t0;
            #pragma unroll
            for (int j = 0; j < 4; j++) {
                int t = tq + 16 * j;
                out[gb + t] = x[gb + t] + stg[t * 129 + c] + bc;
            }
        }
    }
}

// ================= host =================
extern "C" void kernel_launch(void* const* d_in, const int* in_sizes, int n_in,
                              void* d_out, int out_size)
{
    (void)in_sizes; (void)n_in; (void)out_size;
    const float* x      = (const float*)d_in[0];
    const float* W_tok  = (const float*)d_in[1];
    const float* b_tok  = (const float*)d_in[2];
    const float* g_norm = (const float*)d_in[3];
    const float* W_qkv  = (const float*)d_in[4];
    const float* b_qkv  = (const float*)d_in[5];
    const float* W_proj = (const float*)d_in[6];
    const float* b_proj = (const float*)d_in[7];
    const float* W_from = (const float*)d_in[8];
    const float* b_from = (const float*)d_in[9];
    float* out = (float*)d_out;

    cudaFuncSetAttribute(k1_tok, cudaFuncAttributeMaxDynamicSharedMemorySize, K1_SMEM);
    cudaFuncSetAttribute(k23,    cudaFuncAttributeMaxDynamicSharedMemorySize, K23_SMEM);
    cudaFuncSetAttribute(k4_out, cudaFuncAttributeMaxDynamicSharedMemorySize, K4_SMEM);

    k0a<<<4, 256>>>(W_proj, W_from, b_proj, b_from);
    k0b<<<192, 256>>>(W_tok, W_qkv);
    {
        dim3 g(64, 24, 4);
        k1_tok<<<g, 256, K1_SMEM>>>(x, b_tok, g_norm);
    }
    {
        dim3 g(1024, 4);
        k23<<<g, 384, K23_SMEM>>>(b_qkv);
    }
    {
        dim3 g(64, 24, 4);
        k4_out<<<g, 256, K4_SMEM>>>(x, out);
    }
}